// round 3
// baseline (speedup 1.0000x reference)
#include <cuda_runtime.h>

#define CC 512
#define NTOK 13824            // 24*24*24
#define TT 27648              // B * NTOK

// ---------------- scratch (device globals; no allocation allowed) ----------------
__device__ float g_X[TT * CC];
__device__ float g_Q[TT * CC];
__device__ float g_K[TT * CC];
__device__ float g_V[TT * CC];
__device__ float g_O[TT * CC];

// ---- gather branch 1: X1[i*576+p, c1] = x_flat[i*294912 + c1*576 + p], i<48 ----
__global__ void gather_x1(const float* __restrict__ x) {
    __shared__ float tile[32][33];
    const int i  = blockIdx.z;            // 0..47
    const int p0 = blockIdx.x * 32;       // 18 tiles
    const int c0 = blockIdx.y * 32;       // 16 tiles
    const int tx = threadIdx.x, ty = threadIdx.y;   // 32 x 8
    const float* src = x + i * 294912;
#pragma unroll
    for (int l = 0; l < 4; l++)
        tile[ty + 8 * l][tx] = src[(c0 + ty + 8 * l) * 576 + p0 + tx];
    __syncthreads();
    float* dst = g_X + (i * 576 + p0) * CC + c0;
#pragma unroll
    for (int l = 0; l < 4; l++)
        dst[(ty + 8 * l) * CC + tx] = tile[tx][ty + 8 * l];
}

// ---- gather branch 3: X3[b*N+n, c] = x[b,c,n]  (true token-major transpose) ----
__global__ void gather_xT(const float* __restrict__ x) {
    __shared__ float tile[32][33];
    const int b  = blockIdx.z;
    const int n0 = blockIdx.x * 32;
    const int c0 = blockIdx.y * 32;
    const int tx = threadIdx.x, ty = threadIdx.y;   // 32 x 8
    const float* src = x + b * (CC * NTOK);
#pragma unroll
    for (int i = 0; i < 4; i++)
        tile[ty + 8 * i][tx] = src[(c0 + ty + 8 * i) * NTOK + n0 + tx];
    __syncthreads();
    float* dst = g_X + (b * NTOK + n0) * CC + c0;
#pragma unroll
    for (int i = 0; i < 4; i++)
        dst[(ty + 8 * i) * CC + tx] = tile[tx][ty + 8 * i];
}

// ---- gather branch 2: X2[t, c] = x[(t/24)*12288 + c*24 + t%24] ------------------
__global__ void gather_x2(const float* __restrict__ x) {
    __shared__ float t2[24][257];
    const int i = blockIdx.x;                 // 0..1151
    const float* src = x + i * 12288;
    const int tid = threadIdx.x;              // 256
    for (int half = 0; half < 2; half++) {
        const int j0 = half * 256;
#pragma unroll
        for (int l = 0; l < 24; l++) {
            int e = l * 256 + tid;            // 0..6143
            int j = e / 24, k = e - j * 24;
            t2[k][j] = src[j0 * 24 + e];
        }
        __syncthreads();
#pragma unroll
        for (int l = 0; l < 24; l++) {
            int e  = l * 256 + tid;
            int k  = e >> 8, jj = e & 255;
            g_X[(i * 24 + k) * CC + j0 + jj] = t2[k][jj];
        }
        __syncthreads();
    }
}

// ---------------- SGEMM: C[T,512] (+)= A[T,512] @ W[512, ldb](cols bcol..) + bias
__global__ __launch_bounds__(256, 2) void sgemm128(
    const float* __restrict__ A, const float* __restrict__ W,
    const float* __restrict__ bias, float* __restrict__ Cmat,
    int ldb, int bcol, int acc)
{
    __shared__ float As[16][132];
    __shared__ float Bs[16][128];
    const int m0  = blockIdx.y * 128;
    const int n0  = blockIdx.x * 128;
    const int tid = threadIdx.x;
    const int tx = tid & 15, ty = tid >> 4;
    const int arow = tid >> 2, akq = (tid & 3) << 2;
    const int bk   = tid >> 5;            // 0..7  (rows bk and bk+8)
    const int bn   = (tid & 31) << 2;     // 0..124

    float acc_r[8][8];
#pragma unroll
    for (int i = 0; i < 8; i++) {
#pragma unroll
        for (int j = 0; j < 8; j++) acc_r[i][j] = 0.f;
    }
    const float* Ap = A + m0 * CC;
    const float* Wp = W + bcol + n0;

    for (int k0 = 0; k0 < CC; k0 += 16) {
#pragma unroll
        for (int l = 0; l < 2; l++) {
            const int r = arow + l * 64;
            const float4 v = *(const float4*)(Ap + r * CC + k0 + akq);
            As[akq + 0][r] = v.x; As[akq + 1][r] = v.y;
            As[akq + 2][r] = v.z; As[akq + 3][r] = v.w;
        }
        *(float4*)&Bs[bk][bn]     = *(const float4*)(Wp + (k0 + bk) * ldb + bn);
        *(float4*)&Bs[bk + 8][bn] = *(const float4*)(Wp + (k0 + bk + 8) * ldb + bn);
        __syncthreads();
#pragma unroll
        for (int k = 0; k < 16; k++) {
            float a[8], b[8];
            *(float4*)&a[0] = *(const float4*)&As[k][ty * 8];
            *(float4*)&a[4] = *(const float4*)&As[k][ty * 8 + 4];
            *(float4*)&b[0] = *(const float4*)&Bs[k][tx * 8];
            *(float4*)&b[4] = *(const float4*)&Bs[k][tx * 8 + 4];
#pragma unroll
            for (int i = 0; i < 8; i++) {
#pragma unroll
                for (int j = 0; j < 8; j++) acc_r[i][j] += a[i] * b[j];
            }
        }
        __syncthreads();
    }
#pragma unroll
    for (int i = 0; i < 8; i++) {
        const int gm = m0 + ty * 8 + i;
        float* crow = Cmat + gm * CC + n0 + tx * 8;
#pragma unroll
        for (int jj = 0; jj < 2; jj++) {
            float4 v = make_float4(acc_r[i][jj * 4 + 0], acc_r[i][jj * 4 + 1],
                                   acc_r[i][jj * 4 + 2], acc_r[i][jj * 4 + 3]);
            if (bias) {
                const float* bp = bias + n0 + tx * 8 + jj * 4;
                v.x += bp[0]; v.y += bp[1]; v.z += bp[2]; v.w += bp[3];
            }
            if (acc) {
                const float4 o = *(const float4*)(crow + jj * 4);
                v.x += o.x; v.y += o.y; v.z += o.z; v.w += o.w;
            }
            *(float4*)(crow + jj * 4) = v;
        }
    }
}

// ---------------- branch 1 attention: seq 576, per (i, head, q-tile) ------------
__global__ __launch_bounds__(256) void attn_seq576() {
    extern __shared__ float sm[];
    float* S  = sm;                    // 64 x 577
    float* Qs = sm + 64 * 577;         // 64 x 64
    float* KV = Qs + 64 * 64;          // 64 x 68 (stride 65 for K, 68 for V)
    const int qt = blockIdx.x, h = blockIdx.y, bd = blockIdx.z;
    const int tid = threadIdx.x;
    const int tx = tid & 15, ty = tid >> 4;
    const int rq = bd * 576 + qt * 64;
    const int rb = bd * 576;
    const int tok = tid >> 4, dv = (tid & 15) * 4;

#pragma unroll
    for (int l = 0; l < 4; l++) {
        const int m = tok + l * 16;
        *(float4*)(Qs + m * 64 + dv) =
            *(const float4*)(g_Q + (rq + m) * CC + h * 64 + dv);
    }
    for (int kt = 0; kt < 9; kt++) {
        __syncthreads();
#pragma unroll
        for (int l = 0; l < 4; l++) {
            const int j = tok + l * 16;
            const float4 v = *(const float4*)(g_K + (rb + kt * 64 + j) * CC + h * 64 + dv);
            KV[j * 65 + dv + 0] = v.x; KV[j * 65 + dv + 1] = v.y;
            KV[j * 65 + dv + 2] = v.z; KV[j * 65 + dv + 3] = v.w;
        }
        __syncthreads();
        float sc[4][4];
#pragma unroll
        for (int i = 0; i < 4; i++) { sc[i][0]=0; sc[i][1]=0; sc[i][2]=0; sc[i][3]=0; }
#pragma unroll 8
        for (int d = 0; d < 64; d++) {
            float a[4], b[4];
#pragma unroll
            for (int i = 0; i < 4; i++) a[i] = Qs[(ty * 4 + i) * 64 + d];
#pragma unroll
            for (int i = 0; i < 4; i++) b[i] = KV[(tx * 4 + i) * 65 + d];
#pragma unroll
            for (int i = 0; i < 4; i++) {
#pragma unroll
                for (int j = 0; j < 4; j++) sc[i][j] += a[i] * b[j];
            }
        }
#pragma unroll
        for (int i = 0; i < 4; i++) {
#pragma unroll
            for (int j = 0; j < 4; j++)
                S[(ty * 4 + i) * 577 + kt * 64 + tx * 4 + j] = sc[i][j] * 0.125f;
        }
    }
    __syncthreads();
    {   // softmax, 4 threads per row
        const int r = tid >> 2, q = tid & 3;
        float mx = -1e30f;
        for (int j = q; j < 576; j += 4) mx = fmaxf(mx, S[r * 577 + j]);
        mx = fmaxf(mx, __shfl_xor_sync(0xffffffffu, mx, 1));
        mx = fmaxf(mx, __shfl_xor_sync(0xffffffffu, mx, 2));
        float sum = 0.f;
        for (int j = q; j < 576; j += 4) {
            const float p = __expf(S[r * 577 + j] - mx);
            S[r * 577 + j] = p; sum += p;
        }
        sum += __shfl_xor_sync(0xffffffffu, sum, 1);
        sum += __shfl_xor_sync(0xffffffffu, sum, 2);
        const float inv = 1.f / sum;
        for (int j = q; j < 576; j += 4) S[r * 577 + j] *= inv;
    }
    float oacc[4][4];
#pragma unroll
    for (int i = 0; i < 4; i++) { oacc[i][0]=0; oacc[i][1]=0; oacc[i][2]=0; oacc[i][3]=0; }
    for (int vt = 0; vt < 9; vt++) {
        __syncthreads();
#pragma unroll
        for (int l = 0; l < 4; l++) {
            const int j = tok + l * 16;
            *(float4*)(KV + j * 68 + dv) =
                *(const float4*)(g_V + (rb + vt * 64 + j) * CC + h * 64 + dv);
        }
        __syncthreads();
#pragma unroll 4
        for (int j = 0; j < 64; j++) {
            float p[4];
#pragma unroll
            for (int i = 0; i < 4; i++) p[i] = S[(ty * 4 + i) * 577 + vt * 64 + j];
            const float4 v = *(const float4*)(KV + j * 68 + tx * 4);
#pragma unroll
            for (int i = 0; i < 4; i++) {
                oacc[i][0] += p[i] * v.x; oacc[i][1] += p[i] * v.y;
                oacc[i][2] += p[i] * v.z; oacc[i][3] += p[i] * v.w;
            }
        }
    }
#pragma unroll
    for (int i = 0; i < 4; i++) {
        const float4 v = make_float4(oacc[i][0], oacc[i][1], oacc[i][2], oacc[i][3]);
        *(float4*)(g_O + (rq + ty * 4 + i) * CC + h * 64 + tx * 4) = v;
    }
}

// ---------------- branch 3: window attention (64 tokens, +rel-pos bias) ---------
__global__ __launch_bounds__(256) void attn_win(const float* __restrict__ pos_table) {
    extern __shared__ float sm[];
    float* S   = sm;                    // 64 x 65
    float* Qs  = S + 64 * 65;           // 64 x 64
    float* KV  = Qs + 64 * 64;          // 64 x 68
    float* pos = KV + 64 * 68;          // 343
    const int win = blockIdx.x, h = blockIdx.y, b = blockIdx.z;
    const int wd = win / 36, ww = (win / 6) % 6, wh = win % 6;
    const int tid = threadIdx.x;
    const int tx = tid & 15, ty = tid >> 4;
    const int base = b * NTOK + wd * 4 * 576 + ww * 4 * 24 + wh * 4;
    const int tok = tid >> 4, dv = (tid & 15) * 4;

    for (int e = tid; e < 343; e += 256) pos[e] = pos_table[e];
#pragma unroll
    for (int l = 0; l < 4; l++) {
        const int t = tok + l * 16;
        const int row = base + (t >> 4) * 576 + ((t >> 2) & 3) * 24 + (t & 3);
        *(float4*)(Qs + t * 64 + dv) =
            *(const float4*)(g_Q + row * CC + h * 64 + dv);
        const float4 v = *(const float4*)(g_K + row * CC + h * 64 + dv);
        KV[t * 65 + dv + 0] = v.x; KV[t * 65 + dv + 1] = v.y;
        KV[t * 65 + dv + 2] = v.z; KV[t * 65 + dv + 3] = v.w;
    }
    __syncthreads();
    float sc[4][4];
#pragma unroll
    for (int i = 0; i < 4; i++) { sc[i][0]=0; sc[i][1]=0; sc[i][2]=0; sc[i][3]=0; }
#pragma unroll 8
    for (int d = 0; d < 64; d++) {
        float a[4], bb[4];
#pragma unroll
        for (int i = 0; i < 4; i++) a[i] = Qs[(ty * 4 + i) * 64 + d];
#pragma unroll
        for (int i = 0; i < 4; i++) bb[i] = KV[(tx * 4 + i) * 65 + d];
#pragma unroll
        for (int i = 0; i < 4; i++) {
#pragma unroll
            for (int j = 0; j < 4; j++) sc[i][j] += a[i] * bb[j];
        }
    }
#pragma unroll
    for (int i = 0; i < 4; i++) {
        const int m  = ty * 4 + i;
        const int am = m >> 4, bm = (m >> 2) & 3, cm = m & 3;
#pragma unroll
        for (int j = 0; j < 4; j++) {
            const int jn = tx * 4 + j;
            const int aj = jn >> 4, bj = (jn >> 2) & 3, cj = jn & 3;
            const float bias = pos[(aj - am + 3) * 49 + (bj - bm + 3) * 7 + (cj - cm + 3)];
            S[m * 65 + jn] = sc[i][j] * 0.125f + bias;
        }
    }
    __syncthreads();
    {   // softmax over 64, 4 threads per row
        const int r = tid >> 2, q = tid & 3;
        float mx = -1e30f;
        for (int j = q; j < 64; j += 4) mx = fmaxf(mx, S[r * 65 + j]);
        mx = fmaxf(mx, __shfl_xor_sync(0xffffffffu, mx, 1));
        mx = fmaxf(mx, __shfl_xor_sync(0xffffffffu, mx, 2));
        float sum = 0.f;
        for (int j = q; j < 64; j += 4) {
            const float p = __expf(S[r * 65 + j] - mx);
            S[r * 65 + j] = p; sum += p;
        }
        sum += __shfl_xor_sync(0xffffffffu, sum, 1);
        sum += __shfl_xor_sync(0xffffffffu, sum, 2);
        const float inv = 1.f / sum;
        for (int j = q; j < 64; j += 4) S[r * 65 + j] *= inv;
    }
    __syncthreads();
#pragma unroll
    for (int l = 0; l < 4; l++) {
        const int t = tok + l * 16;
        const int row = base + (t >> 4) * 576 + ((t >> 2) & 3) * 24 + (t & 3);
        *(float4*)(KV + t * 68 + dv) =
            *(const float4*)(g_V + row * CC + h * 64 + dv);
    }
    __syncthreads();
    float oacc[4][4];
#pragma unroll
    for (int i = 0; i < 4; i++) { oacc[i][0]=0; oacc[i][1]=0; oacc[i][2]=0; oacc[i][3]=0; }
#pragma unroll 4
    for (int j = 0; j < 64; j++) {
        float p[4];
#pragma unroll
        for (int i = 0; i < 4; i++) p[i] = S[(ty * 4 + i) * 65 + j];
        const float4 v = *(const float4*)(KV + j * 68 + tx * 4);
#pragma unroll
        for (int i = 0; i < 4; i++) {
            oacc[i][0] += p[i] * v.x; oacc[i][1] += p[i] * v.y;
            oacc[i][2] += p[i] * v.z; oacc[i][3] += p[i] * v.w;
        }
    }
#pragma unroll
    for (int i = 0; i < 4; i++) {
        const int m = ty * 4 + i;
        const int row = base + (m >> 4) * 576 + ((m >> 2) & 3) * 24 + (m & 3);
        const float4 v = make_float4(oacc[i][0], oacc[i][1], oacc[i][2], oacc[i][3]);
        *(float4*)(g_O + row * CC + h * 64 + tx * 4) = v;
    }
}

// ---------------- branch 2: tiny seq-24 attention per (i, head) -----------------
__global__ __launch_bounds__(256) void attn_seq24() {
    __shared__ float Qs[24 * 65], Ks[24 * 65], Vs[24 * 65], P[24 * 25];
    const int i = blockIdx.x, h = blockIdx.y;
    const int tid = threadIdx.x;
    const int rbase = i * 24 * CC + h * 64;

    for (int e = tid; e < 24 * 64; e += 256) {
        const int k = e >> 6, d = e & 63;
        Qs[k * 65 + d] = g_Q[rbase + k * CC + d];
        Ks[k * 65 + d] = g_K[rbase + k * CC + d];
        Vs[k * 65 + d] = g_V[rbase + k * CC + d];
    }
    __syncthreads();
    for (int sid = tid; sid < 576; sid += 256) {
        const int r = sid / 24, c = sid - r * 24;
        float s = 0.f;
#pragma unroll 16
        for (int d = 0; d < 64; d++) s += Qs[r * 65 + d] * Ks[c * 65 + d];
        P[r * 25 + c] = s * 0.125f;
    }
    __syncthreads();
    if (tid < 24) {
        float mx = -1e30f;
        for (int c = 0; c < 24; c++) mx = fmaxf(mx, P[tid * 25 + c]);
        float sum = 0.f;
        for (int c = 0; c < 24; c++) {
            const float p = __expf(P[tid * 25 + c] - mx);
            P[tid * 25 + c] = p; sum += p;
        }
        const float inv = 1.f / sum;
        for (int c = 0; c < 24; c++) P[tid * 25 + c] *= inv;
    }
    __syncthreads();
    for (int e = tid; e < 24 * 64; e += 256) {
        const int r = e >> 6, d = e & 63;
        float o = 0.f;
#pragma unroll
        for (int j = 0; j < 24; j++) o += P[r * 25 + j] * Vs[j * 65 + d];
        g_O[rbase + r * CC + d] = o;
    }
}

// ---------------- orchestration --------------------------------------------------
extern "C" void kernel_launch(void* const* d_in, const int* in_sizes, int n_in,
                              void* d_out, int out_size) {
    const float* x     = (const float*)d_in[0];
    const float* vq_w  = (const float*)d_in[1];
    const float* vq_b  = (const float*)d_in[2];
    const float* vk_w  = (const float*)d_in[3];
    const float* vk_b  = (const float*)d_in[4];
    const float* vv_w  = (const float*)d_in[5];
    const float* vv_b  = (const float*)d_in[6];
    const float* vo_w  = (const float*)d_in[7];
    const float* vo_b  = (const float*)d_in[8];
    const float* hq_w  = (const float*)d_in[9];
    const float* hq_b  = (const float*)d_in[10];
    const float* hk_w  = (const float*)d_in[11];
    const float* hk_b  = (const float*)d_in[12];
    const float* hv_w  = (const float*)d_in[13];
    const float* hv_b  = (const float*)d_in[14];
    const float* ho_w  = (const float*)d_in[15];
    const float* ho_b  = (const float*)d_in[16];
    const float* qkv_w = (const float*)d_in[17];
    const float* ow_w  = (const float*)d_in[18];
    const float* ow_b  = (const float*)d_in[19];
    const float* pos   = (const float*)d_in[20];
    float* out = (float*)d_out;
    (void)in_sizes; (void)n_in; (void)out_size;

    float *pX, *pQ, *pK, *pV, *pO;
    cudaGetSymbolAddress((void**)&pX, g_X);
    cudaGetSymbolAddress((void**)&pQ, g_Q);
    cudaGetSymbolAddress((void**)&pK, g_K);
    cudaGetSymbolAddress((void**)&pV, g_V);
    cudaGetSymbolAddress((void**)&pO, g_O);

    const int SMEM1 = (64 * 577 + 64 * 64 + 64 * 68) * 4;            // 181,504 B
    const int SMEM3 = (64 * 65 + 64 * 64 + 64 * 68 + 343) * 4;       //  51,804 B
    cudaFuncSetAttribute(attn_seq576, cudaFuncAttributeMaxDynamicSharedMemorySize, SMEM1);
    cudaFuncSetAttribute(attn_win,    cudaFuncAttributeMaxDynamicSharedMemorySize, SMEM3);

    const dim3 gg(4, 216);      // 512/128 x 27648/128

    // ---- branch 1 (reshape(48,512,576) full-attn, seq 576) ----
    gather_x1<<<dim3(18, 16, 48), dim3(32, 8)>>>(x);
    sgemm128<<<gg, 256>>>(pX, vq_w, vq_b, pQ, 512, 0, 0);
    sgemm128<<<gg, 256>>>(pX, vk_w, vk_b, pK, 512, 0, 0);
    sgemm128<<<gg, 256>>>(pX, vv_w, vv_b, pV, 512, 0, 0);
    attn_seq576<<<dim3(9, 8, 48), 256, SMEM1>>>();
    sgemm128<<<gg, 256>>>(pO, vo_w, vo_b, out, 512, 0, 0);   // write (first)

    // ---- branch 3 (window attn) — true token-major transpose ----
    gather_xT<<<dim3(432, 16, 2), dim3(32, 8)>>>(x);
    sgemm128<<<gg, 256>>>(pX, qkv_w, nullptr, pQ, 1536, 0, 0);
    sgemm128<<<gg, 256>>>(pX, qkv_w, nullptr, pK, 1536, 512, 0);
    sgemm128<<<gg, 256>>>(pX, qkv_w, nullptr, pV, 1536, 1024, 0);
    attn_win<<<dim3(216, 8, 2), 256, SMEM3>>>(pos);
    sgemm128<<<gg, 256>>>(pO, ow_w, ow_b, out, 512, 0, 1);   // accumulate

    // ---- branch 2 (horizontal full-attn, seq 24) ----
    gather_x2<<<1152, 256>>>(x);
    sgemm128<<<gg, 256>>>(pX, hq_w, hq_b, pQ, 512, 0, 0);
    sgemm128<<<gg, 256>>>(pX, hk_w, hk_b, pK, 512, 0, 0);
    sgemm128<<<gg, 256>>>(pX, hv_w, hv_b, pV, 512, 0, 0);
    attn_seq24<<<dim3(1152, 8), 256>>>();
    sgemm128<<<gg, 256>>>(pO, ho_w, ho_b, out, 512, 0, 1);   // accumulate
}

// round 5
// speedup vs baseline: 1.4741x; 1.4741x over previous
#include <cuda_runtime.h>
#include <cuda_bf16.h>
#include <cstdint>

#define CC 512
#define NTOK 13824            // 24*24*24
#define TT 27648              // B * NTOK

// ---------------- scratch (device globals; no allocation allowed) ----------------
__device__ float g_X[TT * CC];
__device__ float g_Q[TT * CC];
__device__ float g_K[TT * CC];
__device__ float g_V[TT * CC];
__device__ float g_O[TT * CC];
__device__ __nv_bfloat16 g_Ahi[TT * CC];
__device__ __nv_bfloat16 g_Alo[TT * CC];
__device__ __nv_bfloat16 g_Whi[12 * CC * CC];   // 12 slots of Wt[n][k]
__device__ __nv_bfloat16 g_Wlo[12 * CC * CC];

__device__ __forceinline__ uint32_t smem_to_u32(const void* p) {
    uint32_t a;
    asm("{ .reg .u64 t; cvta.to.shared.u64 t, %1; cvt.u32.u64 %0, t; }" : "=r"(a) : "l"(p));
    return a;
}
__device__ __forceinline__ void ldm4(uint32_t* r, uint32_t addr) {
    asm volatile("ldmatrix.sync.aligned.m8n8.x4.shared.b16 {%0,%1,%2,%3}, [%4];"
                 : "=r"(r[0]), "=r"(r[1]), "=r"(r[2]), "=r"(r[3]) : "r"(addr));
}
__device__ __forceinline__ void mma_bf16(float* c, const uint32_t* a,
                                         uint32_t b0, uint32_t b1) {
    asm volatile("mma.sync.aligned.m16n8k16.row.col.f32.bf16.bf16.f32 "
                 "{%0,%1,%2,%3}, {%4,%5,%6,%7}, {%8,%9}, {%0,%1,%2,%3};"
                 : "+f"(c[0]), "+f"(c[1]), "+f"(c[2]), "+f"(c[3])
                 : "r"(a[0]), "r"(a[1]), "r"(a[2]), "r"(a[3]), "r"(b0), "r"(b1));
}

// ---------------- conversion kernels ---------------------------------------------
__global__ void asplit(const float* __restrict__ src) {
    const size_t i = (size_t)blockIdx.x * 256 + threadIdx.x;   // x4 elems
    const float4 v = ((const float4*)src)[i];
    __nv_bfloat16 h0 = __float2bfloat16(v.x), h1 = __float2bfloat16(v.y);
    __nv_bfloat16 h2 = __float2bfloat16(v.z), h3 = __float2bfloat16(v.w);
    __nv_bfloat16 l0 = __float2bfloat16(v.x - __bfloat162float(h0));
    __nv_bfloat16 l1 = __float2bfloat16(v.y - __bfloat162float(h1));
    __nv_bfloat16 l2 = __float2bfloat16(v.z - __bfloat162float(h2));
    __nv_bfloat16 l3 = __float2bfloat16(v.w - __bfloat162float(h3));
    __nv_bfloat162* oh = (__nv_bfloat162*)(g_Ahi + 4 * i);
    __nv_bfloat162* ol = (__nv_bfloat162*)(g_Alo + 4 * i);
    oh[0] = __nv_bfloat162(h0, h1); oh[1] = __nv_bfloat162(h2, h3);
    ol[0] = __nv_bfloat162(l0, l1); ol[1] = __nv_bfloat162(l2, l3);
}

// Wt[slot][n][k] = W[k*ldb + bcol + n], split to hi/lo
__global__ void wconv(const float* __restrict__ W, int ldb, int bcol, int slot) {
    __shared__ float tile[32][33];
    const int k0 = blockIdx.x * 32, n0 = blockIdx.y * 32;
    const int tx = threadIdx.x, ty = threadIdx.y;   // 32 x 8
#pragma unroll
    for (int l = 0; l < 4; l++)
        tile[ty + 8 * l][tx] = W[(k0 + ty + 8 * l) * ldb + bcol + n0 + tx];
    __syncthreads();
    const size_t base = (size_t)slot * CC * CC;
#pragma unroll
    for (int l = 0; l < 4; l++) {
        const float v = tile[tx][ty + 8 * l];
        const __nv_bfloat16 h = __float2bfloat16(v);
        const __nv_bfloat16 lo = __float2bfloat16(v - __bfloat162float(h));
        const size_t idx = base + (size_t)(n0 + ty + 8 * l) * CC + k0 + tx;
        g_Whi[idx] = h; g_Wlo[idx] = lo;
    }
}

// ------------- mma.sync GEMM: C[T,512](+)= (Ahi+Alo)@(Bhi+Blo)^T + bias ----------
// 128x128 tile, 256 thr (8 warps, 2x4), warp = 64x32, double-buffered K-chunk 32.
#define GST 40                       // smem row stride (bf16 elems)
#define MATS (128 * GST)             // one matrix (elems)

__global__ __launch_bounds__(256) void mmagemm(
    const __nv_bfloat16* __restrict__ Ahi, const __nv_bfloat16* __restrict__ Alo,
    const __nv_bfloat16* __restrict__ Bhi, const __nv_bfloat16* __restrict__ Blo,
    const float* __restrict__ bias, float* __restrict__ Cmat, int acc)
{
    extern __shared__ __align__(16) __nv_bfloat16 smb[];
    const int tid = threadIdx.x, lane = tid & 31, wid = tid >> 5;
    const int m0 = blockIdx.y * 128, n0 = blockIdx.x * 128;
    const int wm = (wid >> 2) * 64, wn = (wid & 3) * 32;

    float c[4][4][4];
#pragma unroll
    for (int i = 0; i < 4; i++)
#pragma unroll
        for (int j = 0; j < 4; j++) { c[i][j][0]=0; c[i][j][1]=0; c[i][j][2]=0; c[i][j][3]=0; }

    const __nv_bfloat16* pAh = Ahi + (size_t)m0 * CC;
    const __nv_bfloat16* pAl = Alo + (size_t)m0 * CC;
    const __nv_bfloat16* pBh = Bhi + (size_t)n0 * CC;
    const __nv_bfloat16* pBl = Blo + (size_t)n0 * CC;

    const int e0 = tid, e1 = tid + 256;
    const int g0 = (e0 >> 2) * CC + (e0 & 3) * 8, g1 = (e1 >> 2) * CC + (e1 & 3) * 8;
    const int s0 = (e0 >> 2) * GST + (e0 & 3) * 8, s1 = (e1 >> 2) * GST + (e1 & 3) * 8;

    // prologue: chunk 0 -> buf0
    {
        uint4 v;
        v = *(const uint4*)(pAh + g0); *(uint4*)(smb + 0 * MATS + s0) = v;
        v = *(const uint4*)(pAh + g1); *(uint4*)(smb + 0 * MATS + s1) = v;
        v = *(const uint4*)(pAl + g0); *(uint4*)(smb + 1 * MATS + s0) = v;
        v = *(const uint4*)(pAl + g1); *(uint4*)(smb + 1 * MATS + s1) = v;
        v = *(const uint4*)(pBh + g0); *(uint4*)(smb + 2 * MATS + s0) = v;
        v = *(const uint4*)(pBh + g1); *(uint4*)(smb + 2 * MATS + s1) = v;
        v = *(const uint4*)(pBl + g0); *(uint4*)(smb + 3 * MATS + s0) = v;
        v = *(const uint4*)(pBl + g1); *(uint4*)(smb + 3 * MATS + s1) = v;
    }
    __syncthreads();

    for (int kc = 0; kc < 16; kc++) {
        __nv_bfloat16* cur = smb + (kc & 1) * 4 * MATS;
        __nv_bfloat16* nxt = smb + ((kc + 1) & 1) * 4 * MATS;
        const bool pf = (kc + 1) < 16;
        uint4 rr[8];
        if (pf) {
            const int kb = (kc + 1) * 32;
            rr[0] = *(const uint4*)(pAh + g0 + kb); rr[1] = *(const uint4*)(pAh + g1 + kb);
            rr[2] = *(const uint4*)(pAl + g0 + kb); rr[3] = *(const uint4*)(pAl + g1 + kb);
            rr[4] = *(const uint4*)(pBh + g0 + kb); rr[5] = *(const uint4*)(pBh + g1 + kb);
            rr[6] = *(const uint4*)(pBl + g0 + kb); rr[7] = *(const uint4*)(pBl + g1 + kb);
        }
        const uint32_t sb = smem_to_u32(cur);
#pragma unroll
        for (int ks = 0; ks < 2; ks++) {
            uint32_t ah[4][4], al[4][4], bh[2][4], bl[2][4];
#pragma unroll
            for (int mt = 0; mt < 4; mt++) {
                const int r = wm + mt * 16 + (lane & 15);
                const uint32_t ad = sb + (uint32_t)(r * GST + ks * 16 + (lane >> 4) * 8) * 2;
                ldm4(ah[mt], ad);
                ldm4(al[mt], ad + MATS * 2);
            }
#pragma unroll
            for (int bt = 0; bt < 2; bt++) {
                const int r = wn + bt * 16 + (lane & 15);
                const uint32_t bd = sb + (uint32_t)(2 * MATS + r * GST + ks * 16 + (lane >> 4) * 8) * 2;
                ldm4(bh[bt], bd);
                ldm4(bl[bt], bd + MATS * 2);
            }
#pragma unroll
            for (int mt = 0; mt < 4; mt++) {
#pragma unroll
                for (int nt = 0; nt < 4; nt++) {
                    const int bt = nt >> 1, sub = nt & 1;
                    mma_bf16(c[mt][nt], ah[mt], bh[bt][sub], bh[bt][sub + 2]);
                    mma_bf16(c[mt][nt], ah[mt], bl[bt][sub], bl[bt][sub + 2]);
                    mma_bf16(c[mt][nt], al[mt], bh[bt][sub], bh[bt][sub + 2]);
                }
            }
        }
        if (pf) {
            *(uint4*)(nxt + 0 * MATS + s0) = rr[0]; *(uint4*)(nxt + 0 * MATS + s1) = rr[1];
            *(uint4*)(nxt + 1 * MATS + s0) = rr[2]; *(uint4*)(nxt + 1 * MATS + s1) = rr[3];
            *(uint4*)(nxt + 2 * MATS + s0) = rr[4]; *(uint4*)(nxt + 2 * MATS + s1) = rr[5];
            *(uint4*)(nxt + 3 * MATS + s0) = rr[6]; *(uint4*)(nxt + 3 * MATS + s1) = rr[7];
        }
        __syncthreads();
    }

    // epilogue: c[mt][nt] -> C rows m0+wm+mt*16+{g, g+8}, cols n0+wn+nt*8+(lane&3)*2
#pragma unroll
    for (int mt = 0; mt < 4; mt++) {
        const int r0 = m0 + wm + mt * 16 + (lane >> 2);
#pragma unroll
        for (int nt = 0; nt < 4; nt++) {
            const int col = n0 + wn + nt * 8 + (lane & 3) * 2;
            float2 v0 = make_float2(c[mt][nt][0], c[mt][nt][1]);
            float2 v1 = make_float2(c[mt][nt][2], c[mt][nt][3]);
            if (bias) {
                const float b0 = bias[col], b1 = bias[col + 1];
                v0.x += b0; v0.y += b1; v1.x += b0; v1.y += b1;
            }
            float* p0 = Cmat + (size_t)r0 * CC + col;
            float* p1 = Cmat + (size_t)(r0 + 8) * CC + col;
            if (acc) {
                const float2 o0 = *(const float2*)p0, o1 = *(const float2*)p1;
                v0.x += o0.x; v0.y += o0.y; v1.x += o1.x; v1.y += o1.y;
            }
            *(float2*)p0 = v0;
            *(float2*)p1 = v1;
        }
    }
}

// ---- gather branch 1: X1[i*576+p, c1] = x_flat[i*294912 + c1*576 + p], i<48 ----
__global__ void gather_x1(const float* __restrict__ x) {
    __shared__ float tile[32][33];
    const int i  = blockIdx.z;
    const int p0 = blockIdx.x * 32;
    const int c0 = blockIdx.y * 32;
    const int tx = threadIdx.x, ty = threadIdx.y;   // 32 x 8
    const float* src = x + i * 294912;
#pragma unroll
    for (int l = 0; l < 4; l++)
        tile[ty + 8 * l][tx] = src[(c0 + ty + 8 * l) * 576 + p0 + tx];
    __syncthreads();
    float* dst = g_X + (i * 576 + p0) * CC + c0;
#pragma unroll
    for (int l = 0; l < 4; l++)
        dst[(ty + 8 * l) * CC + tx] = tile[tx][ty + 8 * l];
}

// ---- gather branch 3: X3[b*N+n, c] = x[b,c,n] ----------------------------------
__global__ void gather_xT(const float* __restrict__ x) {
    __shared__ float tile[32][33];
    const int b  = blockIdx.z;
    const int n0 = blockIdx.x * 32;
    const int c0 = blockIdx.y * 32;
    const int tx = threadIdx.x, ty = threadIdx.y;   // 32 x 8
    const float* src = x + b * (CC * NTOK);
#pragma unroll
    for (int i = 0; i < 4; i++)
        tile[ty + 8 * i][tx] = src[(c0 + ty + 8 * i) * NTOK + n0 + tx];
    __syncthreads();
    float* dst = g_X + (b * NTOK + n0) * CC + c0;
#pragma unroll
    for (int i = 0; i < 4; i++)
        dst[(ty + 8 * i) * CC + tx] = tile[tx][ty + 8 * i];
}

// ---- gather branch 2: X2[t, c] = x[(t/24)*12288 + c*24 + t%24] ------------------
__global__ void gather_x2(const float* __restrict__ x) {
    __shared__ float t2[24][257];
    const int i = blockIdx.x;
    const float* src = x + i * 12288;
    const int tid = threadIdx.x;              // 256
    for (int half = 0; half < 2; half++) {
        const int j0 = half * 256;
#pragma unroll
        for (int l = 0; l < 24; l++) {
            int e = l * 256 + tid;
            int j = e / 24, k = e - j * 24;
            t2[k][j] = src[j0 * 24 + e];
        }
        __syncthreads();
#pragma unroll
        for (int l = 0; l < 24; l++) {
            int e  = l * 256 + tid;
            int k  = e >> 8, jj = e & 255;
            g_X[(i * 24 + k) * CC + j0 + jj] = t2[k][jj];
        }
        __syncthreads();
    }
}

// ---------------- branch 1 attention: seq 576 ------------------------------------
__global__ __launch_bounds__(256) void attn_seq576() {
    extern __shared__ float sm[];
    float* S  = sm;                    // 64 x 577
    float* Qs = sm + 64 * 577;         // 64 x 64
    float* KV = Qs + 64 * 64;          // 64 x 68
    const int qt = blockIdx.x, h = blockIdx.y, bd = blockIdx.z;
    const int tid = threadIdx.x;
    const int tx = tid & 15, ty = tid >> 4;
    const int rq = bd * 576 + qt * 64;
    const int rb = bd * 576;
    const int tok = tid >> 4, dv = (tid & 15) * 4;

#pragma unroll
    for (int l = 0; l < 4; l++) {
        const int m = tok + l * 16;
        *(float4*)(Qs + m * 64 + dv) =
            *(const float4*)(g_Q + (rq + m) * CC + h * 64 + dv);
    }
    for (int kt = 0; kt < 9; kt++) {
        __syncthreads();
#pragma unroll
        for (int l = 0; l < 4; l++) {
            const int j = tok + l * 16;
            const float4 v = *(const float4*)(g_K + (rb + kt * 64 + j) * CC + h * 64 + dv);
            KV[j * 65 + dv + 0] = v.x; KV[j * 65 + dv + 1] = v.y;
            KV[j * 65 + dv + 2] = v.z; KV[j * 65 + dv + 3] = v.w;
        }
        __syncthreads();
        float sc[4][4];
#pragma unroll
        for (int i = 0; i < 4; i++) { sc[i][0]=0; sc[i][1]=0; sc[i][2]=0; sc[i][3]=0; }
#pragma unroll 8
        for (int d = 0; d < 64; d++) {
            float a[4], b[4];
#pragma unroll
            for (int i = 0; i < 4; i++) a[i] = Qs[(ty * 4 + i) * 64 + d];
#pragma unroll
            for (int i = 0; i < 4; i++) b[i] = KV[(tx * 4 + i) * 65 + d];
#pragma unroll
            for (int i = 0; i < 4; i++) {
#pragma unroll
                for (int j = 0; j < 4; j++) sc[i][j] += a[i] * b[j];
            }
        }
#pragma unroll
        for (int i = 0; i < 4; i++) {
#pragma unroll
            for (int j = 0; j < 4; j++)
                S[(ty * 4 + i) * 577 + kt * 64 + tx * 4 + j] = sc[i][j] * 0.125f;
        }
    }
    __syncthreads();
    {
        const int r = tid >> 2, q = tid & 3;
        float mx = -1e30f;
        for (int j = q; j < 576; j += 4) mx = fmaxf(mx, S[r * 577 + j]);
        mx = fmaxf(mx, __shfl_xor_sync(0xffffffffu, mx, 1));
        mx = fmaxf(mx, __shfl_xor_sync(0xffffffffu, mx, 2));
        float sum = 0.f;
        for (int j = q; j < 576; j += 4) {
            const float p = __expf(S[r * 577 + j] - mx);
            S[r * 577 + j] = p; sum += p;
        }
        sum += __shfl_xor_sync(0xffffffffu, sum, 1);
        sum += __shfl_xor_sync(0xffffffffu, sum, 2);
        const float inv = 1.f / sum;
        for (int j = q; j < 576; j += 4) S[r * 577 + j] *= inv;
    }
    float oacc[4][4];
#pragma unroll
    for (int i = 0; i < 4; i++) { oacc[i][0]=0; oacc[i][1]=0; oacc[i][2]=0; oacc[i][3]=0; }
    for (int vt = 0; vt < 9; vt++) {
        __syncthreads();
#pragma unroll
        for (int l = 0; l < 4; l++) {
            const int j = tok + l * 16;
            *(float4*)(KV + j * 68 + dv) =
                *(const float4*)(g_V + (rb + vt * 64 + j) * CC + h * 64 + dv);
        }
        __syncthreads();
#pragma unroll 4
        for (int j = 0; j < 64; j++) {
            float p[4];
#pragma unroll
            for (int i = 0; i < 4; i++) p[i] = S[(ty * 4 + i) * 577 + vt * 64 + j];
            const float4 v = *(const float4*)(KV + j * 68 + tx * 4);
#pragma unroll
            for (int i = 0; i < 4; i++) {
                oacc[i][0] += p[i] * v.x; oacc[i][1] += p[i] * v.y;
                oacc[i][2] += p[i] * v.z; oacc[i][3] += p[i] * v.w;
            }
        }
    }
#pragma unroll
    for (int i = 0; i < 4; i++) {
        const float4 v = make_float4(oacc[i][0], oacc[i][1], oacc[i][2], oacc[i][3]);
        *(float4*)(g_O + (rq + ty * 4 + i) * CC + h * 64 + tx * 4) = v;
    }
}

// ---------------- branch 3: window attention -------------------------------------
__global__ __launch_bounds__(256) void attn_win(const float* __restrict__ pos_table) {
    extern __shared__ float sm[];
    float* S   = sm;                    // 64 x 65
    float* Qs  = S + 64 * 65;           // 64 x 64
    float* KV  = Qs + 64 * 64;          // 64 x 68
    float* pos = KV + 64 * 68;          // 343
    const int win = blockIdx.x, h = blockIdx.y, b = blockIdx.z;
    const int wd = win / 36, ww = (win / 6) % 6, wh = win % 6;
    const int tid = threadIdx.x;
    const int tx = tid & 15, ty = tid >> 4;
    const int base = b * NTOK + wd * 4 * 576 + ww * 4 * 24 + wh * 4;
    const int tok = tid >> 4, dv = (tid & 15) * 4;

    for (int e = tid; e < 343; e += 256) pos[e] = pos_table[e];
#pragma unroll
    for (int l = 0; l < 4; l++) {
        const int t = tok + l * 16;
        const int row = base + (t >> 4) * 576 + ((t >> 2) & 3) * 24 + (t & 3);
        *(float4*)(Qs + t * 64 + dv) =
            *(const float4*)(g_Q + row * CC + h * 64 + dv);
        const float4 v = *(const float4*)(g_K + row * CC + h * 64 + dv);
        KV[t * 65 + dv + 0] = v.x; KV[t * 65 + dv + 1] = v.y;
        KV[t * 65 + dv + 2] = v.z; KV[t * 65 + dv + 3] = v.w;
    }
    __syncthreads();
    float sc[4][4];
#pragma unroll
    for (int i = 0; i < 4; i++) { sc[i][0]=0; sc[i][1]=0; sc[i][2]=0; sc[i][3]=0; }
#pragma unroll 8
    for (int d = 0; d < 64; d++) {
        float a[4], bb[4];
#pragma unroll
        for (int i = 0; i < 4; i++) a[i] = Qs[(ty * 4 + i) * 64 + d];
#pragma unroll
        for (int i = 0; i < 4; i++) bb[i] = KV[(tx * 4 + i) * 65 + d];
#pragma unroll
        for (int i = 0; i < 4; i++) {
#pragma unroll
            for (int j = 0; j < 4; j++) sc[i][j] += a[i] * bb[j];
        }
    }
#pragma unroll
    for (int i = 0; i < 4; i++) {
        const int m  = ty * 4 + i;
        const int am = m >> 4, bm = (m >> 2) & 3, cm = m & 3;
#pragma unroll
        for (int j = 0; j < 4; j++) {
            const int jn = tx * 4 + j;
            const int aj = jn >> 4, bj = (jn >> 2) & 3, cj = jn & 3;
            const float bias = pos[(aj - am + 3) * 49 + (bj - bm + 3) * 7 + (cj - cm + 3)];
            S[m * 65 + jn] = sc[i][j] * 0.125f + bias;
        }
    }
    __syncthreads();
    {
        const int r = tid >> 2, q = tid & 3;
        float mx = -1e30f;
        for (int j = q; j < 64; j += 4) mx = fmaxf(mx, S[r * 65 + j]);
        mx = fmaxf(mx, __shfl_xor_sync(0xffffffffu, mx, 1));
        mx = fmaxf(mx, __shfl_xor_sync(0xffffffffu, mx, 2));
        float sum = 0.f;
        for (int j = q; j < 64; j += 4) {
            const float p = __expf(S[r * 65 + j] - mx);
            S[r * 65 + j] = p; sum += p;
        }
        sum += __shfl_xor_sync(0xffffffffu, sum, 1);
        sum += __shfl_xor_sync(0xffffffffu, sum, 2);
        const float inv = 1.f / sum;
        for (int j = q; j < 64; j += 4) S[r * 65 + j] *= inv;
    }
    __syncthreads();
#pragma unroll
    for (int l = 0; l < 4; l++) {
        const int t = tok + l * 16;
        const int row = base + (t >> 4) * 576 + ((t >> 2) & 3) * 24 + (t & 3);
        *(float4*)(KV + t * 68 + dv) =
            *(const float4*)(g_V + row * CC + h * 64 + dv);
    }
    __syncthreads();
    float oacc[4][4];
#pragma unroll
    for (int i = 0; i < 4; i++) { oacc[i][0]=0; oacc[i][1]=0; oacc[i][2]=0; oacc[i][3]=0; }
#pragma unroll 4
    for (int j = 0; j < 64; j++) {
        float p[4];
#pragma unroll
        for (int i = 0; i < 4; i++) p[i] = S[(ty * 4 + i) * 65 + j];
        const float4 v = *(const float4*)(KV + j * 68 + tx * 4);
#pragma unroll
        for (int i = 0; i < 4; i++) {
            oacc[i][0] += p[i] * v.x; oacc[i][1] += p[i] * v.y;
            oacc[i][2] += p[i] * v.z; oacc[i][3] += p[i] * v.w;
        }
    }
#pragma unroll
    for (int i = 0; i < 4; i++) {
        const int m = ty * 4 + i;
        const int row = base + (m >> 4) * 576 + ((m >> 2) & 3) * 24 + (m & 3);
        const float4 v = make_float4(oacc[i][0], oacc[i][1], oacc[i][2], oacc[i][3]);
        *(float4*)(g_O + row * CC + h * 64 + tx * 4) = v;
    }
}

// ---------------- branch 2: tiny seq-24 attention --------------------------------
__global__ __launch_bounds__(256) void attn_seq24() {
    __shared__ float Qs[24 * 65], Ks[24 * 65], Vs[24 * 65], P[24 * 25];
    const int i = blockIdx.x, h = blockIdx.y;
    const int tid = threadIdx.x;
    const int rbase = i * 24 * CC + h * 64;

    for (int e = tid; e < 24 * 64; e += 256) {
        const int k = e >> 6, d = e & 63;
        Qs[k * 65 + d] = g_Q[rbase + k * CC + d];
        Ks[k * 65 + d] = g_K[rbase + k * CC + d];
        Vs[k * 65 + d] = g_V[rbase + k * CC + d];
    }
    __syncthreads();
    for (int sid = tid; sid < 576; sid += 256) {
        const int r = sid / 24, c = sid - r * 24;
        float s = 0.f;
#pragma unroll 16
        for (int d = 0; d < 64; d++) s += Qs[r * 65 + d] * Ks[c * 65 + d];
        P[r * 25 + c] = s * 0.125f;
    }
    __syncthreads();
    if (tid < 24) {
        float mx = -1e30f;
        for (int c = 0; c < 24; c++) mx = fmaxf(mx, P[tid * 25 + c]);
        float sum = 0.f;
        for (int c = 0; c < 24; c++) {
            const float p = __expf(P[tid * 25 + c] - mx);
            P[tid * 25 + c] = p; sum += p;
        }
        const float inv = 1.f / sum;
        for (int c = 0; c < 24; c++) P[tid * 25 + c] *= inv;
    }
    __syncthreads();
    for (int e = tid; e < 24 * 64; e += 256) {
        const int r = e >> 6, d = e & 63;
        float o = 0.f;
#pragma unroll
        for (int j = 0; j < 24; j++) o += P[r * 25 + j] * Vs[j * 65 + d];
        g_O[rbase + r * CC + d] = o;
    }
}

// ---------------- orchestration --------------------------------------------------
extern "C" void kernel_launch(void* const* d_in, const int* in_sizes, int n_in,
                              void* d_out, int out_size) {
    const float* x     = (const float*)d_in[0];
    const float* vq_w  = (const float*)d_in[1];
    const float* vq_b  = (const float*)d_in[2];
    const float* vk_w  = (const float*)d_in[3];
    const float* vk_b  = (const float*)d_in[4];
    const float* vv_w  = (const float*)d_in[5];
    const float* vv_b  = (const float*)d_in[6];
    const float* vo_w  = (const float*)d_in[7];
    const float* vo_b  = (const float*)d_in[8];
    const float* hq_w  = (const float*)d_in[9];
    const float* hq_b  = (const float*)d_in[10];
    const float* hk_w  = (const float*)d_in[11];
    const float* hk_b  = (const float*)d_in[12];
    const float* hv_w  = (const float*)d_in[13];
    const float* hv_b  = (const float*)d_in[14];
    const float* ho_w  = (const float*)d_in[15];
    const float* ho_b  = (const float*)d_in[16];
    const float* qkv_w = (const float*)d_in[17];
    const float* ow_w  = (const float*)d_in[18];
    const float* ow_b  = (const float*)d_in[19];
    const float* pos   = (const float*)d_in[20];
    float* out = (float*)d_out;
    (void)in_sizes; (void)n_in; (void)out_size;

    float *pX, *pQ, *pK, *pV, *pO;
    __nv_bfloat16 *pAh, *pAl, *pWh, *pWl;
    cudaGetSymbolAddress((void**)&pX, g_X);
    cudaGetSymbolAddress((void**)&pQ, g_Q);
    cudaGetSymbolAddress((void**)&pK, g_K);
    cudaGetSymbolAddress((void**)&pV, g_V);
    cudaGetSymbolAddress((void**)&pO, g_O);
    cudaGetSymbolAddress((void**)&pAh, g_Ahi);
    cudaGetSymbolAddress((void**)&pAl, g_Alo);
    cudaGetSymbolAddress((void**)&pWh, g_Whi);
    cudaGetSymbolAddress((void**)&pWl, g_Wlo);

    const int SMEM1 = (64 * 577 + 64 * 64 + 64 * 68) * 4;
    const int SMEM3 = (64 * 65 + 64 * 64 + 64 * 68 + 343) * 4;
    const int SMEMG = 2 * 4 * MATS * 2;   // 81920 B
    cudaFuncSetAttribute(attn_seq576, cudaFuncAttributeMaxDynamicSharedMemorySize, SMEM1);
    cudaFuncSetAttribute(attn_win,    cudaFuncAttributeMaxDynamicSharedMemorySize, SMEM3);
    cudaFuncSetAttribute(mmagemm,     cudaFuncAttributeMaxDynamicSharedMemorySize, SMEMG);

    const dim3 wg(16, 16), wb(32, 8);
    // weight slots: 0 vq, 1 vk, 2 vv, 3 vo, 4 hq, 5 hk, 6 hv, 7 ho,
    //               8 qkv.q, 9 qkv.k, 10 qkv.v, 11 win_out
    wconv<<<wg, wb>>>(vq_w, 512, 0, 0);
    wconv<<<wg, wb>>>(vk_w, 512, 0, 1);
    wconv<<<wg, wb>>>(vv_w, 512, 0, 2);
    wconv<<<wg, wb>>>(vo_w, 512, 0, 3);
    wconv<<<wg, wb>>>(hq_w, 512, 0, 4);
    wconv<<<wg, wb>>>(hk_w, 512, 0, 5);
    wconv<<<wg, wb>>>(hv_w, 512, 0, 6);
    wconv<<<wg, wb>>>(ho_w, 512, 0, 7);
    wconv<<<wg, wb>>>(qkv_w, 1536, 0,    8);
    wconv<<<wg, wb>>>(qkv_w, 1536, 512,  9);
    wconv<<<wg, wb>>>(qkv_w, 1536, 1024, 10);
    wconv<<<wg, wb>>>(ow_w, 512, 0, 11);

    const dim3 gg(4, 216);
    const size_t WS = (size_t)CC * CC;
#define TCG(slot, b, Cp, ac) \
    mmagemm<<<gg, 256, SMEMG>>>(pAh, pAl, pWh + (slot) * WS, pWl + (slot) * WS, b, Cp, ac)

    // ---- branch 1 (seq-576 full attention) ----
    gather_x1<<<dim3(18, 16, 48), dim3(32, 8)>>>(x);
    asplit<<<13824, 256>>>(pX);
    TCG(0, vq_b, pQ, 0);
    TCG(1, vk_b, pK, 0);
    TCG(2, vv_b, pV, 0);
    attn_seq576<<<dim3(9, 8, 48), 256, SMEM1>>>();
    asplit<<<13824, 256>>>(pO);
    TCG(3, vo_b, out, 0);          // first write

    // ---- branch 3 (window attention) ----
    gather_xT<<<dim3(432, 16, 2), dim3(32, 8)>>>(x);
    asplit<<<13824, 256>>>(pX);
    TCG(8, nullptr, pQ, 0);
    TCG(9, nullptr, pK, 0);
    TCG(10, nullptr, pV, 0);
    attn_win<<<dim3(216, 8, 2), 256, SMEM3>>>(pos);
    asplit<<<13824, 256>>>(pO);
    TCG(11, ow_b, out, 1);         // accumulate

    // ---- branch 2 (seq-24 full attention) ----
    gather_x2<<<1152, 256>>>(x);
    asplit<<<13824, 256>>>(pX);
    TCG(4, hq_b, pQ, 0);
    TCG(5, hk_b, pK, 0);
    TCG(6, hv_b, pV, 0);
    attn_seq24<<<dim3(1152, 8), 256>>>();
    asplit<<<13824, 256>>>(pO);
    TCG(7, ho_b, out, 1);          // accumulate
#undef TCG
}

// round 6
// speedup vs baseline: 2.2379x; 1.5182x over previous
#include <cuda_runtime.h>
#include <cuda_bf16.h>
#include <cuda_fp16.h>
#include <cstdint>

#define CC 512
#define NTOK 13824            // 24*24*24
#define TT 27648              // B * NTOK

// ---------------- scratch (device globals; no allocation allowed) ----------------
__device__ float g_X[TT * CC];
__device__ float g_Q[TT * CC];
__device__ float g_K[TT * CC];
__device__ float g_V[TT * CC];
__device__ float g_O[TT * CC];
__device__ __nv_bfloat16 g_Ahi[TT * CC];
__device__ __nv_bfloat16 g_Alo[TT * CC];
__device__ __nv_bfloat16 g_Whi[12 * CC * CC];   // 12 slots of Wt[n][k]
__device__ __nv_bfloat16 g_Wlo[12 * CC * CC];
__device__ __half g_Qh[TT * CC];
__device__ __half g_Kh[TT * CC];
__device__ __half g_Vh[TT * CC];

__device__ __forceinline__ uint32_t smem_to_u32(const void* p) {
    uint32_t a;
    asm("{ .reg .u64 t; cvta.to.shared.u64 t, %1; cvt.u32.u64 %0, t; }" : "=r"(a) : "l"(p));
    return a;
}
__device__ __forceinline__ void ldm4(uint32_t* r, uint32_t addr) {
    asm volatile("ldmatrix.sync.aligned.m8n8.x4.shared.b16 {%0,%1,%2,%3}, [%4];"
                 : "=r"(r[0]), "=r"(r[1]), "=r"(r[2]), "=r"(r[3]) : "r"(addr));
}
__device__ __forceinline__ void ldm4t(uint32_t* r, uint32_t addr) {
    asm volatile("ldmatrix.sync.aligned.m8n8.x4.trans.shared.b16 {%0,%1,%2,%3}, [%4];"
                 : "=r"(r[0]), "=r"(r[1]), "=r"(r[2]), "=r"(r[3]) : "r"(addr));
}
__device__ __forceinline__ void mma_bf16(float* c, const uint32_t* a,
                                         uint32_t b0, uint32_t b1) {
    asm volatile("mma.sync.aligned.m16n8k16.row.col.f32.bf16.bf16.f32 "
                 "{%0,%1,%2,%3}, {%4,%5,%6,%7}, {%8,%9}, {%0,%1,%2,%3};"
                 : "+f"(c[0]), "+f"(c[1]), "+f"(c[2]), "+f"(c[3])
                 : "r"(a[0]), "r"(a[1]), "r"(a[2]), "r"(a[3]), "r"(b0), "r"(b1));
}
__device__ __forceinline__ void mma_f16(float* c, const uint32_t* a,
                                        uint32_t b0, uint32_t b1) {
    asm volatile("mma.sync.aligned.m16n8k16.row.col.f32.f16.f16.f32 "
                 "{%0,%1,%2,%3}, {%4,%5,%6,%7}, {%8,%9}, {%0,%1,%2,%3};"
                 : "+f"(c[0]), "+f"(c[1]), "+f"(c[2]), "+f"(c[3])
                 : "r"(a[0]), "r"(a[1]), "r"(a[2]), "r"(a[3]), "r"(b0), "r"(b1));
}

// ---------------- conversion kernels ---------------------------------------------
__global__ void asplit(const float* __restrict__ src) {
    const size_t i = (size_t)blockIdx.x * 256 + threadIdx.x;   // x4 elems
    const float4 v = ((const float4*)src)[i];
    __nv_bfloat16 h0 = __float2bfloat16(v.x), h1 = __float2bfloat16(v.y);
    __nv_bfloat16 h2 = __float2bfloat16(v.z), h3 = __float2bfloat16(v.w);
    __nv_bfloat16 l0 = __float2bfloat16(v.x - __bfloat162float(h0));
    __nv_bfloat16 l1 = __float2bfloat16(v.y - __bfloat162float(h1));
    __nv_bfloat16 l2 = __float2bfloat16(v.z - __bfloat162float(h2));
    __nv_bfloat16 l3 = __float2bfloat16(v.w - __bfloat162float(h3));
    __nv_bfloat162* oh = (__nv_bfloat162*)(g_Ahi + 4 * i);
    __nv_bfloat162* ol = (__nv_bfloat162*)(g_Alo + 4 * i);
    oh[0] = __nv_bfloat162(h0, h1); oh[1] = __nv_bfloat162(h2, h3);
    ol[0] = __nv_bfloat162(l0, l1); ol[1] = __nv_bfloat162(l2, l3);
}

// Wt[slot][n][k] = W[k*ldb + bcol + n], split to hi/lo
__global__ void wconv(const float* __restrict__ W, int ldb, int bcol, int slot) {
    __shared__ float tile[32][33];
    const int k0 = blockIdx.x * 32, n0 = blockIdx.y * 32;
    const int tx = threadIdx.x, ty = threadIdx.y;   // 32 x 8
#pragma unroll
    for (int l = 0; l < 4; l++)
        tile[ty + 8 * l][tx] = W[(k0 + ty + 8 * l) * ldb + bcol + n0 + tx];
    __syncthreads();
    const size_t base = (size_t)slot * CC * CC;
#pragma unroll
    for (int l = 0; l < 4; l++) {
        const float v = tile[tx][ty + 8 * l];
        const __nv_bfloat16 h = __float2bfloat16(v);
        const __nv_bfloat16 lo = __float2bfloat16(v - __bfloat162float(h));
        const size_t idx = base + (size_t)(n0 + ty + 8 * l) * CC + k0 + tx;
        g_Whi[idx] = h; g_Wlo[idx] = lo;
    }
}

// ------------- mma.sync GEMM: C[T,512](+)= (Ahi+Alo)@(Bhi+Blo)^T + bias ----------
#define GST 40                       // smem row stride (bf16 elems)
#define MATS (128 * GST)             // one matrix (elems)

__global__ __launch_bounds__(256) void mmagemm(
    const __nv_bfloat16* __restrict__ Ahi, const __nv_bfloat16* __restrict__ Alo,
    const __nv_bfloat16* __restrict__ Bhi, const __nv_bfloat16* __restrict__ Blo,
    const float* __restrict__ bias, float* __restrict__ Cmat, int acc,
    __half* __restrict__ Chalf, float hscale)
{
    extern __shared__ __align__(16) __nv_bfloat16 smb[];
    const int tid = threadIdx.x, lane = tid & 31, wid = tid >> 5;
    const int m0 = blockIdx.y * 128, n0 = blockIdx.x * 128;
    const int wm = (wid >> 2) * 64, wn = (wid & 3) * 32;

    float c[4][4][4];
#pragma unroll
    for (int i = 0; i < 4; i++)
#pragma unroll
        for (int j = 0; j < 4; j++) { c[i][j][0]=0; c[i][j][1]=0; c[i][j][2]=0; c[i][j][3]=0; }

    const __nv_bfloat16* pAh = Ahi + (size_t)m0 * CC;
    const __nv_bfloat16* pAl = Alo + (size_t)m0 * CC;
    const __nv_bfloat16* pBh = Bhi + (size_t)n0 * CC;
    const __nv_bfloat16* pBl = Blo + (size_t)n0 * CC;

    const int e0 = tid, e1 = tid + 256;
    const int g0 = (e0 >> 2) * CC + (e0 & 3) * 8, g1 = (e1 >> 2) * CC + (e1 & 3) * 8;
    const int s0 = (e0 >> 2) * GST + (e0 & 3) * 8, s1 = (e1 >> 2) * GST + (e1 & 3) * 8;

    {
        uint4 v;
        v = *(const uint4*)(pAh + g0); *(uint4*)(smb + 0 * MATS + s0) = v;
        v = *(const uint4*)(pAh + g1); *(uint4*)(smb + 0 * MATS + s1) = v;
        v = *(const uint4*)(pAl + g0); *(uint4*)(smb + 1 * MATS + s0) = v;
        v = *(const uint4*)(pAl + g1); *(uint4*)(smb + 1 * MATS + s1) = v;
        v = *(const uint4*)(pBh + g0); *(uint4*)(smb + 2 * MATS + s0) = v;
        v = *(const uint4*)(pBh + g1); *(uint4*)(smb + 2 * MATS + s1) = v;
        v = *(const uint4*)(pBl + g0); *(uint4*)(smb + 3 * MATS + s0) = v;
        v = *(const uint4*)(pBl + g1); *(uint4*)(smb + 3 * MATS + s1) = v;
    }
    __syncthreads();

    for (int kc = 0; kc < 16; kc++) {
        __nv_bfloat16* cur = smb + (kc & 1) * 4 * MATS;
        __nv_bfloat16* nxt = smb + ((kc + 1) & 1) * 4 * MATS;
        const bool pf = (kc + 1) < 16;
        uint4 rr[8];
        if (pf) {
            const int kb = (kc + 1) * 32;
            rr[0] = *(const uint4*)(pAh + g0 + kb); rr[1] = *(const uint4*)(pAh + g1 + kb);
            rr[2] = *(const uint4*)(pAl + g0 + kb); rr[3] = *(const uint4*)(pAl + g1 + kb);
            rr[4] = *(const uint4*)(pBh + g0 + kb); rr[5] = *(const uint4*)(pBh + g1 + kb);
            rr[6] = *(const uint4*)(pBl + g0 + kb); rr[7] = *(const uint4*)(pBl + g1 + kb);
        }
        const uint32_t sb = smem_to_u32(cur);
#pragma unroll
        for (int ks = 0; ks < 2; ks++) {
            uint32_t ah[4][4], al[4][4], bh[2][4], bl[2][4];
#pragma unroll
            for (int mt = 0; mt < 4; mt++) {
                const int r = wm + mt * 16 + (lane & 15);
                const uint32_t ad = sb + (uint32_t)(r * GST + ks * 16 + (lane >> 4) * 8) * 2;
                ldm4(ah[mt], ad);
                ldm4(al[mt], ad + MATS * 2);
            }
#pragma unroll
            for (int bt = 0; bt < 2; bt++) {
                const int r = wn + bt * 16 + (lane & 15);
                const uint32_t bd = sb + (uint32_t)(2 * MATS + r * GST + ks * 16 + (lane >> 4) * 8) * 2;
                ldm4(bh[bt], bd);
                ldm4(bl[bt], bd + MATS * 2);
            }
#pragma unroll
            for (int mt = 0; mt < 4; mt++) {
#pragma unroll
                for (int nt = 0; nt < 4; nt++) {
                    const int bt = nt >> 1, sub = nt & 1;
                    mma_bf16(c[mt][nt], ah[mt], bh[bt][sub], bh[bt][sub + 2]);
                    mma_bf16(c[mt][nt], ah[mt], bl[bt][sub], bl[bt][sub + 2]);
                    mma_bf16(c[mt][nt], al[mt], bh[bt][sub], bh[bt][sub + 2]);
                }
            }
        }
        if (pf) {
            *(uint4*)(nxt + 0 * MATS + s0) = rr[0]; *(uint4*)(nxt + 0 * MATS + s1) = rr[1];
            *(uint4*)(nxt + 1 * MATS + s0) = rr[2]; *(uint4*)(nxt + 1 * MATS + s1) = rr[3];
            *(uint4*)(nxt + 2 * MATS + s0) = rr[4]; *(uint4*)(nxt + 2 * MATS + s1) = rr[5];
            *(uint4*)(nxt + 3 * MATS + s0) = rr[6]; *(uint4*)(nxt + 3 * MATS + s1) = rr[7];
        }
        __syncthreads();
    }

#pragma unroll
    for (int mt = 0; mt < 4; mt++) {
        const int r0 = m0 + wm + mt * 16 + (lane >> 2);
#pragma unroll
        for (int nt = 0; nt < 4; nt++) {
            const int col = n0 + wn + nt * 8 + (lane & 3) * 2;
            float2 v0 = make_float2(c[mt][nt][0], c[mt][nt][1]);
            float2 v1 = make_float2(c[mt][nt][2], c[mt][nt][3]);
            if (bias) {
                const float b0 = bias[col], b1 = bias[col + 1];
                v0.x += b0; v0.y += b1; v1.x += b0; v1.y += b1;
            }
            if (Chalf) {
                *(__half2*)(Chalf + (size_t)r0 * CC + col) =
                    __floats2half2_rn(v0.x * hscale, v0.y * hscale);
                *(__half2*)(Chalf + (size_t)(r0 + 8) * CC + col) =
                    __floats2half2_rn(v1.x * hscale, v1.y * hscale);
            } else {
                float* p0 = Cmat + (size_t)r0 * CC + col;
                float* p1 = Cmat + (size_t)(r0 + 8) * CC + col;
                if (acc) {
                    const float2 o0 = *(const float2*)p0, o1 = *(const float2*)p1;
                    v0.x += o0.x; v0.y += o0.y; v1.x += o1.x; v1.y += o1.y;
                }
                *(float2*)p0 = v0;
                *(float2*)p1 = v1;
            }
        }
    }
}

// ------------- branch 1 attention: flash-style fp16 mma, seq 576 -----------------
// CTA = (qt, h, bd), 128 threads (4 warps), warp owns 16 q-rows.
#define FST 72    // smem half-stride

__global__ __launch_bounds__(128) void attn576_mma() {
    __shared__ __half Qs[64 * FST], Ks[64 * FST], Vs[64 * FST];
    const int qt = blockIdx.x, h = blockIdx.y, bd = blockIdx.z;
    const int tid = threadIdx.x, lane = tid & 31, wid = tid >> 5;
    const int rq = bd * 576 + qt * 64, rb = bd * 576;
    const uint32_t sQ = smem_to_u32(Qs), sK = smem_to_u32(Ks), sV = smem_to_u32(Vs);

    // load Q tile (64 x 64 halfs): 512 uint4s over 128 threads
#pragma unroll
    for (int i = 0; i < 4; i++) {
        const int e = tid + i * 128;
        const int r = e >> 3, cu = e & 7;
        *(uint4*)(Qs + r * FST + cu * 8) =
            *(const uint4*)(g_Qh + (size_t)(rq + r) * CC + h * 64 + cu * 8);
    }
    __syncthreads();

    uint32_t qf[4][4];
#pragma unroll
    for (int ks = 0; ks < 4; ks++) {
        const uint32_t ad = sQ + (uint32_t)((wid * 16 + (lane & 15)) * FST
                                            + ks * 16 + (lane >> 4) * 8) * 2;
        ldm4(qf[ks], ad);
    }

    float oacc[8][4];
#pragma unroll
    for (int nt = 0; nt < 8; nt++) { oacc[nt][0]=0; oacc[nt][1]=0; oacc[nt][2]=0; oacc[nt][3]=0; }
    float mrow[2] = {-1e30f, -1e30f};
    float lrow[2] = {0.f, 0.f};

    for (int kt = 0; kt < 9; kt++) {
        __syncthreads();
#pragma unroll
        for (int i = 0; i < 4; i++) {
            const int e = tid + i * 128;
            const int r = e >> 3, cu = e & 7;
            const size_t grow = (size_t)(rb + kt * 64 + r) * CC + h * 64 + cu * 8;
            *(uint4*)(Ks + r * FST + cu * 8) = *(const uint4*)(g_Kh + grow);
            *(uint4*)(Vs + r * FST + cu * 8) = *(const uint4*)(g_Vh + grow);
        }
        __syncthreads();

        // S = Q @ K^T  (16 x 64 per warp)
        float c[8][4];
#pragma unroll
        for (int nt = 0; nt < 8; nt++) { c[nt][0]=0; c[nt][1]=0; c[nt][2]=0; c[nt][3]=0; }
#pragma unroll
        for (int ks = 0; ks < 4; ks++) {
#pragma unroll
            for (int bt = 0; bt < 4; bt++) {
                uint32_t kf[4];
                const uint32_t kd = sK + (uint32_t)((bt * 16 + (lane & 15)) * FST
                                                    + ks * 16 + (lane >> 4) * 8) * 2;
                ldm4(kf, kd);
                mma_f16(c[bt * 2 + 0], qf[ks], kf[0], kf[2]);
                mma_f16(c[bt * 2 + 1], qf[ks], kf[1], kf[3]);
            }
        }

        // online softmax (rows: r0 = lane>>2, r1 = r0+8; 4 lanes per row)
        float tm0 = -1e30f, tm1 = -1e30f;
#pragma unroll
        for (int nt = 0; nt < 8; nt++) {
            tm0 = fmaxf(tm0, fmaxf(c[nt][0], c[nt][1]));
            tm1 = fmaxf(tm1, fmaxf(c[nt][2], c[nt][3]));
        }
        tm0 = fmaxf(tm0, __shfl_xor_sync(0xffffffffu, tm0, 1));
        tm0 = fmaxf(tm0, __shfl_xor_sync(0xffffffffu, tm0, 2));
        tm1 = fmaxf(tm1, __shfl_xor_sync(0xffffffffu, tm1, 1));
        tm1 = fmaxf(tm1, __shfl_xor_sync(0xffffffffu, tm1, 2));
        const float mn0 = fmaxf(mrow[0], tm0), mn1 = fmaxf(mrow[1], tm1);
        const float al0 = __expf(mrow[0] - mn0), al1 = __expf(mrow[1] - mn1);
        mrow[0] = mn0; mrow[1] = mn1;
        float rs0 = 0.f, rs1 = 0.f;
        uint32_t pf[4][4];
#pragma unroll
        for (int nt = 0; nt < 8; nt++) {
            const float p0 = __expf(c[nt][0] - mn0), p1 = __expf(c[nt][1] - mn0);
            const float p2 = __expf(c[nt][2] - mn1), p3 = __expf(c[nt][3] - mn1);
            rs0 += p0 + p1; rs1 += p2 + p3;
            const int kchunk = nt >> 1, half_sel = nt & 1;
            const __half2 h01 = __floats2half2_rn(p0, p1);
            const __half2 h23 = __floats2half2_rn(p2, p3);
            pf[kchunk][half_sel * 2 + 0] = *(const uint32_t*)&h01;
            pf[kchunk][half_sel * 2 + 1] = *(const uint32_t*)&h23;
        }
        rs0 += __shfl_xor_sync(0xffffffffu, rs0, 1);
        rs0 += __shfl_xor_sync(0xffffffffu, rs0, 2);
        rs1 += __shfl_xor_sync(0xffffffffu, rs1, 1);
        rs1 += __shfl_xor_sync(0xffffffffu, rs1, 2);
        lrow[0] = lrow[0] * al0 + rs0;
        lrow[1] = lrow[1] * al1 + rs1;
#pragma unroll
        for (int nt = 0; nt < 8; nt++) {
            oacc[nt][0] *= al0; oacc[nt][1] *= al0;
            oacc[nt][2] *= al1; oacc[nt][3] *= al1;
        }

        // O += P @ V   (V via ldmatrix.trans)
#pragma unroll
        for (int ks = 0; ks < 4; ks++) {
#pragma unroll
            for (int vt = 0; vt < 4; vt++) {
                uint32_t vf[4];
                const int vr = ks * 16 + (lane & 7) + ((lane >> 3) & 1) * 8;
                const int vc = vt * 16 + (lane >> 4) * 8;
                ldm4t(vf, sV + (uint32_t)(vr * FST + vc) * 2);
                mma_f16(oacc[vt * 2 + 0], pf[ks], vf[0], vf[1]);
                mma_f16(oacc[vt * 2 + 1], pf[ks], vf[2], vf[3]);
            }
        }
    }

    const float il0 = 1.f / lrow[0], il1 = 1.f / lrow[1];
    const int r0 = rq + wid * 16 + (lane >> 2);
#pragma unroll
    for (int nt = 0; nt < 8; nt++) {
        const int col = h * 64 + nt * 8 + (lane & 3) * 2;
        *(float2*)(g_O + (size_t)r0 * CC + col) =
            make_float2(oacc[nt][0] * il0, oacc[nt][1] * il0);
        *(float2*)(g_O + (size_t)(r0 + 8) * CC + col) =
            make_float2(oacc[nt][2] * il1, oacc[nt][3] * il1);
    }
}

// ---- gather branch 1: X1[i*576+p, c1] = x_flat[i*294912 + c1*576 + p], i<48 ----
__global__ void gather_x1(const float* __restrict__ x) {
    __shared__ float tile[32][33];
    const int i  = blockIdx.z;
    const int p0 = blockIdx.x * 32;
    const int c0 = blockIdx.y * 32;
    const int tx = threadIdx.x, ty = threadIdx.y;   // 32 x 8
    const float* src = x + i * 294912;
#pragma unroll
    for (int l = 0; l < 4; l++)
        tile[ty + 8 * l][tx] = src[(c0 + ty + 8 * l) * 576 + p0 + tx];
    __syncthreads();
    float* dst = g_X + (i * 576 + p0) * CC + c0;
#pragma unroll
    for (int l = 0; l < 4; l++)
        dst[(ty + 8 * l) * CC + tx] = tile[tx][ty + 8 * l];
}

// ---- gather branch 3: X3[b*N+n, c] = x[b,c,n] ----------------------------------
__global__ void gather_xT(const float* __restrict__ x) {
    __shared__ float tile[32][33];
    const int b  = blockIdx.z;
    const int n0 = blockIdx.x * 32;
    const int c0 = blockIdx.y * 32;
    const int tx = threadIdx.x, ty = threadIdx.y;   // 32 x 8
    const float* src = x + b * (CC * NTOK);
#pragma unroll
    for (int i = 0; i < 4; i++)
        tile[ty + 8 * i][tx] = src[(c0 + ty + 8 * i) * NTOK + n0 + tx];
    __syncthreads();
    float* dst = g_X + (b * NTOK + n0) * CC + c0;
#pragma unroll
    for (int i = 0; i < 4; i++)
        dst[(ty + 8 * i) * CC + tx] = tile[tx][ty + 8 * i];
}

// ---- gather branch 2: X2[t, c] = x[(t/24)*12288 + c*24 + t%24] ------------------
__global__ void gather_x2(const float* __restrict__ x) {
    __shared__ float t2[24][257];
    const int i = blockIdx.x;
    const float* src = x + i * 12288;
    const int tid = threadIdx.x;              // 256
    for (int half = 0; half < 2; half++) {
        const int j0 = half * 256;
#pragma unroll
        for (int l = 0; l < 24; l++) {
            int e = l * 256 + tid;
            int j = e / 24, k = e - j * 24;
            t2[k][j] = src[j0 * 24 + e];
        }
        __syncthreads();
#pragma unroll
        for (int l = 0; l < 24; l++) {
            int e  = l * 256 + tid;
            int k  = e >> 8, jj = e & 255;
            g_X[(i * 24 + k) * CC + j0 + jj] = t2[k][jj];
        }
        __syncthreads();
    }
}

// ---------------- branch 3: window attention -------------------------------------
__global__ __launch_bounds__(256) void attn_win(const float* __restrict__ pos_table) {
    extern __shared__ float sm[];
    float* S   = sm;                    // 64 x 65
    float* Qs  = S + 64 * 65;           // 64 x 64
    float* KV  = Qs + 64 * 64;          // 64 x 68
    float* pos = KV + 64 * 68;          // 343
    const int win = blockIdx.x, h = blockIdx.y, b = blockIdx.z;
    const int wd = win / 36, ww = (win / 6) % 6, wh = win % 6;
    const int tid = threadIdx.x;
    const int tx = tid & 15, ty = tid >> 4;
    const int base = b * NTOK + wd * 4 * 576 + ww * 4 * 24 + wh * 4;
    const int tok = tid >> 4, dv = (tid & 15) * 4;

    for (int e = tid; e < 343; e += 256) pos[e] = pos_table[e];
#pragma unroll
    for (int l = 0; l < 4; l++) {
        const int t = tok + l * 16;
        const int row = base + (t >> 4) * 576 + ((t >> 2) & 3) * 24 + (t & 3);
        *(float4*)(Qs + t * 64 + dv) =
            *(const float4*)(g_Q + row * CC + h * 64 + dv);
        const float4 v = *(const float4*)(g_K + row * CC + h * 64 + dv);
        KV[t * 65 + dv + 0] = v.x; KV[t * 65 + dv + 1] = v.y;
        KV[t * 65 + dv + 2] = v.z; KV[t * 65 + dv + 3] = v.w;
    }
    __syncthreads();
    float sc[4][4];
#pragma unroll
    for (int i = 0; i < 4; i++) { sc[i][0]=0; sc[i][1]=0; sc[i][2]=0; sc[i][3]=0; }
#pragma unroll 8
    for (int d = 0; d < 64; d++) {
        float a[4], bb[4];
#pragma unroll
        for (int i = 0; i < 4; i++) a[i] = Qs[(ty * 4 + i) * 64 + d];
#pragma unroll
        for (int i = 0; i < 4; i++) bb[i] = KV[(tx * 4 + i) * 65 + d];
#pragma unroll
        for (int i = 0; i < 4; i++) {
#pragma unroll
            for (int j = 0; j < 4; j++) sc[i][j] += a[i] * bb[j];
        }
    }
#pragma unroll
    for (int i = 0; i < 4; i++) {
        const int m  = ty * 4 + i;
        const int am = m >> 4, bm = (m >> 2) & 3, cm = m & 3;
#pragma unroll
        for (int j = 0; j < 4; j++) {
            const int jn = tx * 4 + j;
            const int aj = jn >> 4, bj = (jn >> 2) & 3, cj = jn & 3;
            const float bias = pos[(aj - am + 3) * 49 + (bj - bm + 3) * 7 + (cj - cm + 3)];
            S[m * 65 + jn] = sc[i][j] * 0.125f + bias;
        }
    }
    __syncthreads();
    {
        const int r = tid >> 2, q = tid & 3;
        float mx = -1e30f;
        for (int j = q; j < 64; j += 4) mx = fmaxf(mx, S[r * 65 + j]);
        mx = fmaxf(mx, __shfl_xor_sync(0xffffffffu, mx, 1));
        mx = fmaxf(mx, __shfl_xor_sync(0xffffffffu, mx, 2));
        float sum = 0.f;
        for (int j = q; j < 64; j += 4) {
            const float p = __expf(S[r * 65 + j] - mx);
            S[r * 65 + j] = p; sum += p;
        }
        sum += __shfl_xor_sync(0xffffffffu, sum, 1);
        sum += __shfl_xor_sync(0xffffffffu, sum, 2);
        const float inv = 1.f / sum;
        for (int j = q; j < 64; j += 4) S[r * 65 + j] *= inv;
    }
    __syncthreads();
#pragma unroll
    for (int l = 0; l < 4; l++) {
        const int t = tok + l * 16;
        const int row = base + (t >> 4) * 576 + ((t >> 2) & 3) * 24 + (t & 3);
        *(float4*)(KV + t * 68 + dv) =
            *(const float4*)(g_V + row * CC + h * 64 + dv);
    }
    __syncthreads();
    float oacc[4][4];
#pragma unroll
    for (int i = 0; i < 4; i++) { oacc[i][0]=0; oacc[i][1]=0; oacc[i][2]=0; oacc[i][3]=0; }
#pragma unroll 4
    for (int j = 0; j < 64; j++) {
        float p[4];
#pragma unroll
        for (int i = 0; i < 4; i++) p[i] = S[(ty * 4 + i) * 65 + j];
        const float4 v = *(const float4*)(KV + j * 68 + tx * 4);
#pragma unroll
        for (int i = 0; i < 4; i++) {
            oacc[i][0] += p[i] * v.x; oacc[i][1] += p[i] * v.y;
            oacc[i][2] += p[i] * v.z; oacc[i][3] += p[i] * v.w;
        }
    }
#pragma unroll
    for (int i = 0; i < 4; i++) {
        const int m = ty * 4 + i;
        const int row = base + (m >> 4) * 576 + ((m >> 2) & 3) * 24 + (m & 3);
        const float4 v = make_float4(oacc[i][0], oacc[i][1], oacc[i][2], oacc[i][3]);
        *(float4*)(g_O + row * CC + h * 64 + tx * 4) = v;
    }
}

// ---------------- branch 2: tiny seq-24 attention --------------------------------
__global__ __launch_bounds__(256) void attn_seq24() {
    __shared__ float Qs[24 * 65], Ks[24 * 65], Vs[24 * 65], P[24 * 25];
    const int i = blockIdx.x, h = blockIdx.y;
    const int tid = threadIdx.x;
    const int rbase = i * 24 * CC + h * 64;

    for (int e = tid; e < 24 * 64; e += 256) {
        const int k = e >> 6, d = e & 63;
        Qs[k * 65 + d] = g_Q[rbase + k * CC + d];
        Ks[k * 65 + d] = g_K[rbase + k * CC + d];
        Vs[k * 65 + d] = g_V[rbase + k * CC + d];
    }
    __syncthreads();
    for (int sid = tid; sid < 576; sid += 256) {
        const int r = sid / 24, c = sid - r * 24;
        float s = 0.f;
#pragma unroll 16
        for (int d = 0; d < 64; d++) s += Qs[r * 65 + d] * Ks[c * 65 + d];
        P[r * 25 + c] = s * 0.125f;
    }
    __syncthreads();
    if (tid < 24) {
        float mx = -1e30f;
        for (int c = 0; c < 24; c++) mx = fmaxf(mx, P[tid * 25 + c]);
        float sum = 0.f;
        for (int c = 0; c < 24; c++) {
            const float p = __expf(P[tid * 25 + c] - mx);
            P[tid * 25 + c] = p; sum += p;
        }
        const float inv = 1.f / sum;
        for (int c = 0; c < 24; c++) P[tid * 25 + c] *= inv;
    }
    __syncthreads();
    for (int e = tid; e < 24 * 64; e += 256) {
        const int r = e >> 6, d = e & 63;
        float o = 0.f;
#pragma unroll
        for (int j = 0; j < 24; j++) o += P[r * 25 + j] * Vs[j * 65 + d];
        g_O[rbase + r * CC + d] = o;
    }
}

// ---------------- orchestration --------------------------------------------------
extern "C" void kernel_launch(void* const* d_in, const int* in_sizes, int n_in,
                              void* d_out, int out_size) {
    const float* x     = (const float*)d_in[0];
    const float* vq_w  = (const float*)d_in[1];
    const float* vq_b  = (const float*)d_in[2];
    const float* vk_w  = (const float*)d_in[3];
    const float* vk_b  = (const float*)d_in[4];
    const float* vv_w  = (const float*)d_in[5];
    const float* vv_b  = (const float*)d_in[6];
    const float* vo_w  = (const float*)d_in[7];
    const float* vo_b  = (const float*)d_in[8];
    const float* hq_w  = (const float*)d_in[9];
    const float* hq_b  = (const float*)d_in[10];
    const float* hk_w  = (const float*)d_in[11];
    const float* hk_b  = (const float*)d_in[12];
    const float* hv_w  = (const float*)d_in[13];
    const float* hv_b  = (const float*)d_in[14];
    const float* ho_w  = (const float*)d_in[15];
    const float* ho_b  = (const float*)d_in[16];
    const float* qkv_w = (const float*)d_in[17];
    const float* ow_w  = (const float*)d_in[18];
    const float* ow_b  = (const float*)d_in[19];
    const float* pos   = (const float*)d_in[20];
    float* out = (float*)d_out;
    (void)in_sizes; (void)n_in; (void)out_size;

    float *pX, *pQ, *pK, *pV, *pO;
    __nv_bfloat16 *pAh, *pAl, *pWh, *pWl;
    __half *pQh, *pKh, *pVh;
    cudaGetSymbolAddress((void**)&pX, g_X);
    cudaGetSymbolAddress((void**)&pQ, g_Q);
    cudaGetSymbolAddress((void**)&pK, g_K);
    cudaGetSymbolAddress((void**)&pV, g_V);
    cudaGetSymbolAddress((void**)&pO, g_O);
    cudaGetSymbolAddress((void**)&pAh, g_Ahi);
    cudaGetSymbolAddress((void**)&pAl, g_Alo);
    cudaGetSymbolAddress((void**)&pWh, g_Whi);
    cudaGetSymbolAddress((void**)&pWl, g_Wlo);
    cudaGetSymbolAddress((void**)&pQh, g_Qh);
    cudaGetSymbolAddress((void**)&pKh, g_Kh);
    cudaGetSymbolAddress((void**)&pVh, g_Vh);

    const int SMEM3 = (64 * 65 + 64 * 64 + 64 * 68 + 343) * 4;
    const int SMEMG = 2 * 4 * MATS * 2;   // 81920 B
    cudaFuncSetAttribute(attn_win, cudaFuncAttributeMaxDynamicSharedMemorySize, SMEM3);
    cudaFuncSetAttribute(mmagemm,  cudaFuncAttributeMaxDynamicSharedMemorySize, SMEMG);

    const dim3 wg(16, 16), wb(32, 8);
    // weight slots: 0 vq, 1 vk, 2 vv, 3 vo, 4 hq, 5 hk, 6 hv, 7 ho,
    //               8 qkv.q, 9 qkv.k, 10 qkv.v, 11 win_out
    wconv<<<wg, wb>>>(vq_w, 512, 0, 0);
    wconv<<<wg, wb>>>(vk_w, 512, 0, 1);
    wconv<<<wg, wb>>>(vv_w, 512, 0, 2);
    wconv<<<wg, wb>>>(vo_w, 512, 0, 3);
    wconv<<<wg, wb>>>(hq_w, 512, 0, 4);
    wconv<<<wg, wb>>>(hk_w, 512, 0, 5);
    wconv<<<wg, wb>>>(hv_w, 512, 0, 6);
    wconv<<<wg, wb>>>(ho_w, 512, 0, 7);
    wconv<<<wg, wb>>>(qkv_w, 1536, 0,    8);
    wconv<<<wg, wb>>>(qkv_w, 1536, 512,  9);
    wconv<<<wg, wb>>>(qkv_w, 1536, 1024, 10);
    wconv<<<wg, wb>>>(ow_w, 512, 0, 11);

    const dim3 gg(4, 216);
    const size_t WS = (size_t)CC * CC;
#define TCG(slot, b, Cp, ac) \
    mmagemm<<<gg, 256, SMEMG>>>(pAh, pAl, pWh + (slot) * WS, pWl + (slot) * WS, \
                                b, Cp, ac, nullptr, 1.f)
#define TCGH(slot, b, Hp, sc) \
    mmagemm<<<gg, 256, SMEMG>>>(pAh, pAl, pWh + (slot) * WS, pWl + (slot) * WS, \
                                b, nullptr, 0, Hp, sc)

    // ---- branch 1 (seq-576 full attention, fp16 flash) ----
    gather_x1<<<dim3(18, 16, 48), dim3(32, 8)>>>(x);
    asplit<<<13824, 256>>>(pX);
    TCGH(0, vq_b, pQh, 0.125f);
    TCGH(1, vk_b, pKh, 1.f);
    TCGH(2, vv_b, pVh, 1.f);
    attn576_mma<<<dim3(9, 8, 48), 128>>>();
    asplit<<<13824, 256>>>(pO);
    TCG(3, vo_b, out, 0);          // first write

    // ---- branch 3 (window attention) ----
    gather_xT<<<dim3(432, 16, 2), dim3(32, 8)>>>(x);
    asplit<<<13824, 256>>>(pX);
    TCG(8, nullptr, pQ, 0);
    TCG(9, nullptr, pK, 0);
    TCG(10, nullptr, pV, 0);
    attn_win<<<dim3(216, 8, 2), 256, SMEM3>>>(pos);
    asplit<<<13824, 256>>>(pO);
    TCG(11, ow_b, out, 1);         // accumulate

    // ---- branch 2 (seq-24 full attention) ----
    gather_x2<<<1152, 256>>>(x);
    asplit<<<13824, 256>>>(pX);
    TCG(4, hq_b, pQ, 0);
    TCG(5, hk_b, pK, 0);
    TCG(6, hv_b, pV, 0);
    attn_seq24<<<dim3(1152, 8), 256>>>();
    asplit<<<13824, 256>>>(pO);
    TCG(7, ho_b, out, 1);          // accumulate
#undef TCG
#undef TCGH
}

// round 7
// speedup vs baseline: 2.6027x; 1.1630x over previous
#include <cuda_runtime.h>
#include <cuda_bf16.h>
#include <cuda_fp16.h>
#include <cstdint>

#define CC 512
#define NTOK 13824            // 24*24*24
#define TT 27648              // B * NTOK

// ---------------- scratch (device globals; no allocation allowed) ----------------
__device__ float g_X[TT * CC];
__device__ float g_Q[TT * CC];
__device__ float g_K[TT * CC];
__device__ float g_V[TT * CC];
__device__ float g_O[TT * CC];
__device__ __nv_bfloat16 g_Ahi[TT * CC];
__device__ __nv_bfloat16 g_Alo[TT * CC];
__device__ __nv_bfloat16 g_Whi[12 * CC * CC];   // 12 slots of Wt[n][k]
__device__ __nv_bfloat16 g_Wlo[12 * CC * CC];
__device__ __half g_Qh[TT * CC];
__device__ __half g_Kh[TT * CC];
__device__ __half g_Vh[TT * CC];

__device__ __forceinline__ uint32_t smem_to_u32(const void* p) {
    uint32_t a;
    asm("{ .reg .u64 t; cvta.to.shared.u64 t, %1; cvt.u32.u64 %0, t; }" : "=r"(a) : "l"(p));
    return a;
}
__device__ __forceinline__ void ldm4(uint32_t* r, uint32_t addr) {
    asm volatile("ldmatrix.sync.aligned.m8n8.x4.shared.b16 {%0,%1,%2,%3}, [%4];"
                 : "=r"(r[0]), "=r"(r[1]), "=r"(r[2]), "=r"(r[3]) : "r"(addr));
}
__device__ __forceinline__ void ldm4t(uint32_t* r, uint32_t addr) {
    asm volatile("ldmatrix.sync.aligned.m8n8.x4.trans.shared.b16 {%0,%1,%2,%3}, [%4];"
                 : "=r"(r[0]), "=r"(r[1]), "=r"(r[2]), "=r"(r[3]) : "r"(addr));
}
__device__ __forceinline__ void mma_bf16(float* c, const uint32_t* a,
                                         uint32_t b0, uint32_t b1) {
    asm volatile("mma.sync.aligned.m16n8k16.row.col.f32.bf16.bf16.f32 "
                 "{%0,%1,%2,%3}, {%4,%5,%6,%7}, {%8,%9}, {%0,%1,%2,%3};"
                 : "+f"(c[0]), "+f"(c[1]), "+f"(c[2]), "+f"(c[3])
                 : "r"(a[0]), "r"(a[1]), "r"(a[2]), "r"(a[3]), "r"(b0), "r"(b1));
}
__device__ __forceinline__ void mma_f16(float* c, const uint32_t* a,
                                        uint32_t b0, uint32_t b1) {
    asm volatile("mma.sync.aligned.m16n8k16.row.col.f32.f16.f16.f32 "
                 "{%0,%1,%2,%3}, {%4,%5,%6,%7}, {%8,%9}, {%0,%1,%2,%3};"
                 : "+f"(c[0]), "+f"(c[1]), "+f"(c[2]), "+f"(c[3])
                 : "r"(a[0]), "r"(a[1]), "r"(a[2]), "r"(a[3]), "r"(b0), "r"(b1));
}
__device__ __forceinline__ void cp16(uint32_t d, const void* s) {
    asm volatile("cp.async.cg.shared.global [%0], [%1], 16;" :: "r"(d), "l"(s));
}
#define CP_COMMIT() asm volatile("cp.async.commit_group;" ::: "memory")
#define CP_WAIT(n)  asm volatile("cp.async.wait_group %0;" :: "n"(n) : "memory")

// ---------------- conversion kernels ---------------------------------------------
__global__ void asplit(const float* __restrict__ src) {
    const size_t i = (size_t)blockIdx.x * 256 + threadIdx.x;   // x4 elems
    const float4 v = ((const float4*)src)[i];
    __nv_bfloat16 h0 = __float2bfloat16(v.x), h1 = __float2bfloat16(v.y);
    __nv_bfloat16 h2 = __float2bfloat16(v.z), h3 = __float2bfloat16(v.w);
    __nv_bfloat16 l0 = __float2bfloat16(v.x - __bfloat162float(h0));
    __nv_bfloat16 l1 = __float2bfloat16(v.y - __bfloat162float(h1));
    __nv_bfloat16 l2 = __float2bfloat16(v.z - __bfloat162float(h2));
    __nv_bfloat16 l3 = __float2bfloat16(v.w - __bfloat162float(h3));
    __nv_bfloat162* oh = (__nv_bfloat162*)(g_Ahi + 4 * i);
    __nv_bfloat162* ol = (__nv_bfloat162*)(g_Alo + 4 * i);
    oh[0] = __nv_bfloat162(h0, h1); oh[1] = __nv_bfloat162(h2, h3);
    ol[0] = __nv_bfloat162(l0, l1); ol[1] = __nv_bfloat162(l2, l3);
}

// Wt[slot][n][k] = W[k*ldb + bcol + n], split to hi/lo
__global__ void wconv(const float* __restrict__ W, int ldb, int bcol, int slot) {
    __shared__ float tile[32][33];
    const int k0 = blockIdx.x * 32, n0 = blockIdx.y * 32;
    const int tx = threadIdx.x, ty = threadIdx.y;   // 32 x 8
#pragma unroll
    for (int l = 0; l < 4; l++)
        tile[ty + 8 * l][tx] = W[(k0 + ty + 8 * l) * ldb + bcol + n0 + tx];
    __syncthreads();
    const size_t base = (size_t)slot * CC * CC;
#pragma unroll
    for (int l = 0; l < 4; l++) {
        const float v = tile[tx][ty + 8 * l];
        const __nv_bfloat16 h = __float2bfloat16(v);
        const __nv_bfloat16 lo = __float2bfloat16(v - __bfloat162float(h));
        const size_t idx = base + (size_t)(n0 + ty + 8 * l) * CC + k0 + tx;
        g_Whi[idx] = h; g_Wlo[idx] = lo;
    }
}

// ------------- mma.sync GEMM v2: cp.async 2-stage, 2 CTAs/SM ---------------------
#define GST 40                       // smem row stride (bf16 elems)
#define MATS (128 * GST)             // one matrix (elems)

__global__ __launch_bounds__(256, 2) void mmagemm(
    const __nv_bfloat16* __restrict__ Ahi, const __nv_bfloat16* __restrict__ Alo,
    const __nv_bfloat16* __restrict__ Bhi, const __nv_bfloat16* __restrict__ Blo,
    const float* __restrict__ bias, float* __restrict__ Cmat, int acc,
    __half* __restrict__ Chalf, float hscale)
{
    extern __shared__ __align__(16) __nv_bfloat16 smb[];
    const int tid = threadIdx.x, lane = tid & 31, wid = tid >> 5;
    const int m0 = blockIdx.y * 128, n0 = blockIdx.x * 128;
    const int wm = (wid >> 2) * 64, wn = (wid & 3) * 32;

    float c[4][4][4];
#pragma unroll
    for (int i = 0; i < 4; i++)
#pragma unroll
        for (int j = 0; j < 4; j++) { c[i][j][0]=0; c[i][j][1]=0; c[i][j][2]=0; c[i][j][3]=0; }

    const __nv_bfloat16* pAh = Ahi + (size_t)m0 * CC;
    const __nv_bfloat16* pAl = Alo + (size_t)m0 * CC;
    const __nv_bfloat16* pBh = Bhi + (size_t)n0 * CC;
    const __nv_bfloat16* pBl = Blo + (size_t)n0 * CC;

    const int g0 = (tid >> 2) * CC + (tid & 3) * 8;
    const int g1 = g0 + 64 * CC;
    const uint32_t s0 = (uint32_t)((tid >> 2) * GST + (tid & 3) * 8);
    const uint32_t s1 = s0 + 64 * GST;
    const uint32_t smb32 = smem_to_u32(smb);

#define ISSUE(stage, kb) do {                                               \
        const uint32_t sbs = smb32 + (uint32_t)(stage) * (4 * MATS * 2);    \
        cp16(sbs + (0 * MATS + s0) * 2, pAh + g0 + (kb));                   \
        cp16(sbs + (0 * MATS + s1) * 2, pAh + g1 + (kb));                   \
        cp16(sbs + (1 * MATS + s0) * 2, pAl + g0 + (kb));                   \
        cp16(sbs + (1 * MATS + s1) * 2, pAl + g1 + (kb));                   \
        cp16(sbs + (2 * MATS + s0) * 2, pBh + g0 + (kb));                   \
        cp16(sbs + (2 * MATS + s1) * 2, pBh + g1 + (kb));                   \
        cp16(sbs + (3 * MATS + s0) * 2, pBl + g0 + (kb));                   \
        cp16(sbs + (3 * MATS + s1) * 2, pBl + g1 + (kb));                   \
        CP_COMMIT();                                                        \
    } while (0)

    ISSUE(0, 0);
    for (int kc = 0; kc < 16; kc++) {
        if (kc + 1 < 16) { ISSUE((kc + 1) & 1, (kc + 1) * 32); CP_WAIT(1); }
        else             { CP_WAIT(0); }
        __syncthreads();
        const uint32_t sb = smb32 + (uint32_t)(kc & 1) * (4 * MATS * 2);
#pragma unroll
        for (int ks = 0; ks < 2; ks++) {
            uint32_t bh[2][4], bl[2][4];
#pragma unroll
            for (int bt = 0; bt < 2; bt++) {
                const int r = wn + bt * 16 + (lane & 15);
                const uint32_t bd = sb + (uint32_t)(2 * MATS + r * GST + ks * 16 + (lane >> 4) * 8) * 2;
                ldm4(bh[bt], bd);
                ldm4(bl[bt], bd + MATS * 2);
            }
#pragma unroll
            for (int mt = 0; mt < 4; mt++) {
                uint32_t ah[4], al[4];
                const int r = wm + mt * 16 + (lane & 15);
                const uint32_t ad = sb + (uint32_t)(r * GST + ks * 16 + (lane >> 4) * 8) * 2;
                ldm4(ah, ad);
                ldm4(al, ad + MATS * 2);
#pragma unroll
                for (int nt = 0; nt < 4; nt++) {
                    const int bt = nt >> 1, sub = nt & 1;
                    mma_bf16(c[mt][nt], ah, bh[bt][sub], bh[bt][sub + 2]);
                    mma_bf16(c[mt][nt], ah, bl[bt][sub], bl[bt][sub + 2]);
                    mma_bf16(c[mt][nt], al, bh[bt][sub], bh[bt][sub + 2]);
                }
            }
        }
        __syncthreads();
    }
#undef ISSUE

#pragma unroll
    for (int mt = 0; mt < 4; mt++) {
        const int r0 = m0 + wm + mt * 16 + (lane >> 2);
#pragma unroll
        for (int nt = 0; nt < 4; nt++) {
            const int col = n0 + wn + nt * 8 + (lane & 3) * 2;
            float2 v0 = make_float2(c[mt][nt][0], c[mt][nt][1]);
            float2 v1 = make_float2(c[mt][nt][2], c[mt][nt][3]);
            if (bias) {
                const float b0 = bias[col], b1 = bias[col + 1];
                v0.x += b0; v0.y += b1; v1.x += b0; v1.y += b1;
            }
            if (Chalf) {
                *(__half2*)(Chalf + (size_t)r0 * CC + col) =
                    __floats2half2_rn(v0.x * hscale, v0.y * hscale);
                *(__half2*)(Chalf + (size_t)(r0 + 8) * CC + col) =
                    __floats2half2_rn(v1.x * hscale, v1.y * hscale);
            } else {
                float* p0 = Cmat + (size_t)r0 * CC + col;
                float* p1 = Cmat + (size_t)(r0 + 8) * CC + col;
                if (acc) {
                    const float2 o0 = *(const float2*)p0, o1 = *(const float2*)p1;
                    v0.x += o0.x; v0.y += o0.y; v1.x += o1.x; v1.y += o1.y;
                }
                *(float2*)p0 = v0;
                *(float2*)p1 = v1;
            }
        }
    }
}

// ------------- branch 1 attention: flash-style fp16 mma, seq 576 -----------------
#define FST 72    // smem half-stride

__global__ __launch_bounds__(128) void attn576_mma() {
    __shared__ __half Qs[64 * FST], Ks[64 * FST], Vs[64 * FST];
    const int qt = blockIdx.x, h = blockIdx.y, bd = blockIdx.z;
    const int tid = threadIdx.x, lane = tid & 31, wid = tid >> 5;
    const int rq = bd * 576 + qt * 64, rb = bd * 576;
    const uint32_t sQ = smem_to_u32(Qs), sK = smem_to_u32(Ks), sV = smem_to_u32(Vs);

#pragma unroll
    for (int i = 0; i < 4; i++) {
        const int e = tid + i * 128;
        const int r = e >> 3, cu = e & 7;
        *(uint4*)(Qs + r * FST + cu * 8) =
            *(const uint4*)(g_Qh + (size_t)(rq + r) * CC + h * 64 + cu * 8);
    }
    __syncthreads();

    uint32_t qf[4][4];
#pragma unroll
    for (int ks = 0; ks < 4; ks++) {
        const uint32_t ad = sQ + (uint32_t)((wid * 16 + (lane & 15)) * FST
                                            + ks * 16 + (lane >> 4) * 8) * 2;
        ldm4(qf[ks], ad);
    }

    float oacc[8][4];
#pragma unroll
    for (int nt = 0; nt < 8; nt++) { oacc[nt][0]=0; oacc[nt][1]=0; oacc[nt][2]=0; oacc[nt][3]=0; }
    float mrow[2] = {-1e30f, -1e30f};
    float lrow[2] = {0.f, 0.f};

    for (int kt = 0; kt < 9; kt++) {
        __syncthreads();
#pragma unroll
        for (int i = 0; i < 4; i++) {
            const int e = tid + i * 128;
            const int r = e >> 3, cu = e & 7;
            const size_t grow = (size_t)(rb + kt * 64 + r) * CC + h * 64 + cu * 8;
            *(uint4*)(Ks + r * FST + cu * 8) = *(const uint4*)(g_Kh + grow);
            *(uint4*)(Vs + r * FST + cu * 8) = *(const uint4*)(g_Vh + grow);
        }
        __syncthreads();

        float c[8][4];
#pragma unroll
        for (int nt = 0; nt < 8; nt++) { c[nt][0]=0; c[nt][1]=0; c[nt][2]=0; c[nt][3]=0; }
#pragma unroll
        for (int ks = 0; ks < 4; ks++) {
#pragma unroll
            for (int bt = 0; bt < 4; bt++) {
                uint32_t kf[4];
                const uint32_t kd = sK + (uint32_t)((bt * 16 + (lane & 15)) * FST
                                                    + ks * 16 + (lane >> 4) * 8) * 2;
                ldm4(kf, kd);
                mma_f16(c[bt * 2 + 0], qf[ks], kf[0], kf[2]);
                mma_f16(c[bt * 2 + 1], qf[ks], kf[1], kf[3]);
            }
        }

        float tm0 = -1e30f, tm1 = -1e30f;
#pragma unroll
        for (int nt = 0; nt < 8; nt++) {
            tm0 = fmaxf(tm0, fmaxf(c[nt][0], c[nt][1]));
            tm1 = fmaxf(tm1, fmaxf(c[nt][2], c[nt][3]));
        }
        tm0 = fmaxf(tm0, __shfl_xor_sync(0xffffffffu, tm0, 1));
        tm0 = fmaxf(tm0, __shfl_xor_sync(0xffffffffu, tm0, 2));
        tm1 = fmaxf(tm1, __shfl_xor_sync(0xffffffffu, tm1, 1));
        tm1 = fmaxf(tm1, __shfl_xor_sync(0xffffffffu, tm1, 2));
        const float mn0 = fmaxf(mrow[0], tm0), mn1 = fmaxf(mrow[1], tm1);
        const float al0 = __expf(mrow[0] - mn0), al1 = __expf(mrow[1] - mn1);
        mrow[0] = mn0; mrow[1] = mn1;
        float rs0 = 0.f, rs1 = 0.f;
        uint32_t pf[4][4];
#pragma unroll
        for (int nt = 0; nt < 8; nt++) {
            const float p0 = __expf(c[nt][0] - mn0), p1 = __expf(c[nt][1] - mn0);
            const float p2 = __expf(c[nt][2] - mn1), p3 = __expf(c[nt][3] - mn1);
            rs0 += p0 + p1; rs1 += p2 + p3;
            const int kchunk = nt >> 1, half_sel = nt & 1;
            const __half2 h01 = __floats2half2_rn(p0, p1);
            const __half2 h23 = __floats2half2_rn(p2, p3);
            pf[kchunk][half_sel * 2 + 0] = *(const uint32_t*)&h01;
            pf[kchunk][half_sel * 2 + 1] = *(const uint32_t*)&h23;
        }
        rs0 += __shfl_xor_sync(0xffffffffu, rs0, 1);
        rs0 += __shfl_xor_sync(0xffffffffu, rs0, 2);
        rs1 += __shfl_xor_sync(0xffffffffu, rs1, 1);
        rs1 += __shfl_xor_sync(0xffffffffu, rs1, 2);
        lrow[0] = lrow[0] * al0 + rs0;
        lrow[1] = lrow[1] * al1 + rs1;
#pragma unroll
        for (int nt = 0; nt < 8; nt++) {
            oacc[nt][0] *= al0; oacc[nt][1] *= al0;
            oacc[nt][2] *= al1; oacc[nt][3] *= al1;
        }

#pragma unroll
        for (int ks = 0; ks < 4; ks++) {
#pragma unroll
            for (int vt = 0; vt < 4; vt++) {
                uint32_t vf[4];
                const int vr = ks * 16 + (lane & 7) + ((lane >> 3) & 1) * 8;
                const int vc = vt * 16 + (lane >> 4) * 8;
                ldm4t(vf, sV + (uint32_t)(vr * FST + vc) * 2);
                mma_f16(oacc[vt * 2 + 0], pf[ks], vf[0], vf[1]);
                mma_f16(oacc[vt * 2 + 1], pf[ks], vf[2], vf[3]);
            }
        }
    }

    const float il0 = 1.f / lrow[0], il1 = 1.f / lrow[1];
    const int r0 = rq + wid * 16 + (lane >> 2);
#pragma unroll
    for (int nt = 0; nt < 8; nt++) {
        const int col = h * 64 + nt * 8 + (lane & 3) * 2;
        *(float2*)(g_O + (size_t)r0 * CC + col) =
            make_float2(oacc[nt][0] * il0, oacc[nt][1] * il0);
        *(float2*)(g_O + (size_t)(r0 + 8) * CC + col) =
            make_float2(oacc[nt][2] * il1, oacc[nt][3] * il1);
    }
}

// ------------- branch 3: window attention, fp16 mma ------------------------------
__global__ __launch_bounds__(128) void attnwin_mma(const float* __restrict__ pos_table) {
    __shared__ __half Qs[64 * FST], Ks[64 * FST], Vs[64 * FST];
    __shared__ float pos[343];
    const int win = blockIdx.x, h = blockIdx.y, b = blockIdx.z;
    const int wd = win / 36, ww = (win / 6) % 6, wh = win % 6;
    const int tid = threadIdx.x, lane = tid & 31, wid = tid >> 5;
    const int base = b * NTOK + wd * 4 * 576 + ww * 4 * 24 + wh * 4;
    const uint32_t sQ = smem_to_u32(Qs), sK = smem_to_u32(Ks), sV = smem_to_u32(Vs);

    for (int e = tid; e < 343; e += 128) pos[e] = pos_table[e];
#pragma unroll
    for (int i = 0; i < 4; i++) {
        const int e = tid + i * 128;
        const int r = e >> 3, cu = e & 7;
        const int grow = base + (r >> 4) * 576 + ((r >> 2) & 3) * 24 + (r & 3);
        const size_t go = (size_t)grow * CC + h * 64 + cu * 8;
        *(uint4*)(Qs + r * FST + cu * 8) = *(const uint4*)(g_Qh + go);
        *(uint4*)(Ks + r * FST + cu * 8) = *(const uint4*)(g_Kh + go);
        *(uint4*)(Vs + r * FST + cu * 8) = *(const uint4*)(g_Vh + go);
    }
    __syncthreads();

    uint32_t qf[4][4];
#pragma unroll
    for (int ks = 0; ks < 4; ks++) {
        const uint32_t ad = sQ + (uint32_t)((wid * 16 + (lane & 15)) * FST
                                            + ks * 16 + (lane >> 4) * 8) * 2;
        ldm4(qf[ks], ad);
    }

    float c[8][4];
#pragma unroll
    for (int nt = 0; nt < 8; nt++) { c[nt][0]=0; c[nt][1]=0; c[nt][2]=0; c[nt][3]=0; }
#pragma unroll
    for (int ks = 0; ks < 4; ks++) {
#pragma unroll
        for (int bt = 0; bt < 4; bt++) {
            uint32_t kf[4];
            const uint32_t kd = sK + (uint32_t)((bt * 16 + (lane & 15)) * FST
                                                + ks * 16 + (lane >> 4) * 8) * 2;
            ldm4(kf, kd);
            mma_f16(c[bt * 2 + 0], qf[ks], kf[0], kf[2]);
            mma_f16(c[bt * 2 + 1], qf[ks], kf[1], kf[3]);
        }
    }

    // add rel-pos bias: rows m(r0) = wid*16+(lane>>2), m(r1) = m+8
    const int mA = wid * 16 + (lane >> 2), mB = mA + 8;
    const int amA = mA >> 4, bmA = (mA >> 2) & 3, cmA = mA & 3;
    const int amB = mB >> 4, bmB = (mB >> 2) & 3, cmB = mB & 3;
#pragma unroll
    for (int nt = 0; nt < 8; nt++) {
#pragma unroll
        for (int e = 0; e < 2; e++) {
            const int col = nt * 8 + (lane & 3) * 2 + e;
            const int aj = col >> 4, bj = (col >> 2) & 3, cj = col & 3;
            c[nt][e]     += pos[(aj - amA + 3) * 49 + (bj - bmA + 3) * 7 + (cj - cmA + 3)];
            c[nt][2 + e] += pos[(aj - amB + 3) * 49 + (bj - bmB + 3) * 7 + (cj - cmB + 3)];
        }
    }

    // softmax over 64 cols
    float tm0 = -1e30f, tm1 = -1e30f;
#pragma unroll
    for (int nt = 0; nt < 8; nt++) {
        tm0 = fmaxf(tm0, fmaxf(c[nt][0], c[nt][1]));
        tm1 = fmaxf(tm1, fmaxf(c[nt][2], c[nt][3]));
    }
    tm0 = fmaxf(tm0, __shfl_xor_sync(0xffffffffu, tm0, 1));
    tm0 = fmaxf(tm0, __shfl_xor_sync(0xffffffffu, tm0, 2));
    tm1 = fmaxf(tm1, __shfl_xor_sync(0xffffffffu, tm1, 1));
    tm1 = fmaxf(tm1, __shfl_xor_sync(0xffffffffu, tm1, 2));
    float rs0 = 0.f, rs1 = 0.f;
    uint32_t pf[4][4];
#pragma unroll
    for (int nt = 0; nt < 8; nt++) {
        const float p0 = __expf(c[nt][0] - tm0), p1 = __expf(c[nt][1] - tm0);
        const float p2 = __expf(c[nt][2] - tm1), p3 = __expf(c[nt][3] - tm1);
        rs0 += p0 + p1; rs1 += p2 + p3;
        const int kchunk = nt >> 1, half_sel = nt & 1;
        const __half2 h01 = __floats2half2_rn(p0, p1);
        const __half2 h23 = __floats2half2_rn(p2, p3);
        pf[kchunk][half_sel * 2 + 0] = *(const uint32_t*)&h01;
        pf[kchunk][half_sel * 2 + 1] = *(const uint32_t*)&h23;
    }
    rs0 += __shfl_xor_sync(0xffffffffu, rs0, 1);
    rs0 += __shfl_xor_sync(0xffffffffu, rs0, 2);
    rs1 += __shfl_xor_sync(0xffffffffu, rs1, 1);
    rs1 += __shfl_xor_sync(0xffffffffu, rs1, 2);

    float oacc[8][4];
#pragma unroll
    for (int nt = 0; nt < 8; nt++) { oacc[nt][0]=0; oacc[nt][1]=0; oacc[nt][2]=0; oacc[nt][3]=0; }
#pragma unroll
    for (int ks = 0; ks < 4; ks++) {
#pragma unroll
        for (int vt = 0; vt < 4; vt++) {
            uint32_t vf[4];
            const int vr = ks * 16 + (lane & 7) + ((lane >> 3) & 1) * 8;
            const int vc = vt * 16 + (lane >> 4) * 8;
            ldm4t(vf, sV + (uint32_t)(vr * FST + vc) * 2);
            mma_f16(oacc[vt * 2 + 0], pf[ks], vf[0], vf[1]);
            mma_f16(oacc[vt * 2 + 1], pf[ks], vf[2], vf[3]);
        }
    }

    const float il0 = 1.f / rs0, il1 = 1.f / rs1;
    const int gA = base + (mA >> 4) * 576 + ((mA >> 2) & 3) * 24 + (mA & 3);
    const int gB = base + (mB >> 4) * 576 + ((mB >> 2) & 3) * 24 + (mB & 3);
#pragma unroll
    for (int nt = 0; nt < 8; nt++) {
        const int col = h * 64 + nt * 8 + (lane & 3) * 2;
        *(float2*)(g_O + (size_t)gA * CC + col) =
            make_float2(oacc[nt][0] * il0, oacc[nt][1] * il0);
        *(float2*)(g_O + (size_t)gB * CC + col) =
            make_float2(oacc[nt][2] * il1, oacc[nt][3] * il1);
    }
}

// ---- gather branch 1: X1[i*576+p, c1] = x_flat[i*294912 + c1*576 + p], i<48 ----
__global__ void gather_x1(const float* __restrict__ x) {
    __shared__ float tile[32][33];
    const int i  = blockIdx.z;
    const int p0 = blockIdx.x * 32;
    const int c0 = blockIdx.y * 32;
    const int tx = threadIdx.x, ty = threadIdx.y;   // 32 x 8
    const float* src = x + i * 294912;
#pragma unroll
    for (int l = 0; l < 4; l++)
        tile[ty + 8 * l][tx] = src[(c0 + ty + 8 * l) * 576 + p0 + tx];
    __syncthreads();
    float* dst = g_X + (i * 576 + p0) * CC + c0;
#pragma unroll
    for (int l = 0; l < 4; l++)
        dst[(ty + 8 * l) * CC + tx] = tile[tx][ty + 8 * l];
}

// ---- gather branch 3: X3[b*N+n, c] = x[b,c,n] ----------------------------------
__global__ void gather_xT(const float* __restrict__ x) {
    __shared__ float tile[32][33];
    const int b  = blockIdx.z;
    const int n0 = blockIdx.x * 32;
    const int c0 = blockIdx.y * 32;
    const int tx = threadIdx.x, ty = threadIdx.y;   // 32 x 8
    const float* src = x + b * (CC * NTOK);
#pragma unroll
    for (int i = 0; i < 4; i++)
        tile[ty + 8 * i][tx] = src[(c0 + ty + 8 * i) * NTOK + n0 + tx];
    __syncthreads();
    float* dst = g_X + (b * NTOK + n0) * CC + c0;
#pragma unroll
    for (int i = 0; i < 4; i++)
        dst[(ty + 8 * i) * CC + tx] = tile[tx][ty + 8 * i];
}

// ---- gather branch 2: X2[t, c] = x[(t/24)*12288 + c*24 + t%24] ------------------
__global__ void gather_x2(const float* __restrict__ x) {
    __shared__ float t2[24][257];
    const int i = blockIdx.x;
    const float* src = x + i * 12288;
    const int tid = threadIdx.x;              // 256
    for (int half = 0; half < 2; half++) {
        const int j0 = half * 256;
#pragma unroll
        for (int l = 0; l < 24; l++) {
            int e = l * 256 + tid;
            int j = e / 24, k = e - j * 24;
            t2[k][j] = src[j0 * 24 + e];
        }
        __syncthreads();
#pragma unroll
        for (int l = 0; l < 24; l++) {
            int e  = l * 256 + tid;
            int k  = e >> 8, jj = e & 255;
            g_X[(i * 24 + k) * CC + j0 + jj] = t2[k][jj];
        }
        __syncthreads();
    }
}

// ---------------- branch 2: tiny seq-24 attention --------------------------------
__global__ __launch_bounds__(256) void attn_seq24() {
    __shared__ float Qs[24 * 65], Ks[24 * 65], Vs[24 * 65], P[24 * 25];
    const int i = blockIdx.x, h = blockIdx.y;
    const int tid = threadIdx.x;
    const int rbase = i * 24 * CC + h * 64;

    for (int e = tid; e < 24 * 64; e += 256) {
        const int k = e >> 6, d = e & 63;
        Qs[k * 65 + d] = g_Q[rbase + k * CC + d];
        Ks[k * 65 + d] = g_K[rbase + k * CC + d];
        Vs[k * 65 + d] = g_V[rbase + k * CC + d];
    }
    __syncthreads();
    for (int sid = tid; sid < 576; sid += 256) {
        const int r = sid / 24, c = sid - r * 24;
        float s = 0.f;
#pragma unroll 16
        for (int d = 0; d < 64; d++) s += Qs[r * 65 + d] * Ks[c * 65 + d];
        P[r * 25 + c] = s * 0.125f;
    }
    __syncthreads();
    if (tid < 24) {
        float mx = -1e30f;
        for (int c = 0; c < 24; c++) mx = fmaxf(mx, P[tid * 25 + c]);
        float sum = 0.f;
        for (int c = 0; c < 24; c++) {
            const float p = __expf(P[tid * 25 + c] - mx);
            P[tid * 25 + c] = p; sum += p;
        }
        const float inv = 1.f / sum;
        for (int c = 0; c < 24; c++) P[tid * 25 + c] *= inv;
    }
    __syncthreads();
    for (int e = tid; e < 24 * 64; e += 256) {
        const int r = e >> 6, d = e & 63;
        float o = 0.f;
#pragma unroll
        for (int j = 0; j < 24; j++) o += P[r * 25 + j] * Vs[j * 65 + d];
        g_O[rbase + r * CC + d] = o;
    }
}

// ---------------- orchestration --------------------------------------------------
extern "C" void kernel_launch(void* const* d_in, const int* in_sizes, int n_in,
                              void* d_out, int out_size) {
    const float* x     = (const float*)d_in[0];
    const float* vq_w  = (const float*)d_in[1];
    const float* vq_b  = (const float*)d_in[2];
    const float* vk_w  = (const float*)d_in[3];
    const float* vk_b  = (const float*)d_in[4];
    const float* vv_w  = (const float*)d_in[5];
    const float* vv_b  = (const float*)d_in[6];
    const float* vo_w  = (const float*)d_in[7];
    const float* vo_b  = (const float*)d_in[8];
    const float* hq_w  = (const float*)d_in[9];
    const float* hq_b  = (const float*)d_in[10];
    const float* hk_w  = (const float*)d_in[11];
    const float* hk_b  = (const float*)d_in[12];
    const float* hv_w  = (const float*)d_in[13];
    const float* hv_b  = (const float*)d_in[14];
    const float* ho_w  = (const float*)d_in[15];
    const float* ho_b  = (const float*)d_in[16];
    const float* qkv_w = (const float*)d_in[17];
    const float* ow_w  = (const float*)d_in[18];
    const float* ow_b  = (const float*)d_in[19];
    const float* pos   = (const float*)d_in[20];
    float* out = (float*)d_out;
    (void)in_sizes; (void)n_in; (void)out_size;

    float *pX, *pQ, *pK, *pV, *pO;
    __nv_bfloat16 *pAh, *pAl, *pWh, *pWl;
    __half *pQh, *pKh, *pVh;
    cudaGetSymbolAddress((void**)&pX, g_X);
    cudaGetSymbolAddress((void**)&pQ, g_Q);
    cudaGetSymbolAddress((void**)&pK, g_K);
    cudaGetSymbolAddress((void**)&pV, g_V);
    cudaGetSymbolAddress((void**)&pO, g_O);
    cudaGetSymbolAddress((void**)&pAh, g_Ahi);
    cudaGetSymbolAddress((void**)&pAl, g_Alo);
    cudaGetSymbolAddress((void**)&pWh, g_Whi);
    cudaGetSymbolAddress((void**)&pWl, g_Wlo);
    cudaGetSymbolAddress((void**)&pQh, g_Qh);
    cudaGetSymbolAddress((void**)&pKh, g_Kh);
    cudaGetSymbolAddress((void**)&pVh, g_Vh);

    const int SMEMG = 2 * 4 * MATS * 2;   // 81920 B
    cudaFuncSetAttribute(mmagemm, cudaFuncAttributeMaxDynamicSharedMemorySize, SMEMG);

    const dim3 wg(16, 16), wb(32, 8);
    // weight slots: 0 vq, 1 vk, 2 vv, 3 vo, 4 hq, 5 hk, 6 hv, 7 ho,
    //               8 qkv.q, 9 qkv.k, 10 qkv.v, 11 win_out
    wconv<<<wg, wb>>>(vq_w, 512, 0, 0);
    wconv<<<wg, wb>>>(vk_w, 512, 0, 1);
    wconv<<<wg, wb>>>(vv_w, 512, 0, 2);
    wconv<<<wg, wb>>>(vo_w, 512, 0, 3);
    wconv<<<wg, wb>>>(hq_w, 512, 0, 4);
    wconv<<<wg, wb>>>(hk_w, 512, 0, 5);
    wconv<<<wg, wb>>>(hv_w, 512, 0, 6);
    wconv<<<wg, wb>>>(ho_w, 512, 0, 7);
    wconv<<<wg, wb>>>(qkv_w, 1536, 0,    8);
    wconv<<<wg, wb>>>(qkv_w, 1536, 512,  9);
    wconv<<<wg, wb>>>(qkv_w, 1536, 1024, 10);
    wconv<<<wg, wb>>>(ow_w, 512, 0, 11);

    const dim3 gg(4, 216);
    const size_t WS = (size_t)CC * CC;
#define TCG(slot, b, Cp, ac) \
    mmagemm<<<gg, 256, SMEMG>>>(pAh, pAl, pWh + (slot) * WS, pWl + (slot) * WS, \
                                b, Cp, ac, nullptr, 1.f)
#define TCGH(slot, b, Hp, sc) \
    mmagemm<<<gg, 256, SMEMG>>>(pAh, pAl, pWh + (slot) * WS, pWl + (slot) * WS, \
                                b, nullptr, 0, Hp, sc)

    // ---- branch 1 (seq-576 full attention, fp16 flash) ----
    gather_x1<<<dim3(18, 16, 48), dim3(32, 8)>>>(x);
    asplit<<<13824, 256>>>(pX);
    TCGH(0, vq_b, pQh, 0.125f);
    TCGH(1, vk_b, pKh, 1.f);
    TCGH(2, vv_b, pVh, 1.f);
    attn576_mma<<<dim3(9, 8, 48), 128>>>();
    asplit<<<13824, 256>>>(pO);
    TCG(3, vo_b, out, 0);          // first write

    // ---- branch 3 (window attention, fp16 mma) ----
    gather_xT<<<dim3(432, 16, 2), dim3(32, 8)>>>(x);
    asplit<<<13824, 256>>>(pX);
    TCGH(8, nullptr, pQh, 0.125f);
    TCGH(9, nullptr, pKh, 1.f);
    TCGH(10, nullptr, pVh, 1.f);
    attnwin_mma<<<dim3(216, 8, 2), 128>>>(pos);
    asplit<<<13824, 256>>>(pO);
    TCG(11, ow_b, out, 1);         // accumulate

    // ---- branch 2 (seq-24 full attention) ----
    gather_x2<<<1152, 256>>>(x);
    asplit<<<13824, 256>>>(pX);
    TCG(4, hq_b, pQ, 0);
    TCG(5, hk_b, pK, 0);
    TCG(6, hv_b, pV, 0);
    attn_seq24<<<dim3(1152, 8), 256>>>();
    asplit<<<13824, 256>>>(pO);
    TCG(7, ho_b, out, 1);          // accumulate
#undef TCG
#undef TCGH
}

// round 8
// speedup vs baseline: 2.7147x; 1.0430x over previous
#include <cuda_runtime.h>
#include <cuda_bf16.h>
#include <cuda_fp16.h>
#include <cstdint>

#define CC 512
#define NTOK 13824            // 24*24*24
#define TT 27648              // B * NTOK

// ---------------- scratch (device globals; no allocation allowed) ----------------
__device__ __nv_bfloat16 g_Ahi[TT * CC];
__device__ __nv_bfloat16 g_Alo[TT * CC];
__device__ __nv_bfloat16 g_Whi[12 * CC * CC];   // 12 slots of Wt[n][k]
__device__ __nv_bfloat16 g_Wlo[12 * CC * CC];
__device__ __half g_Qh[TT * CC];
__device__ __half g_Kh[TT * CC];
__device__ __half g_Vh[TT * CC];

__device__ __forceinline__ uint32_t smem_to_u32(const void* p) {
    uint32_t a;
    asm("{ .reg .u64 t; cvta.to.shared.u64 t, %1; cvt.u32.u64 %0, t; }" : "=r"(a) : "l"(p));
    return a;
}
__device__ __forceinline__ void ldm4(uint32_t* r, uint32_t addr) {
    asm volatile("ldmatrix.sync.aligned.m8n8.x4.shared.b16 {%0,%1,%2,%3}, [%4];"
                 : "=r"(r[0]), "=r"(r[1]), "=r"(r[2]), "=r"(r[3]) : "r"(addr));
}
__device__ __forceinline__ void ldm4t(uint32_t* r, uint32_t addr) {
    asm volatile("ldmatrix.sync.aligned.m8n8.x4.trans.shared.b16 {%0,%1,%2,%3}, [%4];"
                 : "=r"(r[0]), "=r"(r[1]), "=r"(r[2]), "=r"(r[3]) : "r"(addr));
}
__device__ __forceinline__ void mma_bf16(float* c, const uint32_t* a,
                                         uint32_t b0, uint32_t b1) {
    asm volatile("mma.sync.aligned.m16n8k16.row.col.f32.bf16.bf16.f32 "
                 "{%0,%1,%2,%3}, {%4,%5,%6,%7}, {%8,%9}, {%0,%1,%2,%3};"
                 : "+f"(c[0]), "+f"(c[1]), "+f"(c[2]), "+f"(c[3])
                 : "r"(a[0]), "r"(a[1]), "r"(a[2]), "r"(a[3]), "r"(b0), "r"(b1));
}
__device__ __forceinline__ void mma_f16(float* c, const uint32_t* a,
                                        uint32_t b0, uint32_t b1) {
    asm volatile("mma.sync.aligned.m16n8k16.row.col.f32.f16.f16.f32 "
                 "{%0,%1,%2,%3}, {%4,%5,%6,%7}, {%8,%9}, {%0,%1,%2,%3};"
                 : "+f"(c[0]), "+f"(c[1]), "+f"(c[2]), "+f"(c[3])
                 : "r"(a[0]), "r"(a[1]), "r"(a[2]), "r"(a[3]), "r"(b0), "r"(b1));
}
__device__ __forceinline__ void cp16(uint32_t d, const void* s) {
    asm volatile("cp.async.cg.shared.global [%0], [%1], 16;" :: "r"(d), "l"(s));
}
#define CP_COMMIT() asm volatile("cp.async.commit_group;" ::: "memory")
#define CP_WAIT(n)  asm volatile("cp.async.wait_group %0;" :: "n"(n) : "memory")

// split store: v -> hi bf16 + lo bf16
__device__ __forceinline__ void split_store(__nv_bfloat16* hi, __nv_bfloat16* lo, float v) {
    const __nv_bfloat16 h = __float2bfloat16(v);
    *hi = h;
    *lo = __float2bfloat16(v - __bfloat162float(h));
}
__device__ __forceinline__ void split_store2(size_t idx, float v0, float v1) {
    const __nv_bfloat16 h0 = __float2bfloat16(v0), h1 = __float2bfloat16(v1);
    const __nv_bfloat16 l0 = __float2bfloat16(v0 - __bfloat162float(h0));
    const __nv_bfloat16 l1 = __float2bfloat16(v1 - __bfloat162float(h1));
    *(__nv_bfloat162*)(g_Ahi + idx) = __nv_bfloat162(h0, h1);
    *(__nv_bfloat162*)(g_Alo + idx) = __nv_bfloat162(l0, l1);
}

// ---------------- weight conversion: all 12 slots in one launch ------------------
struct WArgs {
    const float* W[12];
    int ldb[12];
    int bcol[12];
};
__global__ void wconv_all(WArgs a) {
    __shared__ float tile[32][33];
    const int slot = blockIdx.z;
    const int k0 = blockIdx.x * 32, n0 = blockIdx.y * 32;
    const int tx = threadIdx.x, ty = threadIdx.y;   // 32 x 8
    const float* W = a.W[slot];
    const int ldb = a.ldb[slot], bcol = a.bcol[slot];
#pragma unroll
    for (int l = 0; l < 4; l++)
        tile[ty + 8 * l][tx] = W[(k0 + ty + 8 * l) * ldb + bcol + n0 + tx];
    __syncthreads();
    const size_t base = (size_t)slot * CC * CC;
#pragma unroll
    for (int l = 0; l < 4; l++) {
        const float v = tile[tx][ty + 8 * l];
        const size_t idx = base + (size_t)(n0 + ty + 8 * l) * CC + k0 + tx;
        split_store(g_Whi + idx, g_Wlo + idx, v);
    }
}

// ------------- mma.sync GEMM: cp.async 2-stage, 2 CTAs/SM ------------------------
#define GST 40                       // smem row stride (bf16 elems)
#define MATS (128 * GST)             // one matrix (elems)

__global__ __launch_bounds__(256, 2) void mmagemm(
    const __nv_bfloat16* __restrict__ Ahi, const __nv_bfloat16* __restrict__ Alo,
    const __nv_bfloat16* __restrict__ Bhi, const __nv_bfloat16* __restrict__ Blo,
    const float* __restrict__ bias, float* __restrict__ Cmat, int acc,
    __half* __restrict__ Chalf, float hscale)
{
    extern __shared__ __align__(16) __nv_bfloat16 smb[];
    const int tid = threadIdx.x, lane = tid & 31, wid = tid >> 5;
    const int m0 = blockIdx.y * 128, n0 = blockIdx.x * 128;
    const int wm = (wid >> 2) * 64, wn = (wid & 3) * 32;

    float c[4][4][4];
#pragma unroll
    for (int i = 0; i < 4; i++)
#pragma unroll
        for (int j = 0; j < 4; j++) { c[i][j][0]=0; c[i][j][1]=0; c[i][j][2]=0; c[i][j][3]=0; }

    const __nv_bfloat16* pAh = Ahi + (size_t)m0 * CC;
    const __nv_bfloat16* pAl = Alo + (size_t)m0 * CC;
    const __nv_bfloat16* pBh = Bhi + (size_t)n0 * CC;
    const __nv_bfloat16* pBl = Blo + (size_t)n0 * CC;

    const int g0 = (tid >> 2) * CC + (tid & 3) * 8;
    const int g1 = g0 + 64 * CC;
    const uint32_t s0 = (uint32_t)((tid >> 2) * GST + (tid & 3) * 8);
    const uint32_t s1 = s0 + 64 * GST;
    const uint32_t smb32 = smem_to_u32(smb);

#define ISSUE(stage, kb) do {                                               \
        const uint32_t sbs = smb32 + (uint32_t)(stage) * (4 * MATS * 2);    \
        cp16(sbs + (0 * MATS + s0) * 2, pAh + g0 + (kb));                   \
        cp16(sbs + (0 * MATS + s1) * 2, pAh + g1 + (kb));                   \
        cp16(sbs + (1 * MATS + s0) * 2, pAl + g0 + (kb));                   \
        cp16(sbs + (1 * MATS + s1) * 2, pAl + g1 + (kb));                   \
        cp16(sbs + (2 * MATS + s0) * 2, pBh + g0 + (kb));                   \
        cp16(sbs + (2 * MATS + s1) * 2, pBh + g1 + (kb));                   \
        cp16(sbs + (3 * MATS + s0) * 2, pBl + g0 + (kb));                   \
        cp16(sbs + (3 * MATS + s1) * 2, pBl + g1 + (kb));                   \
        CP_COMMIT();                                                        \
    } while (0)

    ISSUE(0, 0);
    for (int kc = 0; kc < 16; kc++) {
        if (kc + 1 < 16) { ISSUE((kc + 1) & 1, (kc + 1) * 32); CP_WAIT(1); }
        else             { CP_WAIT(0); }
        __syncthreads();
        const uint32_t sb = smb32 + (uint32_t)(kc & 1) * (4 * MATS * 2);
#pragma unroll
        for (int ks = 0; ks < 2; ks++) {
            uint32_t bh[2][4], bl[2][4];
#pragma unroll
            for (int bt = 0; bt < 2; bt++) {
                const int r = wn + bt * 16 + (lane & 15);
                const uint32_t bd = sb + (uint32_t)(2 * MATS + r * GST + ks * 16 + (lane >> 4) * 8) * 2;
                ldm4(bh[bt], bd);
                ldm4(bl[bt], bd + MATS * 2);
            }
#pragma unroll
            for (int mt = 0; mt < 4; mt++) {
                uint32_t ah[4], al[4];
                const int r = wm + mt * 16 + (lane & 15);
                const uint32_t ad = sb + (uint32_t)(r * GST + ks * 16 + (lane >> 4) * 8) * 2;
                ldm4(ah, ad);
                ldm4(al, ad + MATS * 2);
#pragma unroll
                for (int nt = 0; nt < 4; nt++) {
                    const int bt = nt >> 1, sub = nt & 1;
                    mma_bf16(c[mt][nt], ah, bh[bt][sub], bh[bt][sub + 2]);
                    mma_bf16(c[mt][nt], ah, bl[bt][sub], bl[bt][sub + 2]);
                    mma_bf16(c[mt][nt], al, bh[bt][sub], bh[bt][sub + 2]);
                }
            }
        }
        __syncthreads();
    }
#undef ISSUE

#pragma unroll
    for (int mt = 0; mt < 4; mt++) {
        const int r0 = m0 + wm + mt * 16 + (lane >> 2);
#pragma unroll
        for (int nt = 0; nt < 4; nt++) {
            const int col = n0 + wn + nt * 8 + (lane & 3) * 2;
            float2 v0 = make_float2(c[mt][nt][0], c[mt][nt][1]);
            float2 v1 = make_float2(c[mt][nt][2], c[mt][nt][3]);
            if (bias) {
                const float b0 = bias[col], b1 = bias[col + 1];
                v0.x += b0; v0.y += b1; v1.x += b0; v1.y += b1;
            }
            if (Chalf) {
                *(__half2*)(Chalf + (size_t)r0 * CC + col) =
                    __floats2half2_rn(v0.x * hscale, v0.y * hscale);
                *(__half2*)(Chalf + (size_t)(r0 + 8) * CC + col) =
                    __floats2half2_rn(v1.x * hscale, v1.y * hscale);
            } else {
                float* p0 = Cmat + (size_t)r0 * CC + col;
                float* p1 = Cmat + (size_t)(r0 + 8) * CC + col;
                if (acc) {
                    const float2 o0 = *(const float2*)p0, o1 = *(const float2*)p1;
                    v0.x += o0.x; v0.y += o0.y; v1.x += o1.x; v1.y += o1.y;
                }
                *(float2*)p0 = v0;
                *(float2*)p1 = v1;
            }
        }
    }
}

// ------------- branch 1 attention: flash-style fp16 mma, seq 576 -----------------
#define FST 72    // smem half-stride

__global__ __launch_bounds__(128) void attn576_mma() {
    __shared__ __half Qs[64 * FST], Ks[64 * FST], Vs[64 * FST];
    const int qt = blockIdx.x, h = blockIdx.y, bd = blockIdx.z;
    const int tid = threadIdx.x, lane = tid & 31, wid = tid >> 5;
    const int rq = bd * 576 + qt * 64, rb = bd * 576;
    const uint32_t sQ = smem_to_u32(Qs), sK = smem_to_u32(Ks), sV = smem_to_u32(Vs);

#pragma unroll
    for (int i = 0; i < 4; i++) {
        const int e = tid + i * 128;
        const int r = e >> 3, cu = e & 7;
        *(uint4*)(Qs + r * FST + cu * 8) =
            *(const uint4*)(g_Qh + (size_t)(rq + r) * CC + h * 64 + cu * 8);
    }
    __syncthreads();

    uint32_t qf[4][4];
#pragma unroll
    for (int ks = 0; ks < 4; ks++) {
        const uint32_t ad = sQ + (uint32_t)((wid * 16 + (lane & 15)) * FST
                                            + ks * 16 + (lane >> 4) * 8) * 2;
        ldm4(qf[ks], ad);
    }

    float oacc[8][4];
#pragma unroll
    for (int nt = 0; nt < 8; nt++) { oacc[nt][0]=0; oacc[nt][1]=0; oacc[nt][2]=0; oacc[nt][3]=0; }
    float mrow[2] = {-1e30f, -1e30f};
    float lrow[2] = {0.f, 0.f};

    for (int kt = 0; kt < 9; kt++) {
        __syncthreads();
#pragma unroll
        for (int i = 0; i < 4; i++) {
            const int e = tid + i * 128;
            const int r = e >> 3, cu = e & 7;
            const size_t grow = (size_t)(rb + kt * 64 + r) * CC + h * 64 + cu * 8;
            *(uint4*)(Ks + r * FST + cu * 8) = *(const uint4*)(g_Kh + grow);
            *(uint4*)(Vs + r * FST + cu * 8) = *(const uint4*)(g_Vh + grow);
        }
        __syncthreads();

        float c[8][4];
#pragma unroll
        for (int nt = 0; nt < 8; nt++) { c[nt][0]=0; c[nt][1]=0; c[nt][2]=0; c[nt][3]=0; }
#pragma unroll
        for (int ks = 0; ks < 4; ks++) {
#pragma unroll
            for (int bt = 0; bt < 4; bt++) {
                uint32_t kf[4];
                const uint32_t kd = sK + (uint32_t)((bt * 16 + (lane & 15)) * FST
                                                    + ks * 16 + (lane >> 4) * 8) * 2;
                ldm4(kf, kd);
                mma_f16(c[bt * 2 + 0], qf[ks], kf[0], kf[2]);
                mma_f16(c[bt * 2 + 1], qf[ks], kf[1], kf[3]);
            }
        }

        float tm0 = -1e30f, tm1 = -1e30f;
#pragma unroll
        for (int nt = 0; nt < 8; nt++) {
            tm0 = fmaxf(tm0, fmaxf(c[nt][0], c[nt][1]));
            tm1 = fmaxf(tm1, fmaxf(c[nt][2], c[nt][3]));
        }
        tm0 = fmaxf(tm0, __shfl_xor_sync(0xffffffffu, tm0, 1));
        tm0 = fmaxf(tm0, __shfl_xor_sync(0xffffffffu, tm0, 2));
        tm1 = fmaxf(tm1, __shfl_xor_sync(0xffffffffu, tm1, 1));
        tm1 = fmaxf(tm1, __shfl_xor_sync(0xffffffffu, tm1, 2));
        const float mn0 = fmaxf(mrow[0], tm0), mn1 = fmaxf(mrow[1], tm1);
        const float al0 = __expf(mrow[0] - mn0), al1 = __expf(mrow[1] - mn1);
        mrow[0] = mn0; mrow[1] = mn1;
        float rs0 = 0.f, rs1 = 0.f;
        uint32_t pf[4][4];
#pragma unroll
        for (int nt = 0; nt < 8; nt++) {
            const float p0 = __expf(c[nt][0] - mn0), p1 = __expf(c[nt][1] - mn0);
            const float p2 = __expf(c[nt][2] - mn1), p3 = __expf(c[nt][3] - mn1);
            rs0 += p0 + p1; rs1 += p2 + p3;
            const int kchunk = nt >> 1, half_sel = nt & 1;
            const __half2 h01 = __floats2half2_rn(p0, p1);
            const __half2 h23 = __floats2half2_rn(p2, p3);
            pf[kchunk][half_sel * 2 + 0] = *(const uint32_t*)&h01;
            pf[kchunk][half_sel * 2 + 1] = *(const uint32_t*)&h23;
        }
        rs0 += __shfl_xor_sync(0xffffffffu, rs0, 1);
        rs0 += __shfl_xor_sync(0xffffffffu, rs0, 2);
        rs1 += __shfl_xor_sync(0xffffffffu, rs1, 1);
        rs1 += __shfl_xor_sync(0xffffffffu, rs1, 2);
        lrow[0] = lrow[0] * al0 + rs0;
        lrow[1] = lrow[1] * al1 + rs1;
#pragma unroll
        for (int nt = 0; nt < 8; nt++) {
            oacc[nt][0] *= al0; oacc[nt][1] *= al0;
            oacc[nt][2] *= al1; oacc[nt][3] *= al1;
        }

#pragma unroll
        for (int ks = 0; ks < 4; ks++) {
#pragma unroll
            for (int vt = 0; vt < 4; vt++) {
                uint32_t vf[4];
                const int vr = ks * 16 + (lane & 7) + ((lane >> 3) & 1) * 8;
                const int vc = vt * 16 + (lane >> 4) * 8;
                ldm4t(vf, sV + (uint32_t)(vr * FST + vc) * 2);
                mma_f16(oacc[vt * 2 + 0], pf[ks], vf[0], vf[1]);
                mma_f16(oacc[vt * 2 + 1], pf[ks], vf[2], vf[3]);
            }
        }
    }

    const float il0 = 1.f / lrow[0], il1 = 1.f / lrow[1];
    const int r0 = rq + wid * 16 + (lane >> 2);
#pragma unroll
    for (int nt = 0; nt < 8; nt++) {
        const int col = h * 64 + nt * 8 + (lane & 3) * 2;
        split_store2((size_t)r0 * CC + col, oacc[nt][0] * il0, oacc[nt][1] * il0);
        split_store2((size_t)(r0 + 8) * CC + col, oacc[nt][2] * il1, oacc[nt][3] * il1);
    }
}

// ------------- branch 3: window attention, fp16 mma ------------------------------
__global__ __launch_bounds__(128) void attnwin_mma(const float* __restrict__ pos_table) {
    __shared__ __half Qs[64 * FST], Ks[64 * FST], Vs[64 * FST];
    __shared__ float pos[343];
    const int win = blockIdx.x, h = blockIdx.y, b = blockIdx.z;
    const int wd = win / 36, ww = (win / 6) % 6, wh = win % 6;
    const int tid = threadIdx.x, lane = tid & 31, wid = tid >> 5;
    const int base = b * NTOK + wd * 4 * 576 + ww * 4 * 24 + wh * 4;
    const uint32_t sQ = smem_to_u32(Qs), sK = smem_to_u32(Ks), sV = smem_to_u32(Vs);

    for (int e = tid; e < 343; e += 128) pos[e] = pos_table[e];
#pragma unroll
    for (int i = 0; i < 4; i++) {
        const int e = tid + i * 128;
        const int r = e >> 3, cu = e & 7;
        const int grow = base + (r >> 4) * 576 + ((r >> 2) & 3) * 24 + (r & 3);
        const size_t go = (size_t)grow * CC + h * 64 + cu * 8;
        *(uint4*)(Qs + r * FST + cu * 8) = *(const uint4*)(g_Qh + go);
        *(uint4*)(Ks + r * FST + cu * 8) = *(const uint4*)(g_Kh + go);
        *(uint4*)(Vs + r * FST + cu * 8) = *(const uint4*)(g_Vh + go);
    }
    __syncthreads();

    uint32_t qf[4][4];
#pragma unroll
    for (int ks = 0; ks < 4; ks++) {
        const uint32_t ad = sQ + (uint32_t)((wid * 16 + (lane & 15)) * FST
                                            + ks * 16 + (lane >> 4) * 8) * 2;
        ldm4(qf[ks], ad);
    }

    float c[8][4];
#pragma unroll
    for (int nt = 0; nt < 8; nt++) { c[nt][0]=0; c[nt][1]=0; c[nt][2]=0; c[nt][3]=0; }
#pragma unroll
    for (int ks = 0; ks < 4; ks++) {
#pragma unroll
        for (int bt = 0; bt < 4; bt++) {
            uint32_t kf[4];
            const uint32_t kd = sK + (uint32_t)((bt * 16 + (lane & 15)) * FST
                                                + ks * 16 + (lane >> 4) * 8) * 2;
            ldm4(kf, kd);
            mma_f16(c[bt * 2 + 0], qf[ks], kf[0], kf[2]);
            mma_f16(c[bt * 2 + 1], qf[ks], kf[1], kf[3]);
        }
    }

    const int mA = wid * 16 + (lane >> 2), mB = mA + 8;
    const int amA = mA >> 4, bmA = (mA >> 2) & 3, cmA = mA & 3;
    const int amB = mB >> 4, bmB = (mB >> 2) & 3, cmB = mB & 3;
#pragma unroll
    for (int nt = 0; nt < 8; nt++) {
#pragma unroll
        for (int e = 0; e < 2; e++) {
            const int col = nt * 8 + (lane & 3) * 2 + e;
            const int aj = col >> 4, bj = (col >> 2) & 3, cj = col & 3;
            c[nt][e]     += pos[(aj - amA + 3) * 49 + (bj - bmA + 3) * 7 + (cj - cmA + 3)];
            c[nt][2 + e] += pos[(aj - amB + 3) * 49 + (bj - bmB + 3) * 7 + (cj - cmB + 3)];
        }
    }

    float tm0 = -1e30f, tm1 = -1e30f;
#pragma unroll
    for (int nt = 0; nt < 8; nt++) {
        tm0 = fmaxf(tm0, fmaxf(c[nt][0], c[nt][1]));
        tm1 = fmaxf(tm1, fmaxf(c[nt][2], c[nt][3]));
    }
    tm0 = fmaxf(tm0, __shfl_xor_sync(0xffffffffu, tm0, 1));
    tm0 = fmaxf(tm0, __shfl_xor_sync(0xffffffffu, tm0, 2));
    tm1 = fmaxf(tm1, __shfl_xor_sync(0xffffffffu, tm1, 1));
    tm1 = fmaxf(tm1, __shfl_xor_sync(0xffffffffu, tm1, 2));
    float rs0 = 0.f, rs1 = 0.f;
    uint32_t pf[4][4];
#pragma unroll
    for (int nt = 0; nt < 8; nt++) {
        const float p0 = __expf(c[nt][0] - tm0), p1 = __expf(c[nt][1] - tm0);
        const float p2 = __expf(c[nt][2] - tm1), p3 = __expf(c[nt][3] - tm1);
        rs0 += p0 + p1; rs1 += p2 + p3;
        const int kchunk = nt >> 1, half_sel = nt & 1;
        const __half2 h01 = __floats2half2_rn(p0, p1);
        const __half2 h23 = __floats2half2_rn(p2, p3);
        pf[kchunk][half_sel * 2 + 0] = *(const uint32_t*)&h01;
        pf[kchunk][half_sel * 2 + 1] = *(const uint32_t*)&h23;
    }
    rs0 += __shfl_xor_sync(0xffffffffu, rs0, 1);
    rs0 += __shfl_xor_sync(0xffffffffu, rs0, 2);
    rs1 += __shfl_xor_sync(0xffffffffu, rs1, 1);
    rs1 += __shfl_xor_sync(0xffffffffu, rs1, 2);

    float oacc[8][4];
#pragma unroll
    for (int nt = 0; nt < 8; nt++) { oacc[nt][0]=0; oacc[nt][1]=0; oacc[nt][2]=0; oacc[nt][3]=0; }
#pragma unroll
    for (int ks = 0; ks < 4; ks++) {
#pragma unroll
        for (int vt = 0; vt < 4; vt++) {
            uint32_t vf[4];
            const int vr = ks * 16 + (lane & 7) + ((lane >> 3) & 1) * 8;
            const int vc = vt * 16 + (lane >> 4) * 8;
            ldm4t(vf, sV + (uint32_t)(vr * FST + vc) * 2);
            mma_f16(oacc[vt * 2 + 0], pf[ks], vf[0], vf[1]);
            mma_f16(oacc[vt * 2 + 1], pf[ks], vf[2], vf[3]);
        }
    }

    const float il0 = 1.f / rs0, il1 = 1.f / rs1;
    const int gA = base + (mA >> 4) * 576 + ((mA >> 2) & 3) * 24 + (mA & 3);
    const int gB = base + (mB >> 4) * 576 + ((mB >> 2) & 3) * 24 + (mB & 3);
#pragma unroll
    for (int nt = 0; nt < 8; nt++) {
        const int col = h * 64 + nt * 8 + (lane & 3) * 2;
        split_store2((size_t)gA * CC + col, oacc[nt][0] * il0, oacc[nt][1] * il0);
        split_store2((size_t)gB * CC + col, oacc[nt][2] * il1, oacc[nt][3] * il1);
    }
}

// ---- gathers: write split bf16 (g_Ahi/g_Alo) directly ---------------------------
__global__ void gather_x1(const float* __restrict__ x) {
    __shared__ float tile[32][33];
    const int i  = blockIdx.z;
    const int p0 = blockIdx.x * 32;
    const int c0 = blockIdx.y * 32;
    const int tx = threadIdx.x, ty = threadIdx.y;   // 32 x 8
    const float* src = x + i * 294912;
#pragma unroll
    for (int l = 0; l < 4; l++)
        tile[ty + 8 * l][tx] = src[(c0 + ty + 8 * l) * 576 + p0 + tx];
    __syncthreads();
    const size_t dst = (size_t)(i * 576 + p0) * CC + c0;
#pragma unroll
    for (int l = 0; l < 4; l++) {
        const size_t idx = dst + (size_t)(ty + 8 * l) * CC + tx;
        split_store(g_Ahi + idx, g_Alo + idx, tile[tx][ty + 8 * l]);
    }
}

__global__ void gather_xT(const float* __restrict__ x) {
    __shared__ float tile[32][33];
    const int b  = blockIdx.z;
    const int n0 = blockIdx.x * 32;
    const int c0 = blockIdx.y * 32;
    const int tx = threadIdx.x, ty = threadIdx.y;   // 32 x 8
    const float* src = x + b * (CC * NTOK);
#pragma unroll
    for (int i = 0; i < 4; i++)
        tile[ty + 8 * i][tx] = src[(c0 + ty + 8 * i) * NTOK + n0 + tx];
    __syncthreads();
    const size_t dst = (size_t)(b * NTOK + n0) * CC + c0;
#pragma unroll
    for (int i = 0; i < 4; i++) {
        const size_t idx = dst + (size_t)(ty + 8 * i) * CC + tx;
        split_store(g_Ahi + idx, g_Alo + idx, tile[tx][ty + 8 * i]);
    }
}

__global__ void gather_x2(const float* __restrict__ x) {
    __shared__ float t2[24][257];
    const int i = blockIdx.x;
    const float* src = x + i * 12288;
    const int tid = threadIdx.x;              // 256
    for (int half = 0; half < 2; half++) {
        const int j0 = half * 256;
#pragma unroll
        for (int l = 0; l < 24; l++) {
            int e = l * 256 + tid;
            int j = e / 24, k = e - j * 24;
            t2[k][j] = src[j0 * 24 + e];
        }
        __syncthreads();
#pragma unroll
        for (int l = 0; l < 24; l++) {
            int e  = l * 256 + tid;
            int k  = e >> 8, jj = e & 255;
            const size_t idx = (size_t)(i * 24 + k) * CC + j0 + jj;
            split_store(g_Ahi + idx, g_Alo + idx, t2[k][jj]);
        }
        __syncthreads();
    }
}

// ---------------- branch 2: tiny seq-24 attention (fp16 in, split out) -----------
__global__ __launch_bounds__(256) void attn_seq24() {
    __shared__ float Qs[24 * 65], Ks[24 * 65], Vs[24 * 65], P[24 * 25];
    const int i = blockIdx.x, h = blockIdx.y;
    const int tid = threadIdx.x;
    const size_t rbase = (size_t)i * 24 * CC + h * 64;

    for (int e = tid; e < 24 * 64; e += 256) {
        const int k = e >> 6, d = e & 63;
        Qs[k * 65 + d] = __half2float(g_Qh[rbase + k * CC + d]);
        Ks[k * 65 + d] = __half2float(g_Kh[rbase + k * CC + d]);
        Vs[k * 65 + d] = __half2float(g_Vh[rbase + k * CC + d]);
    }
    __syncthreads();
    for (int sid = tid; sid < 576; sid += 256) {
        const int r = sid / 24, c = sid - r * 24;
        float s = 0.f;
#pragma unroll 16
        for (int d = 0; d < 64; d++) s += Qs[r * 65 + d] * Ks[c * 65 + d];
        P[r * 25 + c] = s;              // Q pre-scaled by 0.125 in GEMM epilogue
    }
    __syncthreads();
    if (tid < 24) {
        float mx = -1e30f;
        for (int c = 0; c < 24; c++) mx = fmaxf(mx, P[tid * 25 + c]);
        float sum = 0.f;
        for (int c = 0; c < 24; c++) {
            const float p = __expf(P[tid * 25 + c] - mx);
            P[tid * 25 + c] = p; sum += p;
        }
        const float inv = 1.f / sum;
        for (int c = 0; c < 24; c++) P[tid * 25 + c] *= inv;
    }
    __syncthreads();
    for (int e = tid; e < 24 * 32; e += 256) {
        const int r = e >> 5, d2 = (e & 31) * 2;
        float o0 = 0.f, o1 = 0.f;
#pragma unroll
        for (int j = 0; j < 24; j++) {
            const float p = P[r * 25 + j];
            o0 += p * Vs[j * 65 + d2];
            o1 += p * Vs[j * 65 + d2 + 1];
        }
        split_store2(rbase + (size_t)r * CC + d2, o0, o1);
    }
}

// ---------------- orchestration --------------------------------------------------
extern "C" void kernel_launch(void* const* d_in, const int* in_sizes, int n_in,
                              void* d_out, int out_size) {
    const float* x     = (const float*)d_in[0];
    const float* vq_w  = (const float*)d_in[1];
    const float* vq_b  = (const float*)d_in[2];
    const float* vk_w  = (const float*)d_in[3];
    const float* vk_b  = (const float*)d_in[4];
    const float* vv_w  = (const float*)d_in[5];
    const float* vv_b  = (const float*)d_in[6];
    const float* vo_w  = (const float*)d_in[7];
    const float* vo_b  = (const float*)d_in[8];
    const float* hq_w  = (const float*)d_in[9];
    const float* hq_b  = (const float*)d_in[10];
    const float* hk_w  = (const float*)d_in[11];
    const float* hk_b  = (const float*)d_in[12];
    const float* hv_w  = (const float*)d_in[13];
    const float* hv_b  = (const float*)d_in[14];
    const float* ho_w  = (const float*)d_in[15];
    const float* ho_b  = (const float*)d_in[16];
    const float* qkv_w = (const float*)d_in[17];
    const float* ow_w  = (const float*)d_in[18];
    const float* ow_b  = (const float*)d_in[19];
    const float* pos   = (const float*)d_in[20];
    float* out = (float*)d_out;
    (void)in_sizes; (void)n_in; (void)out_size;

    __nv_bfloat16 *pAh, *pAl, *pWh, *pWl;
    __half *pQh, *pKh, *pVh;
    cudaGetSymbolAddress((void**)&pAh, g_Ahi);
    cudaGetSymbolAddress((void**)&pAl, g_Alo);
    cudaGetSymbolAddress((void**)&pWh, g_Whi);
    cudaGetSymbolAddress((void**)&pWl, g_Wlo);
    cudaGetSymbolAddress((void**)&pQh, g_Qh);
    cudaGetSymbolAddress((void**)&pKh, g_Kh);
    cudaGetSymbolAddress((void**)&pVh, g_Vh);

    const int SMEMG = 2 * 4 * MATS * 2;   // 81920 B
    cudaFuncSetAttribute(mmagemm, cudaFuncAttributeMaxDynamicSharedMemorySize, SMEMG);

    // weight slots: 0 vq, 1 vk, 2 vv, 3 vo, 4 hq, 5 hk, 6 hv, 7 ho,
    //               8 qkv.q, 9 qkv.k, 10 qkv.v, 11 win_out
    WArgs wa;
    const float* wp[12] = {vq_w, vk_w, vv_w, vo_w, hq_w, hk_w, hv_w, ho_w,
                           qkv_w, qkv_w, qkv_w, ow_w};
    const int wl[12] = {512,512,512,512,512,512,512,512,1536,1536,1536,512};
    const int wc[12] = {0,0,0,0,0,0,0,0,0,512,1024,0};
    for (int s = 0; s < 12; s++) { wa.W[s] = wp[s]; wa.ldb[s] = wl[s]; wa.bcol[s] = wc[s]; }
    wconv_all<<<dim3(16, 16, 12), dim3(32, 8)>>>(wa);

    const dim3 gg(4, 216);
    const size_t WS = (size_t)CC * CC;
#define TCG(slot, b, Cp, ac) \
    mmagemm<<<gg, 256, SMEMG>>>(pAh, pAl, pWh + (slot) * WS, pWl + (slot) * WS, \
                                b, Cp, ac, nullptr, 1.f)
#define TCGH(slot, b, Hp, sc) \
    mmagemm<<<gg, 256, SMEMG>>>(pAh, pAl, pWh + (slot) * WS, pWl + (slot) * WS, \
                                b, nullptr, 0, Hp, sc)

    // ---- branch 1 (seq-576 full attention, fp16 flash) ----
    gather_x1<<<dim3(18, 16, 48), dim3(32, 8)>>>(x);
    TCGH(0, vq_b, pQh, 0.125f);
    TCGH(1, vk_b, pKh, 1.f);
    TCGH(2, vv_b, pVh, 1.f);
    attn576_mma<<<dim3(9, 8, 48), 128>>>();     // writes split O into g_Ahi/g_Alo
    TCG(3, vo_b, out, 0);                        // first write of out

    // ---- branch 3 (window attention, fp16 mma) ----
    gather_xT<<<dim3(432, 16, 2), dim3(32, 8)>>>(x);
    TCGH(8, nullptr, pQh, 0.125f);
    TCGH(9, nullptr, pKh, 1.f);
    TCGH(10, nullptr, pVh, 1.f);
    attnwin_mma<<<dim3(216, 8, 2), 128>>>(pos);
    TCG(11, ow_b, out, 1);                       // accumulate

    // ---- branch 2 (seq-24 full attention) ----
    gather_x2<<<1152, 256>>>(x);
    TCGH(4, hq_b, pQh, 0.125f);
    TCGH(5, hk_b, pKh, 1.f);
    TCGH(6, hv_b, pVh, 1.f);
    attn_seq24<<<dim3(1152, 8), 256>>>();
    TCG(7, ho_b, out, 1);                        // accumulate
#undef TCG
#undef TCGH
}

// round 9
// speedup vs baseline: 3.2130x; 1.1836x over previous
#include <cuda_runtime.h>
#include <cuda_bf16.h>
#include <cuda_fp16.h>
#include <cstdint>

#define CC 512
#define NTOK 13824            // 24*24*24
#define TT 27648              // B * NTOK

// ---------------- scratch (device globals; no allocation allowed) ----------------
__device__ __nv_bfloat16 g_Ahi[TT * CC];        // split-bf16 A (attention outputs)
__device__ __nv_bfloat16 g_Alo[TT * CC];
__device__ __half        g_Af [TT * CC];        // fp16 A (gathered x)
__device__ __nv_bfloat16 g_Whi[12 * CC * CC];   // bf16 split Wt[n][k]
__device__ __nv_bfloat16 g_Wlo[12 * CC * CC];
__device__ __half        g_Wfh[12 * CC * CC];   // fp16 split Wt[n][k]
__device__ __half        g_Wfl[12 * CC * CC];
__device__ __half g_Qh[TT * CC];
__device__ __half g_Kh[TT * CC];
__device__ __half g_Vh[TT * CC];

__device__ __forceinline__ uint32_t smem_to_u32(const void* p) {
    uint32_t a;
    asm("{ .reg .u64 t; cvta.to.shared.u64 t, %1; cvt.u32.u64 %0, t; }" : "=r"(a) : "l"(p));
    return a;
}
__device__ __forceinline__ void ldm4(uint32_t* r, uint32_t addr) {
    asm volatile("ldmatrix.sync.aligned.m8n8.x4.shared.b16 {%0,%1,%2,%3}, [%4];"
                 : "=r"(r[0]), "=r"(r[1]), "=r"(r[2]), "=r"(r[3]) : "r"(addr));
}
__device__ __forceinline__ void ldm4t(uint32_t* r, uint32_t addr) {
    asm volatile("ldmatrix.sync.aligned.m8n8.x4.trans.shared.b16 {%0,%1,%2,%3}, [%4];"
                 : "=r"(r[0]), "=r"(r[1]), "=r"(r[2]), "=r"(r[3]) : "r"(addr));
}
__device__ __forceinline__ void mma_bf16(float* c, const uint32_t* a,
                                         uint32_t b0, uint32_t b1) {
    asm volatile("mma.sync.aligned.m16n8k16.row.col.f32.bf16.bf16.f32 "
                 "{%0,%1,%2,%3}, {%4,%5,%6,%7}, {%8,%9}, {%0,%1,%2,%3};"
                 : "+f"(c[0]), "+f"(c[1]), "+f"(c[2]), "+f"(c[3])
                 : "r"(a[0]), "r"(a[1]), "r"(a[2]), "r"(a[3]), "r"(b0), "r"(b1));
}
__device__ __forceinline__ void mma_f16(float* c, const uint32_t* a,
                                        uint32_t b0, uint32_t b1) {
    asm volatile("mma.sync.aligned.m16n8k16.row.col.f32.f16.f16.f32 "
                 "{%0,%1,%2,%3}, {%4,%5,%6,%7}, {%8,%9}, {%0,%1,%2,%3};"
                 : "+f"(c[0]), "+f"(c[1]), "+f"(c[2]), "+f"(c[3])
                 : "r"(a[0]), "r"(a[1]), "r"(a[2]), "r"(a[3]), "r"(b0), "r"(b1));
}
__device__ __forceinline__ void cp16(uint32_t d, const void* s) {
    asm volatile("cp.async.cg.shared.global [%0], [%1], 16;" :: "r"(d), "l"(s));
}
#define CP_COMMIT() asm volatile("cp.async.commit_group;" ::: "memory")
#define CP_WAIT(n)  asm volatile("cp.async.wait_group %0;" :: "n"(n) : "memory")

__device__ __forceinline__ void split_store(__nv_bfloat16* hi, __nv_bfloat16* lo, float v) {
    const __nv_bfloat16 h = __float2bfloat16(v);
    *hi = h;
    *lo = __float2bfloat16(v - __bfloat162float(h));
}
__device__ __forceinline__ void split_store2(size_t idx, float v0, float v1) {
    const __nv_bfloat16 h0 = __float2bfloat16(v0), h1 = __float2bfloat16(v1);
    const __nv_bfloat16 l0 = __float2bfloat16(v0 - __bfloat162float(h0));
    const __nv_bfloat16 l1 = __float2bfloat16(v1 - __bfloat162float(h1));
    *(__nv_bfloat162*)(g_Ahi + idx) = __nv_bfloat162(h0, h1);
    *(__nv_bfloat162*)(g_Alo + idx) = __nv_bfloat162(l0, l1);
}

// ---------------- weight conversion: all 12 slots, both reps ---------------------
struct WArgs {
    const float* W[12];
    int ldb[12];
    int bcol[12];
};
__global__ void wconv_all(WArgs a) {
    __shared__ float tile[32][33];
    const int slot = blockIdx.z;
    const int k0 = blockIdx.x * 32, n0 = blockIdx.y * 32;
    const int tx = threadIdx.x, ty = threadIdx.y;   // 32 x 8
    const float* W = a.W[slot];
    const int ldb = a.ldb[slot], bcol = a.bcol[slot];
#pragma unroll
    for (int l = 0; l < 4; l++)
        tile[ty + 8 * l][tx] = W[(k0 + ty + 8 * l) * ldb + bcol + n0 + tx];
    __syncthreads();
    const size_t base = (size_t)slot * CC * CC;
#pragma unroll
    for (int l = 0; l < 4; l++) {
        const float v = tile[tx][ty + 8 * l];
        const size_t idx = base + (size_t)(n0 + ty + 8 * l) * CC + k0 + tx;
        split_store(g_Whi + idx, g_Wlo + idx, v);
        const __half fh = __float2half_rn(v);
        g_Wfh[idx] = fh;
        g_Wfl[idx] = __float2half_rn(v - __half2float(fh));
    }
}

// ------------- bf16 3-product GEMM (out-projections): cp.async 2-stage -----------
#define GST 40                       // smem row stride (16-bit elems)
#define MATS (128 * GST)             // one matrix (elems)

__global__ __launch_bounds__(256, 2) void mmagemm(
    const __nv_bfloat16* __restrict__ Ahi, const __nv_bfloat16* __restrict__ Alo,
    const __nv_bfloat16* __restrict__ Bhi, const __nv_bfloat16* __restrict__ Blo,
    const float* __restrict__ bias, float* __restrict__ Cmat, int acc)
{
    extern __shared__ __align__(16) __nv_bfloat16 smb[];
    const int tid = threadIdx.x, lane = tid & 31, wid = tid >> 5;
    const int m0 = blockIdx.y * 128, n0 = blockIdx.x * 128;
    const int wm = (wid >> 2) * 64, wn = (wid & 3) * 32;

    float c[4][4][4];
#pragma unroll
    for (int i = 0; i < 4; i++)
#pragma unroll
        for (int j = 0; j < 4; j++) { c[i][j][0]=0; c[i][j][1]=0; c[i][j][2]=0; c[i][j][3]=0; }

    const __nv_bfloat16* pAh = Ahi + (size_t)m0 * CC;
    const __nv_bfloat16* pAl = Alo + (size_t)m0 * CC;
    const __nv_bfloat16* pBh = Bhi + (size_t)n0 * CC;
    const __nv_bfloat16* pBl = Blo + (size_t)n0 * CC;

    const int g0 = (tid >> 2) * CC + (tid & 3) * 8;
    const int g1 = g0 + 64 * CC;
    const uint32_t s0 = (uint32_t)((tid >> 2) * GST + (tid & 3) * 8);
    const uint32_t s1 = s0 + 64 * GST;
    const uint32_t smb32 = smem_to_u32(smb);

#define ISSUE(stage, kb) do {                                               \
        const uint32_t sbs = smb32 + (uint32_t)(stage) * (4 * MATS * 2);    \
        cp16(sbs + (0 * MATS + s0) * 2, pAh + g0 + (kb));                   \
        cp16(sbs + (0 * MATS + s1) * 2, pAh + g1 + (kb));                   \
        cp16(sbs + (1 * MATS + s0) * 2, pAl + g0 + (kb));                   \
        cp16(sbs + (1 * MATS + s1) * 2, pAl + g1 + (kb));                   \
        cp16(sbs + (2 * MATS + s0) * 2, pBh + g0 + (kb));                   \
        cp16(sbs + (2 * MATS + s1) * 2, pBh + g1 + (kb));                   \
        cp16(sbs + (3 * MATS + s0) * 2, pBl + g0 + (kb));                   \
        cp16(sbs + (3 * MATS + s1) * 2, pBl + g1 + (kb));                   \
        CP_COMMIT();                                                        \
    } while (0)

    ISSUE(0, 0);
    for (int kc = 0; kc < 16; kc++) {
        if (kc + 1 < 16) { ISSUE((kc + 1) & 1, (kc + 1) * 32); CP_WAIT(1); }
        else             { CP_WAIT(0); }
        __syncthreads();
        const uint32_t sb = smb32 + (uint32_t)(kc & 1) * (4 * MATS * 2);
#pragma unroll
        for (int ks = 0; ks < 2; ks++) {
            uint32_t bh[2][4], bl[2][4];
#pragma unroll
            for (int bt = 0; bt < 2; bt++) {
                const int r = wn + bt * 16 + (lane & 15);
                const uint32_t bd = sb + (uint32_t)(2 * MATS + r * GST + ks * 16 + (lane >> 4) * 8) * 2;
                ldm4(bh[bt], bd);
                ldm4(bl[bt], bd + MATS * 2);
            }
#pragma unroll
            for (int mt = 0; mt < 4; mt++) {
                uint32_t ah[4], al[4];
                const int r = wm + mt * 16 + (lane & 15);
                const uint32_t ad = sb + (uint32_t)(r * GST + ks * 16 + (lane >> 4) * 8) * 2;
                ldm4(ah, ad);
                ldm4(al, ad + MATS * 2);
#pragma unroll
                for (int nt = 0; nt < 4; nt++) {
                    const int bt = nt >> 1, sub = nt & 1;
                    mma_bf16(c[mt][nt], ah, bh[bt][sub], bh[bt][sub + 2]);
                    mma_bf16(c[mt][nt], ah, bl[bt][sub], bl[bt][sub + 2]);
                    mma_bf16(c[mt][nt], al, bh[bt][sub], bh[bt][sub + 2]);
                }
            }
        }
        __syncthreads();
    }
#undef ISSUE

#pragma unroll
    for (int mt = 0; mt < 4; mt++) {
        const int r0 = m0 + wm + mt * 16 + (lane >> 2);
#pragma unroll
        for (int nt = 0; nt < 4; nt++) {
            const int col = n0 + wn + nt * 8 + (lane & 3) * 2;
            float2 v0 = make_float2(c[mt][nt][0], c[mt][nt][1]);
            float2 v1 = make_float2(c[mt][nt][2], c[mt][nt][3]);
            const float b0 = bias[col], b1 = bias[col + 1];
            v0.x += b0; v0.y += b1; v1.x += b0; v1.y += b1;
            float* p0 = Cmat + (size_t)r0 * CC + col;
            float* p1 = Cmat + (size_t)(r0 + 8) * CC + col;
            if (acc) {
                const float2 o0 = *(const float2*)p0, o1 = *(const float2*)p1;
                v0.x += o0.x; v0.y += o0.y; v1.x += o1.x; v1.y += o1.y;
            }
            *(float2*)p0 = v0;
            *(float2*)p1 = v1;
        }
    }
}

// ------------- fp16 2-product GEMM (QKV): A fp16, W = Wh + Wl --------------------
__global__ __launch_bounds__(256, 2) void mmagemm16(
    const __half* __restrict__ Af,
    const __half* __restrict__ Bh, const __half* __restrict__ Bl,
    const float* __restrict__ bias, __half* __restrict__ Chalf, float hscale)
{
    extern __shared__ __align__(16) __half smh[];
    const int tid = threadIdx.x, lane = tid & 31, wid = tid >> 5;
    const int m0 = blockIdx.y * 128, n0 = blockIdx.x * 128;
    const int wm = (wid >> 2) * 64, wn = (wid & 3) * 32;

    float c[4][4][4];
#pragma unroll
    for (int i = 0; i < 4; i++)
#pragma unroll
        for (int j = 0; j < 4; j++) { c[i][j][0]=0; c[i][j][1]=0; c[i][j][2]=0; c[i][j][3]=0; }

    const __half* pA  = Af + (size_t)m0 * CC;
    const __half* pBh = Bh + (size_t)n0 * CC;
    const __half* pBl = Bl + (size_t)n0 * CC;

    const int g0 = (tid >> 2) * CC + (tid & 3) * 8;
    const int g1 = g0 + 64 * CC;
    const uint32_t s0 = (uint32_t)((tid >> 2) * GST + (tid & 3) * 8);
    const uint32_t s1 = s0 + 64 * GST;
    const uint32_t smb32 = smem_to_u32(smh);

#define ISSUE16(stage, kb) do {                                             \
        const uint32_t sbs = smb32 + (uint32_t)(stage) * (3 * MATS * 2);    \
        cp16(sbs + (0 * MATS + s0) * 2, pA  + g0 + (kb));                   \
        cp16(sbs + (0 * MATS + s1) * 2, pA  + g1 + (kb));                   \
        cp16(sbs + (1 * MATS + s0) * 2, pBh + g0 + (kb));                   \
        cp16(sbs + (1 * MATS + s1) * 2, pBh + g1 + (kb));                   \
        cp16(sbs + (2 * MATS + s0) * 2, pBl + g0 + (kb));                   \
        cp16(sbs + (2 * MATS + s1) * 2, pBl + g1 + (kb));                   \
        CP_COMMIT();                                                        \
    } while (0)

    ISSUE16(0, 0);
    for (int kc = 0; kc < 16; kc++) {
        if (kc + 1 < 16) { ISSUE16((kc + 1) & 1, (kc + 1) * 32); CP_WAIT(1); }
        else             { CP_WAIT(0); }
        __syncthreads();
        const uint32_t sb = smb32 + (uint32_t)(kc & 1) * (3 * MATS * 2);
#pragma unroll
        for (int ks = 0; ks < 2; ks++) {
            uint32_t bh[2][4], bl[2][4];
#pragma unroll
            for (int bt = 0; bt < 2; bt++) {
                const int r = wn + bt * 16 + (lane & 15);
                const uint32_t bd = sb + (uint32_t)(1 * MATS + r * GST + ks * 16 + (lane >> 4) * 8) * 2;
                ldm4(bh[bt], bd);
                ldm4(bl[bt], bd + MATS * 2);
            }
#pragma unroll
            for (int mt = 0; mt < 4; mt++) {
                uint32_t af[4];
                const int r = wm + mt * 16 + (lane & 15);
                ldm4(af, sb + (uint32_t)(r * GST + ks * 16 + (lane >> 4) * 8) * 2);
#pragma unroll
                for (int nt = 0; nt < 4; nt++) {
                    const int bt = nt >> 1, sub = nt & 1;
                    mma_f16(c[mt][nt], af, bh[bt][sub], bh[bt][sub + 2]);
                    mma_f16(c[mt][nt], af, bl[bt][sub], bl[bt][sub + 2]);
                }
            }
        }
        __syncthreads();
    }
#undef ISSUE16

#pragma unroll
    for (int mt = 0; mt < 4; mt++) {
        const int r0 = m0 + wm + mt * 16 + (lane >> 2);
#pragma unroll
        for (int nt = 0; nt < 4; nt++) {
            const int col = n0 + wn + nt * 8 + (lane & 3) * 2;
            float2 v0 = make_float2(c[mt][nt][0], c[mt][nt][1]);
            float2 v1 = make_float2(c[mt][nt][2], c[mt][nt][3]);
            if (bias) {
                const float b0 = bias[col], b1 = bias[col + 1];
                v0.x += b0; v0.y += b1; v1.x += b0; v1.y += b1;
            }
            *(__half2*)(Chalf + (size_t)r0 * CC + col) =
                __floats2half2_rn(v0.x * hscale, v0.y * hscale);
            *(__half2*)(Chalf + (size_t)(r0 + 8) * CC + col) =
                __floats2half2_rn(v1.x * hscale, v1.y * hscale);
        }
    }
}

// ------------- branch 1 attention: flash-style fp16 mma, seq 576 -----------------
#define FST 72    // smem half-stride

__global__ __launch_bounds__(128) void attn576_mma() {
    __shared__ __half Qs[64 * FST], Ks[64 * FST], Vs[64 * FST];
    const int qt = blockIdx.x, h = blockIdx.y, bd = blockIdx.z;
    const int tid = threadIdx.x, lane = tid & 31, wid = tid >> 5;
    const int rq = bd * 576 + qt * 64, rb = bd * 576;
    const uint32_t sQ = smem_to_u32(Qs), sK = smem_to_u32(Ks), sV = smem_to_u32(Vs);

#pragma unroll
    for (int i = 0; i < 4; i++) {
        const int e = tid + i * 128;
        const int r = e >> 3, cu = e & 7;
        *(uint4*)(Qs + r * FST + cu * 8) =
            *(const uint4*)(g_Qh + (size_t)(rq + r) * CC + h * 64 + cu * 8);
    }
    __syncthreads();

    uint32_t qf[4][4];
#pragma unroll
    for (int ks = 0; ks < 4; ks++) {
        const uint32_t ad = sQ + (uint32_t)((wid * 16 + (lane & 15)) * FST
                                            + ks * 16 + (lane >> 4) * 8) * 2;
        ldm4(qf[ks], ad);
    }

    float oacc[8][4];
#pragma unroll
    for (int nt = 0; nt < 8; nt++) { oacc[nt][0]=0; oacc[nt][1]=0; oacc[nt][2]=0; oacc[nt][3]=0; }
    float mrow[2] = {-1e30f, -1e30f};
    float lrow[2] = {0.f, 0.f};

    for (int kt = 0; kt < 9; kt++) {
        __syncthreads();
#pragma unroll
        for (int i = 0; i < 4; i++) {
            const int e = tid + i * 128;
            const int r = e >> 3, cu = e & 7;
            const size_t grow = (size_t)(rb + kt * 64 + r) * CC + h * 64 + cu * 8;
            *(uint4*)(Ks + r * FST + cu * 8) = *(const uint4*)(g_Kh + grow);
            *(uint4*)(Vs + r * FST + cu * 8) = *(const uint4*)(g_Vh + grow);
        }
        __syncthreads();

        float c[8][4];
#pragma unroll
        for (int nt = 0; nt < 8; nt++) { c[nt][0]=0; c[nt][1]=0; c[nt][2]=0; c[nt][3]=0; }
#pragma unroll
        for (int ks = 0; ks < 4; ks++) {
#pragma unroll
            for (int bt = 0; bt < 4; bt++) {
                uint32_t kf[4];
                const uint32_t kd = sK + (uint32_t)((bt * 16 + (lane & 15)) * FST
                                                    + ks * 16 + (lane >> 4) * 8) * 2;
                ldm4(kf, kd);
                mma_f16(c[bt * 2 + 0], qf[ks], kf[0], kf[2]);
                mma_f16(c[bt * 2 + 1], qf[ks], kf[1], kf[3]);
            }
        }

        float tm0 = -1e30f, tm1 = -1e30f;
#pragma unroll
        for (int nt = 0; nt < 8; nt++) {
            tm0 = fmaxf(tm0, fmaxf(c[nt][0], c[nt][1]));
            tm1 = fmaxf(tm1, fmaxf(c[nt][2], c[nt][3]));
        }
        tm0 = fmaxf(tm0, __shfl_xor_sync(0xffffffffu, tm0, 1));
        tm0 = fmaxf(tm0, __shfl_xor_sync(0xffffffffu, tm0, 2));
        tm1 = fmaxf(tm1, __shfl_xor_sync(0xffffffffu, tm1, 1));
        tm1 = fmaxf(tm1, __shfl_xor_sync(0xffffffffu, tm1, 2));
        const float mn0 = fmaxf(mrow[0], tm0), mn1 = fmaxf(mrow[1], tm1);
        const float al0 = __expf(mrow[0] - mn0), al1 = __expf(mrow[1] - mn1);
        mrow[0] = mn0; mrow[1] = mn1;
        float rs0 = 0.f, rs1 = 0.f;
        uint32_t pf[4][4];
#pragma unroll
        for (int nt = 0; nt < 8; nt++) {
            const float p0 = __expf(c[nt][0] - mn0), p1 = __expf(c[nt][1] - mn0);
            const float p2 = __expf(c[nt][2] - mn1), p3 = __expf(c[nt][3] - mn1);
            rs0 += p0 + p1; rs1 += p2 + p3;
            const int kchunk = nt >> 1, half_sel = nt & 1;
            const __half2 h01 = __floats2half2_rn(p0, p1);
            const __half2 h23 = __floats2half2_rn(p2, p3);
            pf[kchunk][half_sel * 2 + 0] = *(const uint32_t*)&h01;
            pf[kchunk][half_sel * 2 + 1] = *(const uint32_t*)&h23;
        }
        rs0 += __shfl_xor_sync(0xffffffffu, rs0, 1);
        rs0 += __shfl_xor_sync(0xffffffffu, rs0, 2);
        rs1 += __shfl_xor_sync(0xffffffffu, rs1, 1);
        rs1 += __shfl_xor_sync(0xffffffffu, rs1, 2);
        lrow[0] = lrow[0] * al0 + rs0;
        lrow[1] = lrow[1] * al1 + rs1;
#pragma unroll
        for (int nt = 0; nt < 8; nt++) {
            oacc[nt][0] *= al0; oacc[nt][1] *= al0;
            oacc[nt][2] *= al1; oacc[nt][3] *= al1;
        }

#pragma unroll
        for (int ks = 0; ks < 4; ks++) {
#pragma unroll
            for (int vt = 0; vt < 4; vt++) {
                uint32_t vf[4];
                const int vr = ks * 16 + (lane & 7) + ((lane >> 3) & 1) * 8;
                const int vc = vt * 16 + (lane >> 4) * 8;
                ldm4t(vf, sV + (uint32_t)(vr * FST + vc) * 2);
                mma_f16(oacc[vt * 2 + 0], pf[ks], vf[0], vf[1]);
                mma_f16(oacc[vt * 2 + 1], pf[ks], vf[2], vf[3]);
            }
        }
    }

    const float il0 = 1.f / lrow[0], il1 = 1.f / lrow[1];
    const int r0 = rq + wid * 16 + (lane >> 2);
#pragma unroll
    for (int nt = 0; nt < 8; nt++) {
        const int col = h * 64 + nt * 8 + (lane & 3) * 2;
        split_store2((size_t)r0 * CC + col, oacc[nt][0] * il0, oacc[nt][1] * il0);
        split_store2((size_t)(r0 + 8) * CC + col, oacc[nt][2] * il1, oacc[nt][3] * il1);
    }
}

// ------------- branch 3: window attention, fp16 mma ------------------------------
__global__ __launch_bounds__(128) void attnwin_mma(const float* __restrict__ pos_table) {
    __shared__ __half Qs[64 * FST], Ks[64 * FST], Vs[64 * FST];
    __shared__ float pos[343];
    const int win = blockIdx.x, h = blockIdx.y, b = blockIdx.z;
    const int wd = win / 36, ww = (win / 6) % 6, wh = win % 6;
    const int tid = threadIdx.x, lane = tid & 31, wid = tid >> 5;
    const int base = b * NTOK + wd * 4 * 576 + ww * 4 * 24 + wh * 4;
    const uint32_t sQ = smem_to_u32(Qs), sK = smem_to_u32(Ks), sV = smem_to_u32(Vs);

    for (int e = tid; e < 343; e += 128) pos[e] = pos_table[e];
#pragma unroll
    for (int i = 0; i < 4; i++) {
        const int e = tid + i * 128;
        const int r = e >> 3, cu = e & 7;
        const int grow = base + (r >> 4) * 576 + ((r >> 2) & 3) * 24 + (r & 3);
        const size_t go = (size_t)grow * CC + h * 64 + cu * 8;
        *(uint4*)(Qs + r * FST + cu * 8) = *(const uint4*)(g_Qh + go);
        *(uint4*)(Ks + r * FST + cu * 8) = *(const uint4*)(g_Kh + go);
        *(uint4*)(Vs + r * FST + cu * 8) = *(const uint4*)(g_Vh + go);
    }
    __syncthreads();

    uint32_t qf[4][4];
#pragma unroll
    for (int ks = 0; ks < 4; ks++) {
        const uint32_t ad = sQ + (uint32_t)((wid * 16 + (lane & 15)) * FST
                                            + ks * 16 + (lane >> 4) * 8) * 2;
        ldm4(qf[ks], ad);
    }

    float c[8][4];
#pragma unroll
    for (int nt = 0; nt < 8; nt++) { c[nt][0]=0; c[nt][1]=0; c[nt][2]=0; c[nt][3]=0; }
#pragma unroll
    for (int ks = 0; ks < 4; ks++) {
#pragma unroll
        for (int bt = 0; bt < 4; bt++) {
            uint32_t kf[4];
            const uint32_t kd = sK + (uint32_t)((bt * 16 + (lane & 15)) * FST
                                                + ks * 16 + (lane >> 4) * 8) * 2;
            ldm4(kf, kd);
            mma_f16(c[bt * 2 + 0], qf[ks], kf[0], kf[2]);
            mma_f16(c[bt * 2 + 1], qf[ks], kf[1], kf[3]);
        }
    }

    const int mA = wid * 16 + (lane >> 2), mB = mA + 8;
    const int amA = mA >> 4, bmA = (mA >> 2) & 3, cmA = mA & 3;
    const int amB = mB >> 4, bmB = (mB >> 2) & 3, cmB = mB & 3;
#pragma unroll
    for (int nt = 0; nt < 8; nt++) {
#pragma unroll
        for (int e = 0; e < 2; e++) {
            const int col = nt * 8 + (lane & 3) * 2 + e;
            const int aj = col >> 4, bj = (col >> 2) & 3, cj = col & 3;
            c[nt][e]     += pos[(aj - amA + 3) * 49 + (bj - bmA + 3) * 7 + (cj - cmA + 3)];
            c[nt][2 + e] += pos[(aj - amB + 3) * 49 + (bj - bmB + 3) * 7 + (cj - cmB + 3)];
        }
    }

    float tm0 = -1e30f, tm1 = -1e30f;
#pragma unroll
    for (int nt = 0; nt < 8; nt++) {
        tm0 = fmaxf(tm0, fmaxf(c[nt][0], c[nt][1]));
        tm1 = fmaxf(tm1, fmaxf(c[nt][2], c[nt][3]));
    }
    tm0 = fmaxf(tm0, __shfl_xor_sync(0xffffffffu, tm0, 1));
    tm0 = fmaxf(tm0, __shfl_xor_sync(0xffffffffu, tm0, 2));
    tm1 = fmaxf(tm1, __shfl_xor_sync(0xffffffffu, tm1, 1));
    tm1 = fmaxf(tm1, __shfl_xor_sync(0xffffffffu, tm1, 2));
    float rs0 = 0.f, rs1 = 0.f;
    uint32_t pf[4][4];
#pragma unroll
    for (int nt = 0; nt < 8; nt++) {
        const float p0 = __expf(c[nt][0] - tm0), p1 = __expf(c[nt][1] - tm0);
        const float p2 = __expf(c[nt][2] - tm1), p3 = __expf(c[nt][3] - tm1);
        rs0 += p0 + p1; rs1 += p2 + p3;
        const int kchunk = nt >> 1, half_sel = nt & 1;
        const __half2 h01 = __floats2half2_rn(p0, p1);
        const __half2 h23 = __floats2half2_rn(p2, p3);
        pf[kchunk][half_sel * 2 + 0] = *(const uint32_t*)&h01;
        pf[kchunk][half_sel * 2 + 1] = *(const uint32_t*)&h23;
    }
    rs0 += __shfl_xor_sync(0xffffffffu, rs0, 1);
    rs0 += __shfl_xor_sync(0xffffffffu, rs0, 2);
    rs1 += __shfl_xor_sync(0xffffffffu, rs1, 1);
    rs1 += __shfl_xor_sync(0xffffffffu, rs1, 2);

    float oacc[8][4];
#pragma unroll
    for (int nt = 0; nt < 8; nt++) { oacc[nt][0]=0; oacc[nt][1]=0; oacc[nt][2]=0; oacc[nt][3]=0; }
#pragma unroll
    for (int ks = 0; ks < 4; ks++) {
#pragma unroll
        for (int vt = 0; vt < 4; vt++) {
            uint32_t vf[4];
            const int vr = ks * 16 + (lane & 7) + ((lane >> 3) & 1) * 8;
            const int vc = vt * 16 + (lane >> 4) * 8;
            ldm4t(vf, sV + (uint32_t)(vr * FST + vc) * 2);
            mma_f16(oacc[vt * 2 + 0], pf[ks], vf[0], vf[1]);
            mma_f16(oacc[vt * 2 + 1], pf[ks], vf[2], vf[3]);
        }
    }

    const float il0 = 1.f / rs0, il1 = 1.f / rs1;
    const int gA = base + (mA >> 4) * 576 + ((mA >> 2) & 3) * 24 + (mA & 3);
    const int gB = base + (mB >> 4) * 576 + ((mB >> 2) & 3) * 24 + (mB & 3);
#pragma unroll
    for (int nt = 0; nt < 8; nt++) {
        const int col = h * 64 + nt * 8 + (lane & 3) * 2;
        split_store2((size_t)gA * CC + col, oacc[nt][0] * il0, oacc[nt][1] * il0);
        split_store2((size_t)gB * CC + col, oacc[nt][2] * il1, oacc[nt][3] * il1);
    }
}

// ---- gathers: write fp16 g_Af directly ------------------------------------------
__global__ void gather_x1(const float* __restrict__ x) {
    __shared__ float tile[32][33];
    const int i  = blockIdx.z;
    const int p0 = blockIdx.x * 32;
    const int c0 = blockIdx.y * 32;
    const int tx = threadIdx.x, ty = threadIdx.y;   // 32 x 8
    const float* src = x + i * 294912;
#pragma unroll
    for (int l = 0; l < 4; l++)
        tile[ty + 8 * l][tx] = src[(c0 + ty + 8 * l) * 576 + p0 + tx];
    __syncthreads();
    const size_t dst = (size_t)(i * 576 + p0) * CC + c0;
#pragma unroll
    for (int l = 0; l < 4; l++)
        g_Af[dst + (size_t)(ty + 8 * l) * CC + tx] = __float2half_rn(tile[tx][ty + 8 * l]);
}

__global__ void gather_xT(const float* __restrict__ x) {
    __shared__ float tile[32][33];
    const int b  = blockIdx.z;
    const int n0 = blockIdx.x * 32;
    const int c0 = blockIdx.y * 32;
    const int tx = threadIdx.x, ty = threadIdx.y;   // 32 x 8
    const float* src = x + b * (CC * NTOK);
#pragma unroll
    for (int i = 0; i < 4; i++)
        tile[ty + 8 * i][tx] = src[(c0 + ty + 8 * i) * NTOK + n0 + tx];
    __syncthreads();
    const size_t dst = (size_t)(b * NTOK + n0) * CC + c0;
#pragma unroll
    for (int i = 0; i < 4; i++)
        g_Af[dst + (size_t)(ty + 8 * i) * CC + tx] = __float2half_rn(tile[tx][ty + 8 * i]);
}

__global__ void gather_x2(const float* __restrict__ x) {
    __shared__ float t2[24][257];
    const int i = blockIdx.x;
    const float* src = x + i * 12288;
    const int tid = threadIdx.x;              // 256
    for (int half = 0; half < 2; half++) {
        const int j0 = half * 256;
#pragma unroll
        for (int l = 0; l < 24; l++) {
            int e = l * 256 + tid;
            int j = e / 24, k = e - j * 24;
            t2[k][j] = src[j0 * 24 + e];
        }
        __syncthreads();
#pragma unroll
        for (int l = 0; l < 24; l++) {
            int e  = l * 256 + tid;
            int k  = e >> 8, jj = e & 255;
            g_Af[(size_t)(i * 24 + k) * CC + j0 + jj] = __float2half_rn(t2[k][jj]);
        }
        __syncthreads();
    }
}

// ---------------- branch 2: tiny seq-24 attention (fp16 in, split out) -----------
__global__ __launch_bounds__(256) void attn_seq24() {
    __shared__ float Qs[24 * 65], Ks[24 * 65], Vs[24 * 65], P[24 * 25];
    const int i = blockIdx.x, h = blockIdx.y;
    const int tid = threadIdx.x;
    const size_t rbase = (size_t)i * 24 * CC + h * 64;

    for (int e = tid; e < 24 * 64; e += 256) {
        const int k = e >> 6, d = e & 63;
        Qs[k * 65 + d] = __half2float(g_Qh[rbase + k * CC + d]);
        Ks[k * 65 + d] = __half2float(g_Kh[rbase + k * CC + d]);
        Vs[k * 65 + d] = __half2float(g_Vh[rbase + k * CC + d]);
    }
    __syncthreads();
    for (int sid = tid; sid < 576; sid += 256) {
        const int r = sid / 24, c = sid - r * 24;
        float s = 0.f;
#pragma unroll 16
        for (int d = 0; d < 64; d++) s += Qs[r * 65 + d] * Ks[c * 65 + d];
        P[r * 25 + c] = s;              // Q pre-scaled by 0.125 in GEMM epilogue
    }
    __syncthreads();
    if (tid < 24) {
        float mx = -1e30f;
        for (int c = 0; c < 24; c++) mx = fmaxf(mx, P[tid * 25 + c]);
        float sum = 0.f;
        for (int c = 0; c < 24; c++) {
            const float p = __expf(P[tid * 25 + c] - mx);
            P[tid * 25 + c] = p; sum += p;
        }
        const float inv = 1.f / sum;
        for (int c = 0; c < 24; c++) P[tid * 25 + c] *= inv;
    }
    __syncthreads();
    for (int e = tid; e < 24 * 32; e += 256) {
        const int r = e >> 5, d2 = (e & 31) * 2;
        float o0 = 0.f, o1 = 0.f;
#pragma unroll
        for (int j = 0; j < 24; j++) {
            const float p = P[r * 25 + j];
            o0 += p * Vs[j * 65 + d2];
            o1 += p * Vs[j * 65 + d2 + 1];
        }
        split_store2(rbase + (size_t)r * CC + d2, o0, o1);
    }
}

// ---------------- orchestration --------------------------------------------------
extern "C" void kernel_launch(void* const* d_in, const int* in_sizes, int n_in,
                              void* d_out, int out_size) {
    const float* x     = (const float*)d_in[0];
    const float* vq_w  = (const float*)d_in[1];
    const float* vq_b  = (const float*)d_in[2];
    const float* vk_w  = (const float*)d_in[3];
    const float* vk_b  = (const float*)d_in[4];
    const float* vv_w  = (const float*)d_in[5];
    const float* vv_b  = (const float*)d_in[6];
    const float* vo_w  = (const float*)d_in[7];
    const float* vo_b  = (const float*)d_in[8];
    const float* hq_w  = (const float*)d_in[9];
    const float* hq_b  = (const float*)d_in[10];
    const float* hk_w  = (const float*)d_in[11];
    const float* hk_b  = (const float*)d_in[12];
    const float* hv_w  = (const float*)d_in[13];
    const float* hv_b  = (const float*)d_in[14];
    const float* ho_w  = (const float*)d_in[15];
    const float* ho_b  = (const float*)d_in[16];
    const float* qkv_w = (const float*)d_in[17];
    const float* ow_w  = (const float*)d_in[18];
    const float* ow_b  = (const float*)d_in[19];
    const float* pos   = (const float*)d_in[20];
    float* out = (float*)d_out;
    (void)in_sizes; (void)n_in; (void)out_size;

    __nv_bfloat16 *pAh, *pAl, *pWh, *pWl;
    __half *pAf, *pWfh, *pWfl, *pQh, *pKh, *pVh;
    cudaGetSymbolAddress((void**)&pAh, g_Ahi);
    cudaGetSymbolAddress((void**)&pAl, g_Alo);
    cudaGetSymbolAddress((void**)&pAf, g_Af);
    cudaGetSymbolAddress((void**)&pWh, g_Whi);
    cudaGetSymbolAddress((void**)&pWl, g_Wlo);
    cudaGetSymbolAddress((void**)&pWfh, g_Wfh);
    cudaGetSymbolAddress((void**)&pWfl, g_Wfl);
    cudaGetSymbolAddress((void**)&pQh, g_Qh);
    cudaGetSymbolAddress((void**)&pKh, g_Kh);
    cudaGetSymbolAddress((void**)&pVh, g_Vh);

    const int SMEMG  = 2 * 4 * MATS * 2;   // 81920 B (bf16 3-product)
    const int SMEMG2 = 2 * 3 * MATS * 2;   // 61440 B (fp16 2-product)
    cudaFuncSetAttribute(mmagemm,   cudaFuncAttributeMaxDynamicSharedMemorySize, SMEMG);
    cudaFuncSetAttribute(mmagemm16, cudaFuncAttributeMaxDynamicSharedMemorySize, SMEMG2);

    // weight slots: 0 vq, 1 vk, 2 vv, 3 vo, 4 hq, 5 hk, 6 hv, 7 ho,
    //               8 qkv.q, 9 qkv.k, 10 qkv.v, 11 win_out
    WArgs wa;
    const float* wp[12] = {vq_w, vk_w, vv_w, vo_w, hq_w, hk_w, hv_w, ho_w,
                           qkv_w, qkv_w, qkv_w, ow_w};
    const int wl[12] = {512,512,512,512,512,512,512,512,1536,1536,1536,512};
    const int wc[12] = {0,0,0,0,0,0,0,0,0,512,1024,0};
    for (int s = 0; s < 12; s++) { wa.W[s] = wp[s]; wa.ldb[s] = wl[s]; wa.bcol[s] = wc[s]; }
    wconv_all<<<dim3(16, 16, 12), dim3(32, 8)>>>(wa);

    const dim3 gg(4, 216);
    const size_t WS = (size_t)CC * CC;
#define TCG(slot, b, ac) \
    mmagemm<<<gg, 256, SMEMG>>>(pAh, pAl, pWh + (slot) * WS, pWl + (slot) * WS, b, out, ac)
#define TCGH(slot, b, Hp, sc) \
    mmagemm16<<<gg, 256, SMEMG2>>>(pAf, pWfh + (slot) * WS, pWfl + (slot) * WS, b, Hp, sc)

    // ---- branch 1 (seq-576 full attention, fp16 flash) ----
    gather_x1<<<dim3(18, 16, 48), dim3(32, 8)>>>(x);
    TCGH(0, vq_b, pQh, 0.125f);
    TCGH(1, vk_b, pKh, 1.f);
    TCGH(2, vv_b, pVh, 1.f);
    attn576_mma<<<dim3(9, 8, 48), 128>>>();     // writes split O into g_Ahi/g_Alo
    TCG(3, vo_b, 0);                             // first write of out

    // ---- branch 3 (window attention, fp16 mma) ----
    gather_xT<<<dim3(432, 16, 2), dim3(32, 8)>>>(x);
    TCGH(8, nullptr, pQh, 0.125f);
    TCGH(9, nullptr, pKh, 1.f);
    TCGH(10, nullptr, pVh, 1.f);
    attnwin_mma<<<dim3(216, 8, 2), 128>>>(pos);
    TCG(11, ow_b, 1);                            // accumulate

    // ---- branch 2 (seq-24 full attention) ----
    gather_x2<<<1152, 256>>>(x);
    TCGH(4, hq_b, pQh, 0.125f);
    TCGH(5, hk_b, pKh, 1.f);
    TCGH(6, hv_b, pVh, 1.f);
    attn_seq24<<<dim3(1152, 8), 256>>>();
    TCG(7, ho_b, 1);                             // accumulate
#undef TCG
#undef TCGH
}

// round 10
// speedup vs baseline: 4.5646x; 1.4207x over previous
#include <cuda_runtime.h>
#include <cuda_fp16.h>
#include <cstdint>

#define CC 512
#define NTOK 13824            // 24*24*24
#define TT 27648              // B * NTOK

// ---------------- scratch (device globals; no allocation allowed) ----------------
__device__ __half g_Af [TT * CC];        // fp16 A (gathered x / attention outputs)
__device__ __half g_Wfh[12 * CC * CC];   // fp16 split Wt[n][k]
__device__ __half g_Wfl[12 * CC * CC];
__device__ __half g_Qh[TT * CC];
__device__ __half g_Kh[TT * CC];
__device__ __half g_Vh[TT * CC];

__device__ __forceinline__ uint32_t smem_to_u32(const void* p) {
    uint32_t a;
    asm("{ .reg .u64 t; cvta.to.shared.u64 t, %1; cvt.u32.u64 %0, t; }" : "=r"(a) : "l"(p));
    return a;
}
__device__ __forceinline__ void ldm4(uint32_t* r, uint32_t addr) {
    asm volatile("ldmatrix.sync.aligned.m8n8.x4.shared.b16 {%0,%1,%2,%3}, [%4];"
                 : "=r"(r[0]), "=r"(r[1]), "=r"(r[2]), "=r"(r[3]) : "r"(addr));
}
__device__ __forceinline__ void ldm4t(uint32_t* r, uint32_t addr) {
    asm volatile("ldmatrix.sync.aligned.m8n8.x4.trans.shared.b16 {%0,%1,%2,%3}, [%4];"
                 : "=r"(r[0]), "=r"(r[1]), "=r"(r[2]), "=r"(r[3]) : "r"(addr));
}
__device__ __forceinline__ void mma_f16(float* c, const uint32_t* a,
                                        uint32_t b0, uint32_t b1) {
    asm volatile("mma.sync.aligned.m16n8k16.row.col.f32.f16.f16.f32 "
                 "{%0,%1,%2,%3}, {%4,%5,%6,%7}, {%8,%9}, {%0,%1,%2,%3};"
                 : "+f"(c[0]), "+f"(c[1]), "+f"(c[2]), "+f"(c[3])
                 : "r"(a[0]), "r"(a[1]), "r"(a[2]), "r"(a[3]), "r"(b0), "r"(b1));
}
__device__ __forceinline__ void cp16(uint32_t d, const void* s) {
    asm volatile("cp.async.cg.shared.global [%0], [%1], 16;" :: "r"(d), "l"(s));
}
#define CP_COMMIT() asm volatile("cp.async.commit_group;" ::: "memory")
#define CP_WAIT(n)  asm volatile("cp.async.wait_group %0;" :: "n"(n) : "memory")

// ---------------- weight conversion: all 12 slots ---------------------------------
struct WArgs {
    const float* W[12];
    int ldb[12];
    int bcol[12];
};
__global__ void wconv_all(WArgs a) {
    __shared__ float tile[32][33];
    const int slot = blockIdx.z;
    const int k0 = blockIdx.x * 32, n0 = blockIdx.y * 32;
    const int tx = threadIdx.x, ty = threadIdx.y;   // 32 x 8
    const float* W = a.W[slot];
    const int ldb = a.ldb[slot], bcol = a.bcol[slot];
#pragma unroll
    for (int l = 0; l < 4; l++)
        tile[ty + 8 * l][tx] = W[(k0 + ty + 8 * l) * ldb + bcol + n0 + tx];
    __syncthreads();
    const size_t base = (size_t)slot * CC * CC;
#pragma unroll
    for (int l = 0; l < 4; l++) {
        const float v = tile[tx][ty + 8 * l];
        const size_t idx = base + (size_t)(n0 + ty + 8 * l) * CC + k0 + tx;
        const __half fh = __float2half_rn(v);
        g_Wfh[idx] = fh;
        g_Wfl[idx] = __float2half_rn(v - __half2float(fh));
    }
}

// ------------- fp16 GEMM (NPROD = 1 or 2 W products), cp.async 2-stage -----------
#define GST 40                       // smem row stride (16-bit elems)
#define MATS (128 * GST)             // one matrix (elems)

template<int NPROD>
__global__ __launch_bounds__(256, 2) void gemm16(
    const __half* __restrict__ Af,
    const __half* __restrict__ Bh, const __half* __restrict__ Bl,
    const float* __restrict__ bias,
    __half* __restrict__ Chalf, float hscale,
    float* __restrict__ Cout, int acc)
{
    extern __shared__ __align__(16) __half smh[];
    const int tid = threadIdx.x, lane = tid & 31, wid = tid >> 5;
    const int m0 = blockIdx.y * 128, n0 = blockIdx.x * 128;
    const int wm = (wid >> 2) * 64, wn = (wid & 3) * 32;
    const int NMAT = 1 + NPROD;

    float c[4][4][4];
#pragma unroll
    for (int i = 0; i < 4; i++)
#pragma unroll
        for (int j = 0; j < 4; j++) { c[i][j][0]=0; c[i][j][1]=0; c[i][j][2]=0; c[i][j][3]=0; }

    const __half* pA  = Af + (size_t)m0 * CC;
    const __half* pBh = Bh + (size_t)n0 * CC;
    const __half* pBl = Bl + (size_t)n0 * CC;

    const int g0 = (tid >> 2) * CC + (tid & 3) * 8;
    const int g1 = g0 + 64 * CC;
    const uint32_t s0 = (uint32_t)((tid >> 2) * GST + (tid & 3) * 8);
    const uint32_t s1 = s0 + 64 * GST;
    const uint32_t smb32 = smem_to_u32(smh);

#define ISSUE16(stage, kb) do {                                             \
        const uint32_t sbs = smb32 + (uint32_t)(stage) * (NMAT * MATS * 2); \
        cp16(sbs + (0 * MATS + s0) * 2, pA  + g0 + (kb));                   \
        cp16(sbs + (0 * MATS + s1) * 2, pA  + g1 + (kb));                   \
        cp16(sbs + (1 * MATS + s0) * 2, pBh + g0 + (kb));                   \
        cp16(sbs + (1 * MATS + s1) * 2, pBh + g1 + (kb));                   \
        if (NPROD == 2) {                                                   \
            cp16(sbs + (2 * MATS + s0) * 2, pBl + g0 + (kb));               \
            cp16(sbs + (2 * MATS + s1) * 2, pBl + g1 + (kb));               \
        }                                                                   \
        CP_COMMIT();                                                        \
    } while (0)

    ISSUE16(0, 0);
    for (int kc = 0; kc < 16; kc++) {
        if (kc + 1 < 16) { ISSUE16((kc + 1) & 1, (kc + 1) * 32); CP_WAIT(1); }
        else             { CP_WAIT(0); }
        __syncthreads();
        const uint32_t sb = smb32 + (uint32_t)(kc & 1) * (NMAT * MATS * 2);
#pragma unroll
        for (int ks = 0; ks < 2; ks++) {
            uint32_t bh[2][4], bl[2][4];
#pragma unroll
            for (int bt = 0; bt < 2; bt++) {
                const int r = wn + bt * 16 + (lane & 15);
                const uint32_t bd = sb + (uint32_t)(1 * MATS + r * GST + ks * 16 + (lane >> 4) * 8) * 2;
                ldm4(bh[bt], bd);
                if (NPROD == 2) ldm4(bl[bt], bd + MATS * 2);
            }
#pragma unroll
            for (int mt = 0; mt < 4; mt++) {
                uint32_t af[4];
                const int r = wm + mt * 16 + (lane & 15);
                ldm4(af, sb + (uint32_t)(r * GST + ks * 16 + (lane >> 4) * 8) * 2);
#pragma unroll
                for (int nt = 0; nt < 4; nt++) {
                    const int bt = nt >> 1, sub = nt & 1;
                    mma_f16(c[mt][nt], af, bh[bt][sub], bh[bt][sub + 2]);
                    if (NPROD == 2)
                        mma_f16(c[mt][nt], af, bl[bt][sub], bl[bt][sub + 2]);
                }
            }
        }
        __syncthreads();
    }
#undef ISSUE16

#pragma unroll
    for (int mt = 0; mt < 4; mt++) {
        const int r0 = m0 + wm + mt * 16 + (lane >> 2);
#pragma unroll
        for (int nt = 0; nt < 4; nt++) {
            const int col = n0 + wn + nt * 8 + (lane & 3) * 2;
            float2 v0 = make_float2(c[mt][nt][0], c[mt][nt][1]);
            float2 v1 = make_float2(c[mt][nt][2], c[mt][nt][3]);
            if (bias) {
                const float b0 = bias[col], b1 = bias[col + 1];
                v0.x += b0; v0.y += b1; v1.x += b0; v1.y += b1;
            }
            if (Cout) {
                float* p0 = Cout + (size_t)r0 * CC + col;
                float* p1 = Cout + (size_t)(r0 + 8) * CC + col;
                if (acc) {
                    const float2 o0 = *(const float2*)p0, o1 = *(const float2*)p1;
                    v0.x += o0.x; v0.y += o0.y; v1.x += o1.x; v1.y += o1.y;
                }
                *(float2*)p0 = v0;
                *(float2*)p1 = v1;
            } else {
                *(__half2*)(Chalf + (size_t)r0 * CC + col) =
                    __floats2half2_rn(v0.x * hscale, v0.y * hscale);
                *(__half2*)(Chalf + (size_t)(r0 + 8) * CC + col) =
                    __floats2half2_rn(v1.x * hscale, v1.y * hscale);
            }
        }
    }
}

// ------------- branch 1 attention: flash-style fp16 mma, seq 576 -----------------
#define FST 72    // smem half-stride

__global__ __launch_bounds__(128) void attn576_mma() {
    __shared__ __half Qs[64 * FST], Ks[64 * FST], Vs[64 * FST];
    const int qt = blockIdx.x, h = blockIdx.y, bd = blockIdx.z;
    const int tid = threadIdx.x, lane = tid & 31, wid = tid >> 5;
    const int rq = bd * 576 + qt * 64, rb = bd * 576;
    const uint32_t sQ = smem_to_u32(Qs), sK = smem_to_u32(Ks), sV = smem_to_u32(Vs);

#pragma unroll
    for (int i = 0; i < 4; i++) {
        const int e = tid + i * 128;
        const int r = e >> 3, cu = e & 7;
        *(uint4*)(Qs + r * FST + cu * 8) =
            *(const uint4*)(g_Qh + (size_t)(rq + r) * CC + h * 64 + cu * 8);
    }
    __syncthreads();

    uint32_t qf[4][4];
#pragma unroll
    for (int ks = 0; ks < 4; ks++) {
        const uint32_t ad = sQ + (uint32_t)((wid * 16 + (lane & 15)) * FST
                                            + ks * 16 + (lane >> 4) * 8) * 2;
        ldm4(qf[ks], ad);
    }

    float oacc[8][4];
#pragma unroll
    for (int nt = 0; nt < 8; nt++) { oacc[nt][0]=0; oacc[nt][1]=0; oacc[nt][2]=0; oacc[nt][3]=0; }
    float mrow[2] = {-1e30f, -1e30f};
    float lrow[2] = {0.f, 0.f};

    for (int kt = 0; kt < 9; kt++) {
        __syncthreads();
#pragma unroll
        for (int i = 0; i < 4; i++) {
            const int e = tid + i * 128;
            const int r = e >> 3, cu = e & 7;
            const size_t grow = (size_t)(rb + kt * 64 + r) * CC + h * 64 + cu * 8;
            *(uint4*)(Ks + r * FST + cu * 8) = *(const uint4*)(g_Kh + grow);
            *(uint4*)(Vs + r * FST + cu * 8) = *(const uint4*)(g_Vh + grow);
        }
        __syncthreads();

        float c[8][4];
#pragma unroll
        for (int nt = 0; nt < 8; nt++) { c[nt][0]=0; c[nt][1]=0; c[nt][2]=0; c[nt][3]=0; }
#pragma unroll
        for (int ks = 0; ks < 4; ks++) {
#pragma unroll
            for (int bt = 0; bt < 4; bt++) {
                uint32_t kf[4];
                const uint32_t kd = sK + (uint32_t)((bt * 16 + (lane & 15)) * FST
                                                    + ks * 16 + (lane >> 4) * 8) * 2;
                ldm4(kf, kd);
                mma_f16(c[bt * 2 + 0], qf[ks], kf[0], kf[2]);
                mma_f16(c[bt * 2 + 1], qf[ks], kf[1], kf[3]);
            }
        }

        float tm0 = -1e30f, tm1 = -1e30f;
#pragma unroll
        for (int nt = 0; nt < 8; nt++) {
            tm0 = fmaxf(tm0, fmaxf(c[nt][0], c[nt][1]));
            tm1 = fmaxf(tm1, fmaxf(c[nt][2], c[nt][3]));
        }
        tm0 = fmaxf(tm0, __shfl_xor_sync(0xffffffffu, tm0, 1));
        tm0 = fmaxf(tm0, __shfl_xor_sync(0xffffffffu, tm0, 2));
        tm1 = fmaxf(tm1, __shfl_xor_sync(0xffffffffu, tm1, 1));
        tm1 = fmaxf(tm1, __shfl_xor_sync(0xffffffffu, tm1, 2));
        const float mn0 = fmaxf(mrow[0], tm0), mn1 = fmaxf(mrow[1], tm1);
        const float al0 = __expf(mrow[0] - mn0), al1 = __expf(mrow[1] - mn1);
        mrow[0] = mn0; mrow[1] = mn1;
        float rs0 = 0.f, rs1 = 0.f;
        uint32_t pf[4][4];
#pragma unroll
        for (int nt = 0; nt < 8; nt++) {
            const float p0 = __expf(c[nt][0] - mn0), p1 = __expf(c[nt][1] - mn0);
            const float p2 = __expf(c[nt][2] - mn1), p3 = __expf(c[nt][3] - mn1);
            rs0 += p0 + p1; rs1 += p2 + p3;
            const int kchunk = nt >> 1, half_sel = nt & 1;
            const __half2 h01 = __floats2half2_rn(p0, p1);
            const __half2 h23 = __floats2half2_rn(p2, p3);
            pf[kchunk][half_sel * 2 + 0] = *(const uint32_t*)&h01;
            pf[kchunk][half_sel * 2 + 1] = *(const uint32_t*)&h23;
        }
        rs0 += __shfl_xor_sync(0xffffffffu, rs0, 1);
        rs0 += __shfl_xor_sync(0xffffffffu, rs0, 2);
        rs1 += __shfl_xor_sync(0xffffffffu, rs1, 1);
        rs1 += __shfl_xor_sync(0xffffffffu, rs1, 2);
        lrow[0] = lrow[0] * al0 + rs0;
        lrow[1] = lrow[1] * al1 + rs1;
#pragma unroll
        for (int nt = 0; nt < 8; nt++) {
            oacc[nt][0] *= al0; oacc[nt][1] *= al0;
            oacc[nt][2] *= al1; oacc[nt][3] *= al1;
        }

#pragma unroll
        for (int ks = 0; ks < 4; ks++) {
#pragma unroll
            for (int vt = 0; vt < 4; vt++) {
                uint32_t vf[4];
                const int vr = ks * 16 + (lane & 7) + ((lane >> 3) & 1) * 8;
                const int vc = vt * 16 + (lane >> 4) * 8;
                ldm4t(vf, sV + (uint32_t)(vr * FST + vc) * 2);
                mma_f16(oacc[vt * 2 + 0], pf[ks], vf[0], vf[1]);
                mma_f16(oacc[vt * 2 + 1], pf[ks], vf[2], vf[3]);
            }
        }
    }

    const float il0 = 1.f / lrow[0], il1 = 1.f / lrow[1];
    const int r0 = rq + wid * 16 + (lane >> 2);
#pragma unroll
    for (int nt = 0; nt < 8; nt++) {
        const int col = h * 64 + nt * 8 + (lane & 3) * 2;
        *(__half2*)(g_Af + (size_t)r0 * CC + col) =
            __floats2half2_rn(oacc[nt][0] * il0, oacc[nt][1] * il0);
        *(__half2*)(g_Af + (size_t)(r0 + 8) * CC + col) =
            __floats2half2_rn(oacc[nt][2] * il1, oacc[nt][3] * il1);
    }
}

// ------------- branch 3: window attention, fp16 mma ------------------------------
__global__ __launch_bounds__(128) void attnwin_mma(const float* __restrict__ pos_table) {
    __shared__ __half Qs[64 * FST], Ks[64 * FST], Vs[64 * FST];
    __shared__ float pos[343];
    const int win = blockIdx.x, h = blockIdx.y, b = blockIdx.z;
    const int wd = win / 36, ww = (win / 6) % 6, wh = win % 6;
    const int tid = threadIdx.x, lane = tid & 31, wid = tid >> 5;
    const int base = b * NTOK + wd * 4 * 576 + ww * 4 * 24 + wh * 4;
    const uint32_t sQ = smem_to_u32(Qs), sK = smem_to_u32(Ks), sV = smem_to_u32(Vs);

    for (int e = tid; e < 343; e += 128) pos[e] = pos_table[e];
#pragma unroll
    for (int i = 0; i < 4; i++) {
        const int e = tid + i * 128;
        const int r = e >> 3, cu = e & 7;
        const int grow = base + (r >> 4) * 576 + ((r >> 2) & 3) * 24 + (r & 3);
        const size_t go = (size_t)grow * CC + h * 64 + cu * 8;
        *(uint4*)(Qs + r * FST + cu * 8) = *(const uint4*)(g_Qh + go);
        *(uint4*)(Ks + r * FST + cu * 8) = *(const uint4*)(g_Kh + go);
        *(uint4*)(Vs + r * FST + cu * 8) = *(const uint4*)(g_Vh + go);
    }
    __syncthreads();

    uint32_t qf[4][4];
#pragma unroll
    for (int ks = 0; ks < 4; ks++) {
        const uint32_t ad = sQ + (uint32_t)((wid * 16 + (lane & 15)) * FST
                                            + ks * 16 + (lane >> 4) * 8) * 2;
        ldm4(qf[ks], ad);
    }

    float c[8][4];
#pragma unroll
    for (int nt = 0; nt < 8; nt++) { c[nt][0]=0; c[nt][1]=0; c[nt][2]=0; c[nt][3]=0; }
#pragma unroll
    for (int ks = 0; ks < 4; ks++) {
#pragma unroll
        for (int bt = 0; bt < 4; bt++) {
            uint32_t kf[4];
            const uint32_t kd = sK + (uint32_t)((bt * 16 + (lane & 15)) * FST
                                                + ks * 16 + (lane >> 4) * 8) * 2;
            ldm4(kf, kd);
            mma_f16(c[bt * 2 + 0], qf[ks], kf[0], kf[2]);
            mma_f16(c[bt * 2 + 1], qf[ks], kf[1], kf[3]);
        }
    }

    const int mA = wid * 16 + (lane >> 2), mB = mA + 8;
    const int amA = mA >> 4, bmA = (mA >> 2) & 3, cmA = mA & 3;
    const int amB = mB >> 4, bmB = (mB >> 2) & 3, cmB = mB & 3;
#pragma unroll
    for (int nt = 0; nt < 8; nt++) {
#pragma unroll
        for (int e = 0; e < 2; e++) {
            const int col = nt * 8 + (lane & 3) * 2 + e;
            const int aj = col >> 4, bj = (col >> 2) & 3, cj = col & 3;
            c[nt][e]     += pos[(aj - amA + 3) * 49 + (bj - bmA + 3) * 7 + (cj - cmA + 3)];
            c[nt][2 + e] += pos[(aj - amB + 3) * 49 + (bj - bmB + 3) * 7 + (cj - cmB + 3)];
        }
    }

    float tm0 = -1e30f, tm1 = -1e30f;
#pragma unroll
    for (int nt = 0; nt < 8; nt++) {
        tm0 = fmaxf(tm0, fmaxf(c[nt][0], c[nt][1]));
        tm1 = fmaxf(tm1, fmaxf(c[nt][2], c[nt][3]));
    }
    tm0 = fmaxf(tm0, __shfl_xor_sync(0xffffffffu, tm0, 1));
    tm0 = fmaxf(tm0, __shfl_xor_sync(0xffffffffu, tm0, 2));
    tm1 = fmaxf(tm1, __shfl_xor_sync(0xffffffffu, tm1, 1));
    tm1 = fmaxf(tm1, __shfl_xor_sync(0xffffffffu, tm1, 2));
    float rs0 = 0.f, rs1 = 0.f;
    uint32_t pf[4][4];
#pragma unroll
    for (int nt = 0; nt < 8; nt++) {
        const float p0 = __expf(c[nt][0] - tm0), p1 = __expf(c[nt][1] - tm0);
        const float p2 = __expf(c[nt][2] - tm1), p3 = __expf(c[nt][3] - tm1);
        rs0 += p0 + p1; rs1 += p2 + p3;
        const int kchunk = nt >> 1, half_sel = nt & 1;
        const __half2 h01 = __floats2half2_rn(p0, p1);
        const __half2 h23 = __floats2half2_rn(p2, p3);
        pf[kchunk][half_sel * 2 + 0] = *(const uint32_t*)&h01;
        pf[kchunk][half_sel * 2 + 1] = *(const uint32_t*)&h23;
    }
    rs0 += __shfl_xor_sync(0xffffffffu, rs0, 1);
    rs0 += __shfl_xor_sync(0xffffffffu, rs0, 2);
    rs1 += __shfl_xor_sync(0xffffffffu, rs1, 1);
    rs1 += __shfl_xor_sync(0xffffffffu, rs1, 2);

    float oacc[8][4];
#pragma unroll
    for (int nt = 0; nt < 8; nt++) { oacc[nt][0]=0; oacc[nt][1]=0; oacc[nt][2]=0; oacc[nt][3]=0; }
#pragma unroll
    for (int ks = 0; ks < 4; ks++) {
#pragma unroll
        for (int vt = 0; vt < 4; vt++) {
            uint32_t vf[4];
            const int vr = ks * 16 + (lane & 7) + ((lane >> 3) & 1) * 8;
            const int vc = vt * 16 + (lane >> 4) * 8;
            ldm4t(vf, sV + (uint32_t)(vr * FST + vc) * 2);
            mma_f16(oacc[vt * 2 + 0], pf[ks], vf[0], vf[1]);
            mma_f16(oacc[vt * 2 + 1], pf[ks], vf[2], vf[3]);
        }
    }

    const float il0 = 1.f / rs0, il1 = 1.f / rs1;
    const int gA = base + (mA >> 4) * 576 + ((mA >> 2) & 3) * 24 + (mA & 3);
    const int gB = base + (mB >> 4) * 576 + ((mB >> 2) & 3) * 24 + (mB & 3);
#pragma unroll
    for (int nt = 0; nt < 8; nt++) {
        const int col = h * 64 + nt * 8 + (lane & 3) * 2;
        *(__half2*)(g_Af + (size_t)gA * CC + col) =
            __floats2half2_rn(oacc[nt][0] * il0, oacc[nt][1] * il0);
        *(__half2*)(g_Af + (size_t)gB * CC + col) =
            __floats2half2_rn(oacc[nt][2] * il1, oacc[nt][3] * il1);
    }
}

// ---- gathers: write fp16 g_Af directly ------------------------------------------
__global__ void gather_x1(const float* __restrict__ x) {
    __shared__ float tile[32][33];
    const int i  = blockIdx.z;
    const int p0 = blockIdx.x * 32;
    const int c0 = blockIdx.y * 32;
    const int tx = threadIdx.x, ty = threadIdx.y;   // 32 x 8
    const float* src = x + i * 294912;
#pragma unroll
    for (int l = 0; l < 4; l++)
        tile[ty + 8 * l][tx] = src[(c0 + ty + 8 * l) * 576 + p0 + tx];
    __syncthreads();
    const size_t dst = (size_t)(i * 576 + p0) * CC + c0;
#pragma unroll
    for (int l = 0; l < 4; l++)
        g_Af[dst + (size_t)(ty + 8 * l) * CC + tx] = __float2half_rn(tile[tx][ty + 8 * l]);
}

__global__ void gather_xT(const float* __restrict__ x) {
    __shared__ float tile[32][33];
    const int b  = blockIdx.z;
    const int n0 = blockIdx.x * 32;
    const int c0 = blockIdx.y * 32;
    const int tx = threadIdx.x, ty = threadIdx.y;   // 32 x 8
    const float* src = x + b * (CC * NTOK);
#pragma unroll
    for (int i = 0; i < 4; i++)
        tile[ty + 8 * i][tx] = src[(c0 + ty + 8 * i) * NTOK + n0 + tx];
    __syncthreads();
    const size_t dst = (size_t)(b * NTOK + n0) * CC + c0;
#pragma unroll
    for (int i = 0; i < 4; i++)
        g_Af[dst + (size_t)(ty + 8 * i) * CC + tx] = __float2half_rn(tile[tx][ty + 8 * i]);
}

__global__ void gather_x2(const float* __restrict__ x) {
    __shared__ float t2[24][257];
    const int i = blockIdx.x;
    const float* src = x + i * 12288;
    const int tid = threadIdx.x;              // 256
    for (int half = 0; half < 2; half++) {
        const int j0 = half * 256;
#pragma unroll
        for (int l = 0; l < 24; l++) {
            int e = l * 256 + tid;
            int j = e / 24, k = e - j * 24;
            t2[k][j] = src[j0 * 24 + e];
        }
        __syncthreads();
#pragma unroll
        for (int l = 0; l < 24; l++) {
            int e  = l * 256 + tid;
            int k  = e >> 8, jj = e & 255;
            g_Af[(size_t)(i * 24 + k) * CC + j0 + jj] = __float2half_rn(t2[k][jj]);
        }
        __syncthreads();
    }
}

// ---------------- branch 2: tiny seq-24 attention (fp16 in/out) ------------------
__global__ __launch_bounds__(256) void attn_seq24() {
    __shared__ float Qs[24 * 65], Ks[24 * 65], Vs[24 * 65], P[24 * 25];
    const int i = blockIdx.x, h = blockIdx.y;
    const int tid = threadIdx.x;
    const size_t rbase = (size_t)i * 24 * CC + h * 64;

    for (int e = tid; e < 24 * 64; e += 256) {
        const int k = e >> 6, d = e & 63;
        Qs[k * 65 + d] = __half2float(g_Qh[rbase + k * CC + d]);
        Ks[k * 65 + d] = __half2float(g_Kh[rbase + k * CC + d]);
        Vs[k * 65 + d] = __half2float(g_Vh[rbase + k * CC + d]);
    }
    __syncthreads();
    for (int sid = tid; sid < 576; sid += 256) {
        const int r = sid / 24, c = sid - r * 24;
        float s = 0.f;
#pragma unroll 16
        for (int d = 0; d < 64; d++) s += Qs[r * 65 + d] * Ks[c * 65 + d];
        P[r * 25 + c] = s;              // Q pre-scaled by 0.125 in GEMM epilogue
    }
    __syncthreads();
    if (tid < 24) {
        float mx = -1e30f;
        for (int c = 0; c < 24; c++) mx = fmaxf(mx, P[tid * 25 + c]);
        float sum = 0.f;
        for (int c = 0; c < 24; c++) {
            const float p = __expf(P[tid * 25 + c] - mx);
            P[tid * 25 + c] = p; sum += p;
        }
        const float inv = 1.f / sum;
        for (int c = 0; c < 24; c++) P[tid * 25 + c] *= inv;
    }
    __syncthreads();
    for (int e = tid; e < 24 * 32; e += 256) {
        const int r = e >> 5, d2 = (e & 31) * 2;
        float o0 = 0.f, o1 = 0.f;
#pragma unroll
        for (int j = 0; j < 24; j++) {
            const float p = P[r * 25 + j];
            o0 += p * Vs[j * 65 + d2];
            o1 += p * Vs[j * 65 + d2 + 1];
        }
        *(__half2*)(g_Af + rbase + (size_t)r * CC + d2) = __floats2half2_rn(o0, o1);
    }
}

// ---------------- orchestration --------------------------------------------------
extern "C" void kernel_launch(void* const* d_in, const int* in_sizes, int n_in,
                              void* d_out, int out_size) {
    const float* x     = (const float*)d_in[0];
    const float* vq_w  = (const float*)d_in[1];
    const float* vq_b  = (const float*)d_in[2];
    const float* vk_w  = (const float*)d_in[3];
    const float* vk_b  = (const float*)d_in[4];
    const float* vv_w  = (const float*)d_in[5];
    const float* vv_b  = (const float*)d_in[6];
    const float* vo_w  = (const float*)d_in[7];
    const float* vo_b  = (const float*)d_in[8];
    const float* hq_w  = (const float*)d_in[9];
    const float* hq_b  = (const float*)d_in[10];
    const float* hk_w  = (const float*)d_in[11];
    const float* hk_b  = (const float*)d_in[12];
    const float* hv_w  = (const float*)d_in[13];
    const float* hv_b  = (const float*)d_in[14];
    const float* ho_w  = (const float*)d_in[15];
    const float* ho_b  = (const float*)d_in[16];
    const float* qkv_w = (const float*)d_in[17];
    const float* ow_w  = (const float*)d_in[18];
    const float* ow_b  = (const float*)d_in[19];
    const float* pos   = (const float*)d_in[20];
    float* out = (float*)d_out;
    (void)in_sizes; (void)n_in; (void)out_size;

    __half *pAf, *pWfh, *pWfl, *pQh, *pKh, *pVh;
    cudaGetSymbolAddress((void**)&pAf, g_Af);
    cudaGetSymbolAddress((void**)&pWfh, g_Wfh);
    cudaGetSymbolAddress((void**)&pWfl, g_Wfl);
    cudaGetSymbolAddress((void**)&pQh, g_Qh);
    cudaGetSymbolAddress((void**)&pKh, g_Kh);
    cudaGetSymbolAddress((void**)&pVh, g_Vh);

    const int SMEM1 = 2 * 2 * MATS * 2;   // 40960 B (1-product)
    const int SMEM2 = 2 * 3 * MATS * 2;   // 61440 B (2-product)
    cudaFuncSetAttribute(gemm16<1>, cudaFuncAttributeMaxDynamicSharedMemorySize, SMEM1);
    cudaFuncSetAttribute(gemm16<2>, cudaFuncAttributeMaxDynamicSharedMemorySize, SMEM2);

    // weight slots: 0 vq, 1 vk, 2 vv, 3 vo, 4 hq, 5 hk, 6 hv, 7 ho,
    //               8 qkv.q, 9 qkv.k, 10 qkv.v, 11 win_out
    WArgs wa;
    const float* wp[12] = {vq_w, vk_w, vv_w, vo_w, hq_w, hk_w, hv_w, ho_w,
                           qkv_w, qkv_w, qkv_w, ow_w};
    const int wl[12] = {512,512,512,512,512,512,512,512,1536,1536,1536,512};
    const int wc[12] = {0,0,0,0,0,0,0,0,0,512,1024,0};
    for (int s = 0; s < 12; s++) { wa.W[s] = wp[s]; wa.ldb[s] = wl[s]; wa.bcol[s] = wc[s]; }
    wconv_all<<<dim3(16, 16, 12), dim3(32, 8)>>>(wa);

    const dim3 gg(4, 216);
    const size_t WS = (size_t)CC * CC;
    // QKV: single-product fp16 -> fp16 output
#define QKV(slot, b, Hp, sc) \
    gemm16<1><<<gg, 256, SMEM1>>>(pAf, pWfh + (slot) * WS, nullptr, b, Hp, sc, nullptr, 0)
    // out-projection: 2-product fp16 -> fp32 out
#define OPROJ(slot, b, ac) \
    gemm16<2><<<gg, 256, SMEM2>>>(pAf, pWfh + (slot) * WS, pWfl + (slot) * WS, \
                                  b, nullptr, 1.f, out, ac)

    // ---- branch 1 (seq-576 full attention, fp16 flash) ----
    gather_x1<<<dim3(18, 16, 48), dim3(32, 8)>>>(x);
    QKV(0, vq_b, pQh, 0.125f);
    QKV(1, vk_b, pKh, 1.f);
    QKV(2, vv_b, pVh, 1.f);
    attn576_mma<<<dim3(9, 8, 48), 128>>>();     // writes fp16 O into g_Af
    OPROJ(3, vo_b, 0);                           // first write of out

    // ---- branch 3 (window attention, fp16 mma) ----
    gather_xT<<<dim3(432, 16, 2), dim3(32, 8)>>>(x);
    QKV(8, nullptr, pQh, 0.125f);
    QKV(9, nullptr, pKh, 1.f);
    QKV(10, nullptr, pVh, 1.f);
    attnwin_mma<<<dim3(216, 8, 2), 128>>>(pos);
    OPROJ(11, ow_b, 1);                          // accumulate

    // ---- branch 2 (seq-24 full attention) ----
    gather_x2<<<1152, 256>>>(x);
    QKV(4, hq_b, pQh, 0.125f);
    QKV(5, hk_b, pKh, 1.f);
    QKV(6, hv_b, pVh, 1.f);
    attn_seq24<<<dim3(1152, 8), 256>>>();
    OPROJ(7, ho_b, 1);                           // accumulate
#undef QKV
#undef OPROJ
}

// round 11
// speedup vs baseline: 5.3151x; 1.1644x over previous
#include <cuda_runtime.h>
#include <cuda_fp16.h>
#include <cstdint>

#define CC 512
#define NTOK 13824            // 24*24*24
#define TT 27648              // B * NTOK

// ---------------- scratch (device globals; no allocation allowed) ----------------
__device__ __half g_Af [TT * CC];        // fp16 A (gathered x / attention outputs)
__device__ __half g_Wfh[12 * CC * CC];   // fp16 Wt[n][k], 12 slots
__device__ __half g_Qh[TT * CC];
__device__ __half g_Kh[TT * CC];
__device__ __half g_Vh[TT * CC];

__device__ __forceinline__ uint32_t smem_to_u32(const void* p) {
    uint32_t a;
    asm("{ .reg .u64 t; cvta.to.shared.u64 t, %1; cvt.u32.u64 %0, t; }" : "=r"(a) : "l"(p));
    return a;
}
__device__ __forceinline__ void ldm4(uint32_t* r, uint32_t addr) {
    asm volatile("ldmatrix.sync.aligned.m8n8.x4.shared.b16 {%0,%1,%2,%3}, [%4];"
                 : "=r"(r[0]), "=r"(r[1]), "=r"(r[2]), "=r"(r[3]) : "r"(addr));
}
__device__ __forceinline__ void ldm4t(uint32_t* r, uint32_t addr) {
    asm volatile("ldmatrix.sync.aligned.m8n8.x4.trans.shared.b16 {%0,%1,%2,%3}, [%4];"
                 : "=r"(r[0]), "=r"(r[1]), "=r"(r[2]), "=r"(r[3]) : "r"(addr));
}
__device__ __forceinline__ void mma_f16(float* c, const uint32_t* a,
                                        uint32_t b0, uint32_t b1) {
    asm volatile("mma.sync.aligned.m16n8k16.row.col.f32.f16.f16.f32 "
                 "{%0,%1,%2,%3}, {%4,%5,%6,%7}, {%8,%9}, {%0,%1,%2,%3};"
                 : "+f"(c[0]), "+f"(c[1]), "+f"(c[2]), "+f"(c[3])
                 : "r"(a[0]), "r"(a[1]), "r"(a[2]), "r"(a[3]), "r"(b0), "r"(b1));
}
__device__ __forceinline__ void cp16(uint32_t d, const void* s) {
    asm volatile("cp.async.cg.shared.global [%0], [%1], 16;" :: "r"(d), "l"(s));
}
#define CP_COMMIT() asm volatile("cp.async.commit_group;" ::: "memory")
#define CP_WAIT(n)  asm volatile("cp.async.wait_group %0;" :: "n"(n) : "memory")

// ---------------- weight conversion: all 12 slots ---------------------------------
struct WArgs {
    const float* W[12];
    int ldb[12];
    int bcol[12];
};
__global__ void wconv_all(WArgs a) {
    __shared__ float tile[32][33];
    const int slot = blockIdx.z;
    const int k0 = blockIdx.x * 32, n0 = blockIdx.y * 32;
    const int tx = threadIdx.x, ty = threadIdx.y;   // 32 x 8
    const float* W = a.W[slot];
    const int ldb = a.ldb[slot], bcol = a.bcol[slot];
#pragma unroll
    for (int l = 0; l < 4; l++)
        tile[ty + 8 * l][tx] = W[(k0 + ty + 8 * l) * ldb + bcol + n0 + tx];
    __syncthreads();
    const size_t base = (size_t)slot * CC * CC;
#pragma unroll
    for (int l = 0; l < 4; l++) {
        const size_t idx = base + (size_t)(n0 + ty + 8 * l) * CC + k0 + tx;
        g_Wfh[idx] = __float2half_rn(tile[tx][ty + 8 * l]);
    }
}

// ------------- fp16 GEMM, K-chunk 64, 2-stage cp.async ---------------------------
// Two modes: outf==null -> fp16 outputs (QKV merged: grid.x up to 12, chunk>>2
// selects the destination tensor); outf!=null -> fp32 accumulate (grid.x = 4).
#define G64 72                       // smem row stride (halfs) for 64-col chunk
#define MAT64 (128 * G64)            // one matrix (halfs)

struct GArgs {
    const __half* A;
    const __half* B;                 // weight rows [grid.x*128][512]
    const float* bias[3];
    __half* outh[3];
    float hs[3];
    float* outf;
    int acc;
};

__global__ __launch_bounds__(256, 2) void gemm64(GArgs g) {
    extern __shared__ __align__(16) __half smh[];
    const int tid = threadIdx.x, lane = tid & 31, wid = tid >> 5;
    const int m0 = blockIdx.y * 128;
    const int wrow0 = blockIdx.x * 128;
    const int which = blockIdx.x >> 2;
    const int ncol0 = g.outf ? wrow0 : (blockIdx.x & 3) * 128;
    const int wm = (wid >> 2) * 64, wn = (wid & 3) * 32;

    float c[4][4][4];
#pragma unroll
    for (int i = 0; i < 4; i++)
#pragma unroll
        for (int j = 0; j < 4; j++) { c[i][j][0]=0; c[i][j][1]=0; c[i][j][2]=0; c[i][j][3]=0; }

    const __half* pA = g.A + (size_t)m0 * CC;
    const __half* pB = g.B + (size_t)wrow0 * CC;
    const uint32_t smb32 = smem_to_u32(smh);

    // per-thread load map: 4 uint4 per matrix per stage
    const int r0l = tid >> 3, cu0 = tid & 7;           // idx = tid (+256k)
    const uint32_t so = (uint32_t)(r0l * G64 + cu0 * 8);
    const int go = r0l * CC + cu0 * 8;

#define ISSUE64(stage, kb) do {                                              \
        const uint32_t sbs = smb32 + (uint32_t)(stage) * (2 * MAT64 * 2);    \
        _Pragma("unroll")                                                    \
        for (int i = 0; i < 4; i++) {                                        \
            cp16(sbs + (so + (uint32_t)(i * 32 * G64)) * 2,                  \
                 pA + go + i * 32 * CC + (kb));                              \
            cp16(sbs + (MAT64 + so + (uint32_t)(i * 32 * G64)) * 2,          \
                 pB + go + i * 32 * CC + (kb));                              \
        }                                                                    \
        CP_COMMIT();                                                         \
    } while (0)

    ISSUE64(0, 0);
    for (int kc = 0; kc < 8; kc++) {
        if (kc + 1 < 8) { ISSUE64((kc + 1) & 1, (kc + 1) * 64); CP_WAIT(1); }
        else            { CP_WAIT(0); }
        __syncthreads();
        const uint32_t sb = smb32 + (uint32_t)(kc & 1) * (2 * MAT64 * 2);
#pragma unroll
        for (int ks = 0; ks < 4; ks++) {
            uint32_t bh[2][4];
#pragma unroll
            for (int bt = 0; bt < 2; bt++) {
                const int r = wn + bt * 16 + (lane & 15);
                ldm4(bh[bt], sb + (uint32_t)(MAT64 + r * G64 + ks * 16 + (lane >> 4) * 8) * 2);
            }
#pragma unroll
            for (int mt = 0; mt < 4; mt++) {
                uint32_t af[4];
                const int r = wm + mt * 16 + (lane & 15);
                ldm4(af, sb + (uint32_t)(r * G64 + ks * 16 + (lane >> 4) * 8) * 2);
#pragma unroll
                for (int nt = 0; nt < 4; nt++) {
                    const int bt = nt >> 1, sub = nt & 1;
                    mma_f16(c[mt][nt], af, bh[bt][sub], bh[bt][sub + 2]);
                }
            }
        }
        __syncthreads();
    }
#undef ISSUE64

    const float* bias = g.outf ? g.bias[0] : g.bias[which];
#pragma unroll
    for (int mt = 0; mt < 4; mt++) {
        const int r0 = m0 + wm + mt * 16 + (lane >> 2);
#pragma unroll
        for (int nt = 0; nt < 4; nt++) {
            const int col = ncol0 + wn + nt * 8 + (lane & 3) * 2;
            float2 v0 = make_float2(c[mt][nt][0], c[mt][nt][1]);
            float2 v1 = make_float2(c[mt][nt][2], c[mt][nt][3]);
            if (bias) {
                const float b0 = bias[col], b1 = bias[col + 1];
                v0.x += b0; v0.y += b1; v1.x += b0; v1.y += b1;
            }
            if (g.outf) {
                float* p0 = g.outf + (size_t)r0 * CC + col;
                float* p1 = g.outf + (size_t)(r0 + 8) * CC + col;
                if (g.acc) {
                    const float2 o0 = *(const float2*)p0, o1 = *(const float2*)p1;
                    v0.x += o0.x; v0.y += o0.y; v1.x += o1.x; v1.y += o1.y;
                }
                *(float2*)p0 = v0;
                *(float2*)p1 = v1;
            } else {
                __half* C = g.outh[which];
                const float hs = g.hs[which];
                *(__half2*)(C + (size_t)r0 * CC + col) =
                    __floats2half2_rn(v0.x * hs, v0.y * hs);
                *(__half2*)(C + (size_t)(r0 + 8) * CC + col) =
                    __floats2half2_rn(v1.x * hs, v1.y * hs);
            }
        }
    }
}

// ------------- branch 1 attention: flash-style fp16 mma, seq 576 -----------------
#define FST 72    // smem half-stride

__global__ __launch_bounds__(128) void attn576_mma() {
    __shared__ __half Qs[64 * FST], Ks[64 * FST], Vs[64 * FST];
    const int qt = blockIdx.x, h = blockIdx.y, bd = blockIdx.z;
    const int tid = threadIdx.x, lane = tid & 31, wid = tid >> 5;
    const int rq = bd * 576 + qt * 64, rb = bd * 576;
    const uint32_t sQ = smem_to_u32(Qs), sK = smem_to_u32(Ks), sV = smem_to_u32(Vs);

#pragma unroll
    for (int i = 0; i < 4; i++) {
        const int e = tid + i * 128;
        const int r = e >> 3, cu = e & 7;
        *(uint4*)(Qs + r * FST + cu * 8) =
            *(const uint4*)(g_Qh + (size_t)(rq + r) * CC + h * 64 + cu * 8);
    }
    __syncthreads();

    uint32_t qf[4][4];
#pragma unroll
    for (int ks = 0; ks < 4; ks++) {
        const uint32_t ad = sQ + (uint32_t)((wid * 16 + (lane & 15)) * FST
                                            + ks * 16 + (lane >> 4) * 8) * 2;
        ldm4(qf[ks], ad);
    }

    float oacc[8][4];
#pragma unroll
    for (int nt = 0; nt < 8; nt++) { oacc[nt][0]=0; oacc[nt][1]=0; oacc[nt][2]=0; oacc[nt][3]=0; }
    float mrow[2] = {-1e30f, -1e30f};
    float lrow[2] = {0.f, 0.f};

    for (int kt = 0; kt < 9; kt++) {
        __syncthreads();
#pragma unroll
        for (int i = 0; i < 4; i++) {
            const int e = tid + i * 128;
            const int r = e >> 3, cu = e & 7;
            const size_t grow = (size_t)(rb + kt * 64 + r) * CC + h * 64 + cu * 8;
            *(uint4*)(Ks + r * FST + cu * 8) = *(const uint4*)(g_Kh + grow);
            *(uint4*)(Vs + r * FST + cu * 8) = *(const uint4*)(g_Vh + grow);
        }
        __syncthreads();

        float c[8][4];
#pragma unroll
        for (int nt = 0; nt < 8; nt++) { c[nt][0]=0; c[nt][1]=0; c[nt][2]=0; c[nt][3]=0; }
#pragma unroll
        for (int ks = 0; ks < 4; ks++) {
#pragma unroll
            for (int bt = 0; bt < 4; bt++) {
                uint32_t kf[4];
                const uint32_t kd = sK + (uint32_t)((bt * 16 + (lane & 15)) * FST
                                                    + ks * 16 + (lane >> 4) * 8) * 2;
                ldm4(kf, kd);
                mma_f16(c[bt * 2 + 0], qf[ks], kf[0], kf[2]);
                mma_f16(c[bt * 2 + 1], qf[ks], kf[1], kf[3]);
            }
        }

        float tm0 = -1e30f, tm1 = -1e30f;
#pragma unroll
        for (int nt = 0; nt < 8; nt++) {
            tm0 = fmaxf(tm0, fmaxf(c[nt][0], c[nt][1]));
            tm1 = fmaxf(tm1, fmaxf(c[nt][2], c[nt][3]));
        }
        tm0 = fmaxf(tm0, __shfl_xor_sync(0xffffffffu, tm0, 1));
        tm0 = fmaxf(tm0, __shfl_xor_sync(0xffffffffu, tm0, 2));
        tm1 = fmaxf(tm1, __shfl_xor_sync(0xffffffffu, tm1, 1));
        tm1 = fmaxf(tm1, __shfl_xor_sync(0xffffffffu, tm1, 2));
        const float mn0 = fmaxf(mrow[0], tm0), mn1 = fmaxf(mrow[1], tm1);
        const float al0 = __expf(mrow[0] - mn0), al1 = __expf(mrow[1] - mn1);
        mrow[0] = mn0; mrow[1] = mn1;
        float rs0 = 0.f, rs1 = 0.f;
        uint32_t pf[4][4];
#pragma unroll
        for (int nt = 0; nt < 8; nt++) {
            const float p0 = __expf(c[nt][0] - mn0), p1 = __expf(c[nt][1] - mn0);
            const float p2 = __expf(c[nt][2] - mn1), p3 = __expf(c[nt][3] - mn1);
            rs0 += p0 + p1; rs1 += p2 + p3;
            const int kchunk = nt >> 1, half_sel = nt & 1;
            const __half2 h01 = __floats2half2_rn(p0, p1);
            const __half2 h23 = __floats2half2_rn(p2, p3);
            pf[kchunk][half_sel * 2 + 0] = *(const uint32_t*)&h01;
            pf[kchunk][half_sel * 2 + 1] = *(const uint32_t*)&h23;
        }
        rs0 += __shfl_xor_sync(0xffffffffu, rs0, 1);
        rs0 += __shfl_xor_sync(0xffffffffu, rs0, 2);
        rs1 += __shfl_xor_sync(0xffffffffu, rs1, 1);
        rs1 += __shfl_xor_sync(0xffffffffu, rs1, 2);
        lrow[0] = lrow[0] * al0 + rs0;
        lrow[1] = lrow[1] * al1 + rs1;
#pragma unroll
        for (int nt = 0; nt < 8; nt++) {
            oacc[nt][0] *= al0; oacc[nt][1] *= al0;
            oacc[nt][2] *= al1; oacc[nt][3] *= al1;
        }

#pragma unroll
        for (int ks = 0; ks < 4; ks++) {
#pragma unroll
            for (int vt = 0; vt < 4; vt++) {
                uint32_t vf[4];
                const int vr = ks * 16 + (lane & 7) + ((lane >> 3) & 1) * 8;
                const int vc = vt * 16 + (lane >> 4) * 8;
                ldm4t(vf, sV + (uint32_t)(vr * FST + vc) * 2);
                mma_f16(oacc[vt * 2 + 0], pf[ks], vf[0], vf[1]);
                mma_f16(oacc[vt * 2 + 1], pf[ks], vf[2], vf[3]);
            }
        }
    }

    const float il0 = 1.f / lrow[0], il1 = 1.f / lrow[1];
    const int r0 = rq + wid * 16 + (lane >> 2);
#pragma unroll
    for (int nt = 0; nt < 8; nt++) {
        const int col = h * 64 + nt * 8 + (lane & 3) * 2;
        *(__half2*)(g_Af + (size_t)r0 * CC + col) =
            __floats2half2_rn(oacc[nt][0] * il0, oacc[nt][1] * il0);
        *(__half2*)(g_Af + (size_t)(r0 + 8) * CC + col) =
            __floats2half2_rn(oacc[nt][2] * il1, oacc[nt][3] * il1);
    }
}

// ------------- branch 3: window attention, fp16 mma ------------------------------
__global__ __launch_bounds__(128) void attnwin_mma(const float* __restrict__ pos_table) {
    __shared__ __half Qs[64 * FST], Ks[64 * FST], Vs[64 * FST];
    __shared__ float pos[343];
    const int win = blockIdx.x, h = blockIdx.y, b = blockIdx.z;
    const int wd = win / 36, ww = (win / 6) % 6, wh = win % 6;
    const int tid = threadIdx.x, lane = tid & 31, wid = tid >> 5;
    const int base = b * NTOK + wd * 4 * 576 + ww * 4 * 24 + wh * 4;
    const uint32_t sQ = smem_to_u32(Qs), sK = smem_to_u32(Ks), sV = smem_to_u32(Vs);

    for (int e = tid; e < 343; e += 128) pos[e] = pos_table[e];
#pragma unroll
    for (int i = 0; i < 4; i++) {
        const int e = tid + i * 128;
        const int r = e >> 3, cu = e & 7;
        const int grow = base + (r >> 4) * 576 + ((r >> 2) & 3) * 24 + (r & 3);
        const size_t go = (size_t)grow * CC + h * 64 + cu * 8;
        *(uint4*)(Qs + r * FST + cu * 8) = *(const uint4*)(g_Qh + go);
        *(uint4*)(Ks + r * FST + cu * 8) = *(const uint4*)(g_Kh + go);
        *(uint4*)(Vs + r * FST + cu * 8) = *(const uint4*)(g_Vh + go);
    }
    __syncthreads();

    uint32_t qf[4][4];
#pragma unroll
    for (int ks = 0; ks < 4; ks++) {
        const uint32_t ad = sQ + (uint32_t)((wid * 16 + (lane & 15)) * FST
                                            + ks * 16 + (lane >> 4) * 8) * 2;
        ldm4(qf[ks], ad);
    }

    float c[8][4];
#pragma unroll
    for (int nt = 0; nt < 8; nt++) { c[nt][0]=0; c[nt][1]=0; c[nt][2]=0; c[nt][3]=0; }
#pragma unroll
    for (int ks = 0; ks < 4; ks++) {
#pragma unroll
        for (int bt = 0; bt < 4; bt++) {
            uint32_t kf[4];
            const uint32_t kd = sK + (uint32_t)((bt * 16 + (lane & 15)) * FST
                                                + ks * 16 + (lane >> 4) * 8) * 2;
            ldm4(kf, kd);
            mma_f16(c[bt * 2 + 0], qf[ks], kf[0], kf[2]);
            mma_f16(c[bt * 2 + 1], qf[ks], kf[1], kf[3]);
        }
    }

    const int mA = wid * 16 + (lane >> 2), mB = mA + 8;
    const int amA = mA >> 4, bmA = (mA >> 2) & 3, cmA = mA & 3;
    const int amB = mB >> 4, bmB = (mB >> 2) & 3, cmB = mB & 3;
#pragma unroll
    for (int nt = 0; nt < 8; nt++) {
#pragma unroll
        for (int e = 0; e < 2; e++) {
            const int col = nt * 8 + (lane & 3) * 2 + e;
            const int aj = col >> 4, bj = (col >> 2) & 3, cj = col & 3;
            c[nt][e]     += pos[(aj - amA + 3) * 49 + (bj - bmA + 3) * 7 + (cj - cmA + 3)];
            c[nt][2 + e] += pos[(aj - amB + 3) * 49 + (bj - bmB + 3) * 7 + (cj - cmB + 3)];
        }
    }

    float tm0 = -1e30f, tm1 = -1e30f;
#pragma unroll
    for (int nt = 0; nt < 8; nt++) {
        tm0 = fmaxf(tm0, fmaxf(c[nt][0], c[nt][1]));
        tm1 = fmaxf(tm1, fmaxf(c[nt][2], c[nt][3]));
    }
    tm0 = fmaxf(tm0, __shfl_xor_sync(0xffffffffu, tm0, 1));
    tm0 = fmaxf(tm0, __shfl_xor_sync(0xffffffffu, tm0, 2));
    tm1 = fmaxf(tm1, __shfl_xor_sync(0xffffffffu, tm1, 1));
    tm1 = fmaxf(tm1, __shfl_xor_sync(0xffffffffu, tm1, 2));
    float rs0 = 0.f, rs1 = 0.f;
    uint32_t pf[4][4];
#pragma unroll
    for (int nt = 0; nt < 8; nt++) {
        const float p0 = __expf(c[nt][0] - tm0), p1 = __expf(c[nt][1] - tm0);
        const float p2 = __expf(c[nt][2] - tm1), p3 = __expf(c[nt][3] - tm1);
        rs0 += p0 + p1; rs1 += p2 + p3;
        const int kchunk = nt >> 1, half_sel = nt & 1;
        const __half2 h01 = __floats2half2_rn(p0, p1);
        const __half2 h23 = __floats2half2_rn(p2, p3);
        pf[kchunk][half_sel * 2 + 0] = *(const uint32_t*)&h01;
        pf[kchunk][half_sel * 2 + 1] = *(const uint32_t*)&h23;
    }
    rs0 += __shfl_xor_sync(0xffffffffu, rs0, 1);
    rs0 += __shfl_xor_sync(0xffffffffu, rs0, 2);
    rs1 += __shfl_xor_sync(0xffffffffu, rs1, 1);
    rs1 += __shfl_xor_sync(0xffffffffu, rs1, 2);

    float oacc[8][4];
#pragma unroll
    for (int nt = 0; nt < 8; nt++) { oacc[nt][0]=0; oacc[nt][1]=0; oacc[nt][2]=0; oacc[nt][3]=0; }
#pragma unroll
    for (int ks = 0; ks < 4; ks++) {
#pragma unroll
        for (int vt = 0; vt < 4; vt++) {
            uint32_t vf[4];
            const int vr = ks * 16 + (lane & 7) + ((lane >> 3) & 1) * 8;
            const int vc = vt * 16 + (lane >> 4) * 8;
            ldm4t(vf, sV + (uint32_t)(vr * FST + vc) * 2);
            mma_f16(oacc[vt * 2 + 0], pf[ks], vf[0], vf[1]);
            mma_f16(oacc[vt * 2 + 1], pf[ks], vf[2], vf[3]);
        }
    }

    const float il0 = 1.f / rs0, il1 = 1.f / rs1;
    const int gA = base + (mA >> 4) * 576 + ((mA >> 2) & 3) * 24 + (mA & 3);
    const int gB = base + (mB >> 4) * 576 + ((mB >> 2) & 3) * 24 + (mB & 3);
#pragma unroll
    for (int nt = 0; nt < 8; nt++) {
        const int col = h * 64 + nt * 8 + (lane & 3) * 2;
        *(__half2*)(g_Af + (size_t)gA * CC + col) =
            __floats2half2_rn(oacc[nt][0] * il0, oacc[nt][1] * il0);
        *(__half2*)(g_Af + (size_t)gB * CC + col) =
            __floats2half2_rn(oacc[nt][2] * il1, oacc[nt][3] * il1);
    }
}

// ---- gathers: write fp16 g_Af directly ------------------------------------------
__global__ void gather_x1(const float* __restrict__ x) {
    __shared__ float tile[32][33];
    const int i  = blockIdx.z;
    const int p0 = blockIdx.x * 32;
    const int c0 = blockIdx.y * 32;
    const int tx = threadIdx.x, ty = threadIdx.y;   // 32 x 8
    const float* src = x + i * 294912;
#pragma unroll
    for (int l = 0; l < 4; l++)
        tile[ty + 8 * l][tx] = src[(c0 + ty + 8 * l) * 576 + p0 + tx];
    __syncthreads();
    const size_t dst = (size_t)(i * 576 + p0) * CC + c0;
#pragma unroll
    for (int l = 0; l < 4; l++)
        g_Af[dst + (size_t)(ty + 8 * l) * CC + tx] = __float2half_rn(tile[tx][ty + 8 * l]);
}

__global__ void gather_xT(const float* __restrict__ x) {
    __shared__ float tile[32][33];
    const int b  = blockIdx.z;
    const int n0 = blockIdx.x * 32;
    const int c0 = blockIdx.y * 32;
    const int tx = threadIdx.x, ty = threadIdx.y;   // 32 x 8
    const float* src = x + b * (CC * NTOK);
#pragma unroll
    for (int i = 0; i < 4; i++)
        tile[ty + 8 * i][tx] = src[(c0 + ty + 8 * i) * NTOK + n0 + tx];
    __syncthreads();
    const size_t dst = (size_t)(b * NTOK + n0) * CC + c0;
#pragma unroll
    for (int i = 0; i < 4; i++)
        g_Af[dst + (size_t)(ty + 8 * i) * CC + tx] = __float2half_rn(tile[tx][ty + 8 * i]);
}

__global__ void gather_x2(const float* __restrict__ x) {
    __shared__ float t2[24][257];
    const int i = blockIdx.x;
    const float* src = x + i * 12288;
    const int tid = threadIdx.x;              // 256
    for (int half = 0; half < 2; half++) {
        const int j0 = half * 256;
#pragma unroll
        for (int l = 0; l < 24; l++) {
            int e = l * 256 + tid;
            int j = e / 24, k = e - j * 24;
            t2[k][j] = src[j0 * 24 + e];
        }
        __syncthreads();
#pragma unroll
        for (int l = 0; l < 24; l++) {
            int e  = l * 256 + tid;
            int k  = e >> 8, jj = e & 255;
            g_Af[(size_t)(i * 24 + k) * CC + j0 + jj] = __float2half_rn(t2[k][jj]);
        }
        __syncthreads();
    }
}

// ---------------- branch 2: tiny seq-24 attention (fp16 in/out) ------------------
__global__ __launch_bounds__(256) void attn_seq24() {
    __shared__ float Qs[24 * 65], Ks[24 * 65], Vs[24 * 65], P[24 * 25];
    const int i = blockIdx.x, h = blockIdx.y;
    const int tid = threadIdx.x;
    const size_t rbase = (size_t)i * 24 * CC + h * 64;

    for (int e = tid; e < 24 * 64; e += 256) {
        const int k = e >> 6, d = e & 63;
        Qs[k * 65 + d] = __half2float(g_Qh[rbase + k * CC + d]);
        Ks[k * 65 + d] = __half2float(g_Kh[rbase + k * CC + d]);
        Vs[k * 65 + d] = __half2float(g_Vh[rbase + k * CC + d]);
    }
    __syncthreads();
    for (int sid = tid; sid < 576; sid += 256) {
        const int r = sid / 24, c = sid - r * 24;
        float s = 0.f;
#pragma unroll 16
        for (int d = 0; d < 64; d++) s += Qs[r * 65 + d] * Ks[c * 65 + d];
        P[r * 25 + c] = s;              // Q pre-scaled by 0.125 in GEMM epilogue
    }
    __syncthreads();
    if (tid < 24) {
        float mx = -1e30f;
        for (int c = 0; c < 24; c++) mx = fmaxf(mx, P[tid * 25 + c]);
        float sum = 0.f;
        for (int c = 0; c < 24; c++) {
            const float p = __expf(P[tid * 25 + c] - mx);
            P[tid * 25 + c] = p; sum += p;
        }
        const float inv = 1.f / sum;
        for (int c = 0; c < 24; c++) P[tid * 25 + c] *= inv;
    }
    __syncthreads();
    for (int e = tid; e < 24 * 32; e += 256) {
        const int r = e >> 5, d2 = (e & 31) * 2;
        float o0 = 0.f, o1 = 0.f;
#pragma unroll
        for (int j = 0; j < 24; j++) {
            const float p = P[r * 25 + j];
            o0 += p * Vs[j * 65 + d2];
            o1 += p * Vs[j * 65 + d2 + 1];
        }
        *(__half2*)(g_Af + rbase + (size_t)r * CC + d2) = __floats2half2_rn(o0, o1);
    }
}

// ---------------- orchestration --------------------------------------------------
extern "C" void kernel_launch(void* const* d_in, const int* in_sizes, int n_in,
                              void* d_out, int out_size) {
    const float* x     = (const float*)d_in[0];
    const float* vq_w  = (const float*)d_in[1];
    const float* vq_b  = (const float*)d_in[2];
    const float* vk_w  = (const float*)d_in[3];
    const float* vk_b  = (const float*)d_in[4];
    const float* vv_w  = (const float*)d_in[5];
    const float* vv_b  = (const float*)d_in[6];
    const float* vo_w  = (const float*)d_in[7];
    const float* vo_b  = (const float*)d_in[8];
    const float* hq_w  = (const float*)d_in[9];
    const float* hq_b  = (const float*)d_in[10];
    const float* hk_w  = (const float*)d_in[11];
    const float* hk_b  = (const float*)d_in[12];
    const float* hv_w  = (const float*)d_in[13];
    const float* hv_b  = (const float*)d_in[14];
    const float* ho_w  = (const float*)d_in[15];
    const float* ho_b  = (const float*)d_in[16];
    const float* qkv_w = (const float*)d_in[17];
    const float* ow_w  = (const float*)d_in[18];
    const float* ow_b  = (const float*)d_in[19];
    const float* pos   = (const float*)d_in[20];
    float* out = (float*)d_out;
    (void)in_sizes; (void)n_in; (void)out_size;

    __half *pAf, *pWfh, *pQh, *pKh, *pVh;
    cudaGetSymbolAddress((void**)&pAf, g_Af);
    cudaGetSymbolAddress((void**)&pWfh, g_Wfh);
    cudaGetSymbolAddress((void**)&pQh, g_Qh);
    cudaGetSymbolAddress((void**)&pKh, g_Kh);
    cudaGetSymbolAddress((void**)&pVh, g_Vh);

    const int SMEMK = 2 * 2 * MAT64 * 2;   // 73728 B
    cudaFuncSetAttribute(gemm64, cudaFuncAttributeMaxDynamicSharedMemorySize, SMEMK);

    // weight slots: 0 vq, 1 vk, 2 vv, 3 vo, 4 hq, 5 hk, 6 hv, 7 ho,
    //               8 qkv.q, 9 qkv.k, 10 qkv.v, 11 win_out
    WArgs wa;
    const float* wp[12] = {vq_w, vk_w, vv_w, vo_w, hq_w, hk_w, hv_w, ho_w,
                           qkv_w, qkv_w, qkv_w, ow_w};
    const int wl[12] = {512,512,512,512,512,512,512,512,1536,1536,1536,512};
    const int wc[12] = {0,0,0,0,0,0,0,0,0,512,1024,0};
    for (int s = 0; s < 12; s++) { wa.W[s] = wp[s]; wa.ldb[s] = wl[s]; wa.bcol[s] = wc[s]; }
    wconv_all<<<dim3(16, 16, 12), dim3(32, 8)>>>(wa);

    const size_t WS = (size_t)CC * CC;
    const dim3 gqkv(12, 216), gout(4, 216);

    auto launch_qkv = [&](int slot0, const float* b0, const float* b1, const float* b2) {
        GArgs g{};
        g.A = pAf;
        g.B = pWfh + (size_t)slot0 * WS;
        g.bias[0] = b0; g.bias[1] = b1; g.bias[2] = b2;
        g.outh[0] = pQh; g.outh[1] = pKh; g.outh[2] = pVh;
        g.hs[0] = 0.125f; g.hs[1] = 1.f; g.hs[2] = 1.f;
        g.outf = nullptr; g.acc = 0;
        gemm64<<<gqkv, 256, SMEMK>>>(g);
    };
    auto launch_out = [&](int slot, const float* b, int acc) {
        GArgs g{};
        g.A = pAf;
        g.B = pWfh + (size_t)slot * WS;
        g.bias[0] = b;
        g.outf = out; g.acc = acc;
        gemm64<<<gout, 256, SMEMK>>>(g);
    };

    // ---- branch 1 (seq-576 full attention, fp16 flash) ----
    gather_x1<<<dim3(18, 16, 48), dim3(32, 8)>>>(x);
    launch_qkv(0, vq_b, vk_b, vv_b);
    attn576_mma<<<dim3(9, 8, 48), 128>>>();     // writes fp16 O into g_Af
    launch_out(3, vo_b, 0);                      // first write of out

    // ---- branch 3 (window attention, fp16 mma) ----
    gather_xT<<<dim3(432, 16, 2), dim3(32, 8)>>>(x);
    launch_qkv(8, nullptr, nullptr, nullptr);
    attnwin_mma<<<dim3(216, 8, 2), 128>>>(pos);
    launch_out(11, ow_b, 1);                     // accumulate

    // ---- branch 2 (seq-24 full attention) ----
    gather_x2<<<1152, 256>>>(x);
    launch_qkv(4, hq_b, hk_b, hv_b);
    attn_seq24<<<dim3(1152, 8), 256>>>();
    launch_out(7, ho_b, 1);                      // accumulate
}